// round 9
// baseline (speedup 1.0000x reference)
#include <cuda_runtime.h>
#include <cuda_fp16.h>
#include <math.h>
#include <stdint.h>

// ---------------------------------------------------------------------------
// Problem constants
// ---------------------------------------------------------------------------
#define BB   2
#define SS   2048
#define DD   2048
#define HH   16
#define DHH  128
#define FFN  5632
#define ROWS (BB*SS)           // 4096
#define NQKV (3*HH*DHH)        // 6144
#define NFC  (2*FFN)           // 11264

// ---------------------------------------------------------------------------
// Scratch
// ---------------------------------------------------------------------------
__device__ __half g_X  [ROWS*DD];    // LN1 out
__device__ __half g_QKV[ROWS*NQKV];  // qkv proj (fp16)
__device__ __half g_Q  [ROWS*DD];    // [B,H,S,DH]
__device__ __half g_K  [ROWS*DD];
__device__ __half g_V  [ROWS*DD];    // [B,H,S,DH]
__device__ __half g_CTX[ROWS*DD];    // [B,S,H*DH]
__device__ float  g_H1 [ROWS*DD];    // residual 1 (fp32)
__device__ __half g_X2 [ROWS*DD];    // LN2 out
__device__ __half g_G  [ROWS*FFN];   // swiglu out (written by fused fc_in)
// transposed weights [N,K] K-major, fp16
__device__ __half g_WqkvT [NQKV*DD];
__device__ __half g_WoT   [DD*DD];
__device__ __half g_WfciT [NFC*DD];  // interleaved: row 2j = a_j, 2j+1 = b_j
__device__ __half g_WfcoT [DD*FFN];

// ---------------------------------------------------------------------------
// Helpers
// ---------------------------------------------------------------------------
__device__ __forceinline__ uint32_t smem_u32(const void* p) {
    uint32_t a;
    asm("{ .reg .u64 t; cvta.to.shared.u64 t, %1; cvt.u32.u64 %0, t; }"
        : "=r"(a) : "l"(p));
    return a;
}

#define CP_ASYNC16(dst, src) \
    asm volatile("cp.async.cg.shared.global [%0], [%1], 16;" \
                 :: "r"(dst), "l"(src))
#define CP_COMMIT() asm volatile("cp.async.commit_group;" ::: "memory")
#define CP_WAIT1()  asm volatile("cp.async.wait_group 1;" ::: "memory")
#define CP_WAIT0()  asm volatile("cp.async.wait_group 0;" ::: "memory")

#define MMA_F16(d, a, b)                                                   \
    asm volatile(                                                          \
        "mma.sync.aligned.m16n8k16.row.col.f32.f16.f16.f32 "               \
        "{%0,%1,%2,%3}, {%4,%5,%6,%7}, {%8,%9}, {%0,%1,%2,%3};"            \
        : "+f"((d)[0]), "+f"((d)[1]), "+f"((d)[2]), "+f"((d)[3])           \
        : "r"((a)[0]), "r"((a)[1]), "r"((a)[2]), "r"((a)[3]),              \
          "r"((b)[0]), "r"((b)[1]))

#define LDSM_X4(r0, r1, r2, r3, addr)                                      \
    asm volatile("ldmatrix.sync.aligned.m8n8.x4.shared.b16 "               \
                 "{%0,%1,%2,%3}, [%4];"                                    \
                 : "=r"(r0), "=r"(r1), "=r"(r2), "=r"(r3) : "r"(addr))

#define LDSM_X2(r0, r1, addr)                                              \
    asm volatile("ldmatrix.sync.aligned.m8n8.x2.shared.b16 "               \
                 "{%0,%1}, [%2];"                                          \
                 : "=r"(r0), "=r"(r1) : "r"(addr))

#define LDSM_X2T(r0, r1, addr)                                             \
    asm volatile("ldmatrix.sync.aligned.m8n8.x2.trans.shared.b16 "         \
                 "{%0,%1}, [%2];"                                          \
                 : "=r"(r0), "=r"(r1) : "r"(addr))

// ---------------------------------------------------------------------------
// Weight transpose + fp16 round: W[K,N] f32 -> Wt[N,K] f16
// ---------------------------------------------------------------------------
__global__ void __launch_bounds__(256) transpose_h(
    const float* __restrict__ W, __half* __restrict__ Wt, int K, int N)
{
    __shared__ float t[32][33];
    const int tx = threadIdx.x, ty = threadIdx.y;
    const int n0 = blockIdx.x * 32, k0 = blockIdx.y * 32;
#pragma unroll
    for (int j = 0; j < 4; j++)
        t[ty + j*8][tx] = W[(size_t)(k0 + ty + j*8) * N + n0 + tx];
    __syncthreads();
#pragma unroll
    for (int j = 0; j < 4; j++)
        Wt[(size_t)(n0 + ty + j*8) * K + k0 + tx] = __float2half_rn(t[tx][ty + j*8]);
}

// Paired transpose for fc_in: source col (colOff + j) -> output row (2j + off)
__global__ void __launch_bounds__(256) transpose_h_pair(
    const float* __restrict__ W, __half* __restrict__ Wt,
    int colOff, int rowOff)
{
    __shared__ float t[32][33];
    const int tx = threadIdx.x, ty = threadIdx.y;
    const int n0 = blockIdx.x * 32, k0 = blockIdx.y * 32;
#pragma unroll
    for (int j = 0; j < 4; j++)
        t[ty + j*8][tx] = W[(size_t)(k0 + ty + j*8) * NFC + colOff + n0 + tx];
    __syncthreads();
#pragma unroll
    for (int j = 0; j < 4; j++)
        Wt[(size_t)(2*(n0 + ty + j*8) + rowOff) * DD + k0 + tx] =
            __float2half_rn(t[tx][ty + j*8]);
}

// ---------------------------------------------------------------------------
// FP16 mma.sync GEMM, ldmatrix fragments, 3-stage cp.async pipeline.
// CTA tile 128x256x32, 8 warps (2M x 4N), warp tile 64x64.
// Smem rows: 32 halfs padded to 80 B (granule stride 5 -> conflict-free).
// OUT: 0 = f32 (+residual if EPI), 1 = f16, 2 = f16 fused swiglu (paired cols)
// ---------------------------------------------------------------------------
#define A_TILE_B  10240               // 128 rows * 80 B
#define B_TILE_B  20480               // 256 rows * 80 B
#define STAGE_BYTES (A_TILE_B + B_TILE_B)     // 30720
#define GM_SMEM_BYTES (3*STAGE_BYTES)         // 92160

template<int EPI, int OUT>
__global__ void __launch_bounds__(256, 1) tgemm(
    const __half* __restrict__ A, const __half* __restrict__ Bt,
    const float* __restrict__ R, void* __restrict__ Cv,
    int K, int N)
{
    extern __shared__ char smc[];
    const uint32_t smb = smem_u32(smc);

    const int tid  = threadIdx.x;
    const int wid  = tid >> 5;
    const int lane = tid & 31;
    const int g    = lane >> 2;
    const int cc   = lane & 3;
    const int wm   = (wid & 1) * 64;
    const int wn   = (wid >> 1) * 64;

    const int m0 = blockIdx.y * 128;
    const int n0 = blockIdx.x * 256;

    const __half* Ab = A  + (size_t)m0 * K;
    const __half* Bb = Bt + (size_t)n0 * K;

    const int NC = K / 32;

    const uint32_t aoff = (uint32_t)(wm + (lane & 15)) * 80 + (lane >> 4) * 16;
    const uint32_t boff = (uint32_t)(wn + (lane & 7) + ((lane >> 4) * 8)) * 80
                        + ((lane >> 3) & 1) * 16;

#define LOAD_STAGE(chunk, st) do {                                         \
        const uint32_t asw = smb + (st)*STAGE_BYTES;                       \
        const uint32_t bsw = asw + A_TILE_B;                               \
        const int kt = (chunk) * 32;                                       \
        _Pragma("unroll")                                                  \
        for (int j = 0; j < 2; j++) {                                      \
            const int f = tid + j * 256;                                   \
            const int row = f >> 2, c4 = f & 3;                            \
            CP_ASYNC16(asw + (uint32_t)(row*80 + c4*16),                   \
                       Ab + (size_t)row * K + kt + c4*8);                  \
        }                                                                  \
        _Pragma("unroll")                                                  \
        for (int j = 0; j < 4; j++) {                                      \
            const int f = tid + j * 256;                                   \
            const int row = f >> 2, c4 = f & 3;                            \
            CP_ASYNC16(bsw + (uint32_t)(row*80 + c4*16),                   \
                       Bb + (size_t)row * K + kt + c4*8);                  \
        }                                                                  \
        CP_COMMIT();                                                       \
    } while (0)

    float acc[4][8][4];
#pragma unroll
    for (int mf = 0; mf < 4; mf++)
#pragma unroll
        for (int nf = 0; nf < 8; nf++)
#pragma unroll
            for (int q = 0; q < 4; q++) acc[mf][nf][q] = 0.f;

    LOAD_STAGE(0, 0);
    LOAD_STAGE(1, 1);

    for (int i = 0; i < NC; i++) {
        if (i == NC - 1) CP_WAIT0(); else CP_WAIT1();
        __syncthreads();
        if (i + 2 < NC) LOAD_STAGE(i + 2, (i + 2) % 3);

        const uint32_t abase = smb + (i % 3) * STAGE_BYTES;
        const uint32_t bbase = abase + A_TILE_B;

#pragma unroll
        for (int ks = 0; ks < 2; ks++) {
            uint32_t a[4][4], b[8][2];
#pragma unroll
            for (int mf = 0; mf < 4; mf++)
                LDSM_X4(a[mf][0], a[mf][1], a[mf][2], a[mf][3],
                        abase + aoff + mf*1280 + ks*32);
#pragma unroll
            for (int p = 0; p < 4; p++)
                LDSM_X4(b[2*p][0], b[2*p][1], b[2*p+1][0], b[2*p+1][1],
                        bbase + boff + p*1280 + ks*32);
#pragma unroll
            for (int mf = 0; mf < 4; mf++)
#pragma unroll
                for (int nf = 0; nf < 8; nf++)
                    MMA_F16(acc[mf][nf], a[mf], b[nf]);
        }
    }
#undef LOAD_STAGE

#pragma unroll
    for (int mf = 0; mf < 4; mf++) {
#pragma unroll
        for (int nf = 0; nf < 8; nf++) {
            const int row = m0 + wm + mf * 16 + g;
            const int col = n0 + wn + nf * 8 + cc * 2;
            float2 v0 = { acc[mf][nf][0], acc[mf][nf][1] };
            float2 v1 = { acc[mf][nf][2], acc[mf][nf][3] };
            if (OUT == 2) {
                __half* Gp = (__half*)Cv;
                const int gcol = col >> 1;
                const float s0 = v0.x / (1.0f + __expf(-v0.x)) * v0.y;
                const float s1 = v1.x / (1.0f + __expf(-v1.x)) * v1.y;
                Gp[(size_t)row * FFN + gcol]       = __float2half_rn(s0);
                Gp[(size_t)(row + 8) * FFN + gcol] = __float2half_rn(s1);
            } else {
                const size_t o0 = (size_t)row * N + col;
                const size_t o1 = (size_t)(row + 8) * N + col;
                if (EPI == 1) {
                    float2 r0 = *(const float2*)&R[o0];
                    float2 r1 = *(const float2*)&R[o1];
                    v0.x += r0.x; v0.y += r0.y;
                    v1.x += r1.x; v1.y += r1.y;
                }
                if (OUT == 1) {
                    __half* C = (__half*)Cv;
                    const __half2 h0 = __floats2half2_rn(v0.x, v0.y);
                    const __half2 h1 = __floats2half2_rn(v1.x, v1.y);
                    *(uint32_t*)&C[o0] = *(const uint32_t*)&h0;
                    *(uint32_t*)&C[o1] = *(const uint32_t*)&h1;
                } else {
                    float* C = (float*)Cv;
                    *(float2*)&C[o0] = v0;
                    *(float2*)&C[o1] = v1;
                }
            }
        }
    }
}

// ---------------------------------------------------------------------------
// LayerNorm: fp32 in, fp16 out
// ---------------------------------------------------------------------------
__global__ void __launch_bounds__(256) ln_kernel(
    const float* __restrict__ X, const float* __restrict__ g,
    const float* __restrict__ b, __half* __restrict__ Y)
{
    const int tid = threadIdx.x;
    const float* x = X + (size_t)blockIdx.x * DD;
    __half* y = Y + (size_t)blockIdx.x * DD;

    float v[8];
    *(float4*)&v[0] = *(const float4*)&x[tid*8];
    *(float4*)&v[4] = *(const float4*)&x[tid*8 + 4];

    float s = 0.f, sq = 0.f;
#pragma unroll
    for (int i = 0; i < 8; i++) { s += v[i]; sq += v[i]*v[i]; }
#pragma unroll
    for (int o = 16; o; o >>= 1) {
        s  += __shfl_xor_sync(0xffffffffu, s,  o);
        sq += __shfl_xor_sync(0xffffffffu, sq, o);
    }
    __shared__ float red[2][8];
    __shared__ float stats[2];
    const int w = tid >> 5, l = tid & 31;
    if (l == 0) { red[0][w] = s; red[1][w] = sq; }
    __syncthreads();
    if (tid == 0) {
        float S = 0.f, SQ = 0.f;
#pragma unroll
        for (int i = 0; i < 8; i++) { S += red[0][i]; SQ += red[1][i]; }
        const float mean = S * (1.0f/DD);
        const float var  = SQ * (1.0f/DD) - mean*mean;
        stats[0] = mean;
        stats[1] = rsqrtf(var + 1e-5f);
    }
    __syncthreads();
    const float mean = stats[0], rstd = stats[1];

    float gv[8], bv[8];
    *(float4*)&gv[0] = *(const float4*)&g[tid*8];
    *(float4*)&gv[4] = *(const float4*)&g[tid*8+4];
    *(float4*)&bv[0] = *(const float4*)&b[tid*8];
    *(float4*)&bv[4] = *(const float4*)&b[tid*8+4];

    __half2 h[4];
#pragma unroll
    for (int i = 0; i < 4; i++) {
        const float a0 = (v[2*i]   - mean) * rstd * gv[2*i]   + bv[2*i];
        const float a1 = (v[2*i+1] - mean) * rstd * gv[2*i+1] + bv[2*i+1];
        h[i] = __floats2half2_rn(a0, a1);
    }
    *(uint4*)&y[tid*8] = *(uint4*)h;
}

// ---------------------------------------------------------------------------
// RoPE + scatter: QKV f16 [B,S,H,3*DH] -> Q/K/V f16 [B,H,S,DH]
// ---------------------------------------------------------------------------
__global__ void __launch_bounds__(128) rope_kernel(
    const __half* __restrict__ QKV, const int* __restrict__ pos_ids,
    __half* __restrict__ Q, __half* __restrict__ K, __half* __restrict__ V)
{
    const int bs = blockIdx.x;
    const int h  = blockIdx.y;
    const int d  = threadIdx.x;
    const int pos = pos_ids[bs];

    const __half* row = QKV + (size_t)bs * NQKV + h * (3*DHH);
    const float q = __half2float(row[d]);
    const float k = __half2float(row[DHH + d]);
    const __half v = row[2*DHH + d];

    const int j = d & 63;
    const float inv = 1.0f / powf(10000.0f, (float)(2*j) * (1.0f/128.0f));
    const float fr = (float)pos * inv;
    const float sn = sinf(fr), cs = cosf(fr);

    float qo, ko;
    if (d < 64) {
        qo = q * cs - __half2float(row[d + 64]) * sn;
        ko = k * cs - __half2float(row[DHH + d + 64]) * sn;
    } else {
        qo = q * cs + __half2float(row[d - 64]) * sn;
        ko = k * cs + __half2float(row[DHH + d - 64]) * sn;
    }
    const int b = bs >> 11, s = bs & 2047;
    const size_t o = (((size_t)(b*HH + h)) * SS + s) * DHH + d;
    Q[o] = __float2half_rn(qo);
    K[o] = __float2half_rn(ko);
    V[o] = v;
}

// ---------------------------------------------------------------------------
// Flash attention: fp16 mma + ldmatrix, cp.async double-buffered K/V tiles,
// V via ldmatrix.trans, Q frags in registers.
// ---------------------------------------------------------------------------
#define AT_SMEM_BYTES (26112*4)

__global__ void __launch_bounds__(256) attn_kernel(
    const __half* __restrict__ Q, const __half* __restrict__ K,
    const __half* __restrict__ V, const unsigned char* __restrict__ mask,
    __half* __restrict__ CTX)
{
    extern __shared__ uint32_t smu[];
    uint32_t* QPs = smu;
    const uint32_t smb = smem_u32(smu);
    const uint32_t kB0 = smb + 8704*4;
    const uint32_t vB0 = smb + 17408*4;
#define KBUF(bf) (kB0 + (bf)*17408)
#define VBUF(bf) (vB0 + (bf)*17408)

    const int tid  = threadIdx.x;
    const int lane = tid & 31;
    const int wid  = tid >> 5;
    const int g    = lane >> 2;
    const int cc   = lane & 3;
    const int wm   = wid * 16;

    const int qt = blockIdx.x, h = blockIdx.y, b = blockIdx.z;
    const size_t headoff = ((size_t)(b*HH + h)) * SS * DHH;
    const __half* Qg    = Q + headoff + (size_t)qt * 128 * DHH;
    const __half* Kbase = K + headoff;
    const __half* Vbase = V + headoff;

#pragma unroll
    for (int j = 0; j < 8; j++) {
        const int f = tid + j * 256;
        const int r = f >> 4, c = f & 15;
        CP_ASYNC16(smb + (uint32_t)(r*272 + c*16), Qg + r*DHH + c*8);
    }
    CP_COMMIT();

#define LOAD_KV(t, bf) do {                                                \
        const __half* Kg_ = Kbase + (size_t)(t) * 64 * DHH;                \
        const __half* Vg_ = Vbase + (size_t)(t) * 64 * DHH;                \
        _Pragma("unroll")                                                  \
        for (int j = 0; j < 4; j++) {                                      \
            const int f = tid + j * 256;                                   \
            const int r = f >> 4, c = f & 15;                              \
            CP_ASYNC16(KBUF(bf) + (uint32_t)(r*272 + c*16),                \
                       Kg_ + r*DHH + c*8);                                 \
            CP_ASYNC16(VBUF(bf) + (uint32_t)(r*272 + c*16),                \
                       Vg_ + r*DHH + c*8);                                 \
        }                                                                  \
        CP_COMMIT();                                                       \
    } while (0)

    LOAD_KV(0, 0);
    LOAD_KV(1, 1);

    CP_WAIT1();
    __syncthreads();

    uint32_t qf[8][4];
    {
        const uint32_t qaddr = smb + (uint32_t)(wm + (lane & 15)) * 272
                             + (lane >> 4) * 16;
#pragma unroll
        for (int ks = 0; ks < 8; ks++)
            LDSM_X4(qf[ks][0], qf[ks][1], qf[ks][2], qf[ks][3], qaddr + ks*32);
    }
    __syncthreads();

    const uint32_t kaddrL = (uint32_t)(lane & 7) * 272 + ((lane >> 3) & 1) * 16;
    const uint32_t vaddrL = (uint32_t)(lane & 15) * 272;
    const uint32_t paddr  = smb + (uint32_t)(wm + (lane & 15)) * 144
                          + (lane >> 4) * 16;

    float m0r = -1e30f, m1r = -1e30f, l0r = 0.f, l1r = 0.f;
    float O[16][4];
#pragma unroll
    for (int nf = 0; nf < 16; nf++)
#pragma unroll
        for (int q = 0; q < 4; q++) O[nf][q] = 0.f;

    const float scale = 0.08838834764831845f;
    const unsigned char* mrow = mask + (size_t)b * SS * SS;
    const int qg0 = qt * 128 + wm + g;
    const int qg8 = qg0 + 8;

    for (int t = 0; t < 32; t++) {
        const int bf = t & 1;
        const int kt = t * 64;

        unsigned short mRa[8], mRb[8];
        {
            const unsigned char* mpA = mrow + (size_t)qg0 * SS + kt + 2*cc;
            const unsigned char* mpB = mrow + (size_t)qg8 * SS + kt + 2*cc;
#pragma unroll
            for (int nf = 0; nf < 8; nf++) {
                mRa[nf] = *(const unsigned short*)(mpA + nf*8);
                mRb[nf] = *(const unsigned short*)(mpB + nf*8);
            }
        }

        float s[8][4];
#pragma unroll
        for (int nf = 0; nf < 8; nf++)
#pragma unroll
            for (int q = 0; q < 4; q++) s[nf][q] = 0.f;

        const uint32_t kb = KBUF(bf) + kaddrL;
#pragma unroll
        for (int ks = 0; ks < 8; ks++) {
            uint32_t bb[8][2];
#pragma unroll
            for (int nf = 0; nf < 8; nf++)
                LDSM_X2(bb[nf][0], bb[nf][1], kb + nf*2176 + ks*32);
#pragma unroll
            for (int nf = 0; nf < 8; nf++)
                MMA_F16(s[nf], qf[ks], bb[nf]);
        }

        float rmax0 = -1e30f, rmax1 = -1e30f;
#pragma unroll
        for (int nf = 0; nf < 8; nf++) {
            float s0 = s[nf][0]*scale, s1 = s[nf][1]*scale;
            float s2 = s[nf][2]*scale, s3 = s[nf][3]*scale;
            if (mRa[nf] & 0x00ffu) s0 = -10000.f;
            if (mRa[nf] & 0xff00u) s1 = -10000.f;
            if (mRb[nf] & 0x00ffu) s2 = -10000.f;
            if (mRb[nf] & 0xff00u) s3 = -10000.f;
            s[nf][0] = s0; s[nf][1] = s1; s[nf][2] = s2; s[nf][3] = s3;
            rmax0 = fmaxf(rmax0, fmaxf(s0, s1));
            rmax1 = fmaxf(rmax1, fmaxf(s2, s3));
        }
        rmax0 = fmaxf(rmax0, __shfl_xor_sync(0xffffffffu, rmax0, 1));
        rmax0 = fmaxf(rmax0, __shfl_xor_sync(0xffffffffu, rmax0, 2));
        rmax1 = fmaxf(rmax1, __shfl_xor_sync(0xffffffffu, rmax1, 1));
        rmax1 = fmaxf(rmax1, __shfl_xor_sync(0xffffffffu, rmax1, 2));

        const float mn0 = fmaxf(m0r, rmax0);
        const float mn1 = fmaxf(m1r, rmax1);
        const float cf0 = __expf(m0r - mn0);
        const float cf1 = __expf(m1r - mn1);
        m0r = mn0; m1r = mn1;

        float ls0 = 0.f, ls1 = 0.f;
#pragma unroll
        for (int nf = 0; nf < 8; nf++) {
            const float p0 = __expf(s[nf][0] - mn0);
            const float p1 = __expf(s[nf][1] - mn0);
            const float p2 = __expf(s[nf][2] - mn1);
            const float p3 = __expf(s[nf][3] - mn1);
            ls0 += p0 + p1; ls1 += p2 + p3;
            const __half2 h01 = __floats2half2_rn(p0, p1);
            const __half2 h23 = __floats2half2_rn(p2, p3);
            QPs[(wm+g)*36 + nf*4 + cc]   = *(const uint32_t*)&h01;
            QPs[(wm+g+8)*36 + nf*4 + cc] = *(const uint32_t*)&h23;
        }
        ls0 += __shfl_xor_sync(0xffffffffu, ls0, 1);
        ls0 += __shfl_xor_sync(0xffffffffu, ls0, 2);
        ls1 += __shfl_xor_sync(0xffffffffu, ls1, 1);
        ls1 += __shfl_xor_sync(0xffffffffu, ls1, 2);
        l0r = l0r * cf0 + ls0;
        l1r = l1r * cf1 + ls1;

#pragma unroll
        for (int nf = 0; nf < 16; nf++) {
            O[nf][0] *= cf0; O[nf][1] *= cf0;
            O[nf][2] *= cf1; O[nf][3] *= cf1;
        }
        __syncthreads();

        const uint32_t vb = VBUF(bf) + vaddrL;
#pragma unroll
        for (int ks = 0; ks < 4; ks++) {
            uint32_t a[4], bb[16][2];
            LDSM_X4(a[0], a[1], a[2], a[3], paddr + ks*32);
#pragma unroll
            for (int nf = 0; nf < 16; nf++)
                LDSM_X2T(bb[nf][0], bb[nf][1], vb + ks*4352 + nf*16);
#pragma unroll
            for (int nf = 0; nf < 16; nf++)
                MMA_F16(O[nf], a, bb[nf]);
        }
        __syncthreads();

        if (t + 2 < 32) LOAD_KV(t + 2, bf);
        CP_WAIT1();
    }
#undef LOAD_KV

    const float inv0 = 1.0f / l0r;
    const float inv1 = 1.0f / l1r;
    __half* C0 = CTX + ((size_t)(b*SS + qg0)) * DD + h*DHH;
    __half* C1 = CTX + ((size_t)(b*SS + qg8)) * DD + h*DHH;
#pragma unroll
    for (int nf = 0; nf < 16; nf++) {
        const int c2 = nf*8 + 2*cc;
        const __half2 h0 = __floats2half2_rn(O[nf][0]*inv0, O[nf][1]*inv0);
        const __half2 h1 = __floats2half2_rn(O[nf][2]*inv1, O[nf][3]*inv1);
        *(uint32_t*)(C0 + c2) = *(const uint32_t*)&h0;
        *(uint32_t*)(C1 + c2) = *(const uint32_t*)&h1;
    }
}

// ---------------------------------------------------------------------------
// Launch
// ---------------------------------------------------------------------------
extern "C" void kernel_launch(void* const* d_in, const int* in_sizes, int n_in,
                              void* d_out, int out_size)
{
    const float*         hidden  = (const float*)d_in[0];
    const unsigned char* mask    = (const unsigned char*)d_in[1];
    const int*           pos     = (const int*)d_in[2];
    const float*         ln1_g   = (const float*)d_in[3];
    const float*         ln1_b   = (const float*)d_in[4];
    const float*         Wqkv    = (const float*)d_in[5];
    const float*         Wo      = (const float*)d_in[6];
    const float*         ln2_g   = (const float*)d_in[7];
    const float*         ln2_b   = (const float*)d_in[8];
    const float*         Wfc_in  = (const float*)d_in[9];
    const float*         Wfc_out = (const float*)d_in[10];
    float*               out     = (float*)d_out;

    __half *X, *QKV, *Q, *K, *V, *CTX, *X2, *G;
    __half *WqkvT, *WoT, *WfciT, *WfcoT;
    float *H1;
    cudaGetSymbolAddress((void**)&X,     g_X);
    cudaGetSymbolAddress((void**)&QKV,   g_QKV);
    cudaGetSymbolAddress((void**)&Q,     g_Q);
    cudaGetSymbolAddress((void**)&K,     g_K);
    cudaGetSymbolAddress((void**)&V,     g_V);
    cudaGetSymbolAddress((void**)&CTX,   g_CTX);
    cudaGetSymbolAddress((void**)&H1,    g_H1);
    cudaGetSymbolAddress((void**)&X2,    g_X2);
    cudaGetSymbolAddress((void**)&G,     g_G);
    cudaGetSymbolAddress((void**)&WqkvT, g_WqkvT);
    cudaGetSymbolAddress((void**)&WoT,   g_WoT);
    cudaGetSymbolAddress((void**)&WfciT, g_WfciT);
    cudaGetSymbolAddress((void**)&WfcoT, g_WfcoT);

    cudaFuncSetAttribute(attn_kernel,
                         cudaFuncAttributeMaxDynamicSharedMemorySize,
                         AT_SMEM_BYTES);
    cudaFuncSetAttribute((tgemm<0,1>),
                         cudaFuncAttributeMaxDynamicSharedMemorySize,
                         GM_SMEM_BYTES);
    cudaFuncSetAttribute((tgemm<1,0>),
                         cudaFuncAttributeMaxDynamicSharedMemorySize,
                         GM_SMEM_BYTES);
    cudaFuncSetAttribute((tgemm<0,2>),
                         cudaFuncAttributeMaxDynamicSharedMemorySize,
                         GM_SMEM_BYTES);

    // 0) transpose + fp16 weights -> [N,K]
    transpose_h<<<dim3(NQKV/32, DD/32),  dim3(32,8)>>>(Wqkv,    WqkvT, DD,  NQKV);
    transpose_h<<<dim3(DD/32,   DD/32),  dim3(32,8)>>>(Wo,      WoT,   DD,  DD);
    transpose_h<<<dim3(DD/32,   FFN/32), dim3(32,8)>>>(Wfc_out, WfcoT, FFN, DD);
    transpose_h_pair<<<dim3(FFN/32, DD/32), dim3(32,8)>>>(Wfc_in, WfciT, 0,   0);
    transpose_h_pair<<<dim3(FFN/32, DD/32), dim3(32,8)>>>(Wfc_in, WfciT, FFN, 1);

    // 1) LN1 (fp16 out)
    ln_kernel<<<ROWS, 256>>>(hidden, ln1_g, ln1_b, X);
    // 2) QKV projection (fp16 out)
    tgemm<0,1><<<dim3(NQKV/256, ROWS/128), 256, GM_SMEM_BYTES>>>(
        X, WqkvT, nullptr, QKV, DD, NQKV);
    // 3) RoPE + scatter
    rope_kernel<<<dim3(ROWS, HH), 128>>>(QKV, pos, Q, K, V);
    // 4) attention -> ctx (fp16)
    attn_kernel<<<dim3(SS/128, HH, BB), 256, AT_SMEM_BYTES>>>(Q, K, V, mask, CTX);
    // 5) Wo projection + residual (f32 out)
    tgemm<1,0><<<dim3(DD/256, ROWS/128), 256, GM_SMEM_BYTES>>>(
        CTX, WoT, hidden, H1, DD, DD);
    // 6) LN2 (fp16 out)
    ln_kernel<<<ROWS, 256>>>(H1, ln2_g, ln2_b, X2);
    // 7) fc_in + fused SwiGLU (fp16 G out)
    tgemm<0,2><<<dim3(NFC/256, ROWS/128), 256, GM_SMEM_BYTES>>>(
        X2, WfciT, nullptr, G, DD, NFC);
    // 8) fc_out + residual (final output, f32)
    tgemm<1,0><<<dim3(DD/256, ROWS/128), 256, GM_SMEM_BYTES>>>(
        G, WfcoT, H1, out, FFN, DD);
}

// round 10
// speedup vs baseline: 1.2384x; 1.2384x over previous
#include <cuda_runtime.h>
#include <cuda_fp16.h>
#include <math.h>
#include <stdint.h>

// ---------------------------------------------------------------------------
// Problem constants
// ---------------------------------------------------------------------------
#define BB   2
#define SS   2048
#define DD   2048
#define HH   16
#define DHH  128
#define FFN  5632
#define ROWS (BB*SS)           // 4096
#define NQKV (3*HH*DHH)        // 6144
#define NFC  (2*FFN)           // 11264

// ---------------------------------------------------------------------------
// Scratch
// ---------------------------------------------------------------------------
__device__ __half g_X  [ROWS*DD];    // LN1 out
__device__ __half g_QKV[ROWS*NQKV];  // qkv proj (fp16)
__device__ __half g_Q  [ROWS*DD];    // [B,H,S,DH]
__device__ __half g_K  [ROWS*DD];
__device__ __half g_V  [ROWS*DD];    // [B,H,S,DH]
__device__ __half g_CTX[ROWS*DD];    // [B,S,H*DH]
__device__ float  g_H1 [ROWS*DD];    // residual 1 (fp32)
__device__ __half g_X2 [ROWS*DD];    // LN2 out
__device__ __half g_G  [ROWS*FFN];   // swiglu out (written by fused fc_in)
// transposed weights [N,K] K-major, fp16
__device__ __half g_WqkvT [NQKV*DD];
__device__ __half g_WoT   [DD*DD];
__device__ __half g_WfciT [NFC*DD];  // interleaved: row 2j = a_j, 2j+1 = b_j
__device__ __half g_WfcoT [DD*FFN];

// ---------------------------------------------------------------------------
// Helpers
// ---------------------------------------------------------------------------
__device__ __forceinline__ uint32_t smem_u32(const void* p) {
    uint32_t a;
    asm("{ .reg .u64 t; cvta.to.shared.u64 t, %1; cvt.u32.u64 %0, t; }"
        : "=r"(a) : "l"(p));
    return a;
}

#define CP_ASYNC16(dst, src) \
    asm volatile("cp.async.cg.shared.global [%0], [%1], 16;" \
                 :: "r"(dst), "l"(src))
#define CP_COMMIT() asm volatile("cp.async.commit_group;" ::: "memory")
#define CP_WAIT2()  asm volatile("cp.async.wait_group 2;" ::: "memory")
#define CP_WAIT1()  asm volatile("cp.async.wait_group 1;" ::: "memory")
#define CP_WAIT0()  asm volatile("cp.async.wait_group 0;" ::: "memory")

#define MMA_F16(d, a, b)                                                   \
    asm volatile(                                                          \
        "mma.sync.aligned.m16n8k16.row.col.f32.f16.f16.f32 "               \
        "{%0,%1,%2,%3}, {%4,%5,%6,%7}, {%8,%9}, {%0,%1,%2,%3};"            \
        : "+f"((d)[0]), "+f"((d)[1]), "+f"((d)[2]), "+f"((d)[3])           \
        : "r"((a)[0]), "r"((a)[1]), "r"((a)[2]), "r"((a)[3]),              \
          "r"((b)[0]), "r"((b)[1]))

#define LDSM_X4(r0, r1, r2, r3, addr)                                      \
    asm volatile("ldmatrix.sync.aligned.m8n8.x4.shared.b16 "               \
                 "{%0,%1,%2,%3}, [%4];"                                    \
                 : "=r"(r0), "=r"(r1), "=r"(r2), "=r"(r3) : "r"(addr))

#define LDSM_X2(r0, r1, addr)                                              \
    asm volatile("ldmatrix.sync.aligned.m8n8.x2.shared.b16 "               \
                 "{%0,%1}, [%2];"                                          \
                 : "=r"(r0), "=r"(r1) : "r"(addr))

#define LDSM_X2T(r0, r1, addr)                                             \
    asm volatile("ldmatrix.sync.aligned.m8n8.x2.trans.shared.b16 "         \
                 "{%0,%1}, [%2];"                                          \
                 : "=r"(r0), "=r"(r1) : "r"(addr))

// ---------------------------------------------------------------------------
// Weight transpose + fp16 round: W[K,N] f32 -> Wt[N,K] f16
// ---------------------------------------------------------------------------
__global__ void __launch_bounds__(256) transpose_h(
    const float* __restrict__ W, __half* __restrict__ Wt, int K, int N)
{
    __shared__ float t[32][33];
    const int tx = threadIdx.x, ty = threadIdx.y;
    const int n0 = blockIdx.x * 32, k0 = blockIdx.y * 32;
#pragma unroll
    for (int j = 0; j < 4; j++)
        t[ty + j*8][tx] = W[(size_t)(k0 + ty + j*8) * N + n0 + tx];
    __syncthreads();
#pragma unroll
    for (int j = 0; j < 4; j++)
        Wt[(size_t)(n0 + ty + j*8) * K + k0 + tx] = __float2half_rn(t[tx][ty + j*8]);
}

// Merged paired transpose for fc_in: handles BOTH halves in one launch.
// a-col j -> row 2j, b-col j (offset FFN) -> row 2j+1.  W: [DD][NFC]
__global__ void __launch_bounds__(256) transpose_h_pair2(
    const float* __restrict__ W, __half* __restrict__ Wt)
{
    __shared__ float ta[32][33];
    __shared__ float tb[32][33];
    const int tx = threadIdx.x, ty = threadIdx.y;
    const int n0 = blockIdx.x * 32, k0 = blockIdx.y * 32;
#pragma unroll
    for (int j = 0; j < 4; j++) {
        const size_t rbase = (size_t)(k0 + ty + j*8) * NFC;
        ta[ty + j*8][tx] = W[rbase + n0 + tx];
        tb[ty + j*8][tx] = W[rbase + FFN + n0 + tx];
    }
    __syncthreads();
#pragma unroll
    for (int j = 0; j < 4; j++) {
        const int n = n0 + ty + j*8;
        Wt[(size_t)(2*n)     * DD + k0 + tx] = __float2half_rn(ta[tx][ty + j*8]);
        Wt[(size_t)(2*n + 1) * DD + k0 + tx] = __float2half_rn(tb[tx][ty + j*8]);
    }
}

// ---------------------------------------------------------------------------
// FP16 mma.sync GEMM, ldmatrix fragments, 4-stage cp.async pipeline.
// CTA tile 128x128x32, 4 warps (2M x 2N), warp tile 64x64.  (R8 champion)
// Smem rows: 32 halfs padded to 80 B (granule stride 5 -> conflict-free).
// OUT: 0 = f32 (+residual if EPI), 1 = f16, 2 = f16 fused swiglu (paired cols)
// ---------------------------------------------------------------------------
#define TILE_BYTES 10240              // 128 rows * 80 B
#define STAGE_BYTES (2*TILE_BYTES)
#define GM_SMEM_BYTES (4*STAGE_BYTES) // 81920

template<int EPI, int OUT>
__global__ void __launch_bounds__(128, 2) tgemm(
    const __half* __restrict__ A, const __half* __restrict__ Bt,
    const float* __restrict__ R, void* __restrict__ Cv,
    int K, int N)
{
    extern __shared__ char smc[];
    const uint32_t smb = smem_u32(smc);

    const int tid  = threadIdx.x;
    const int wid  = tid >> 5;
    const int lane = tid & 31;
    const int g    = lane >> 2;
    const int cc   = lane & 3;
    const int wm   = (wid & 1) * 64;
    const int wn   = (wid >> 1) * 64;

    const int m0 = blockIdx.y * 128;
    const int n0 = blockIdx.x * 128;

    const __half* Ab = A  + (size_t)m0 * K;
    const __half* Bb = Bt + (size_t)n0 * K;

    const int NC = K / 32;

    const uint32_t aoff = (uint32_t)(wm + (lane & 15)) * 80 + (lane >> 4) * 16;
    const uint32_t boff = (uint32_t)(wn + (lane & 7) + ((lane >> 4) * 8)) * 80
                        + ((lane >> 3) & 1) * 16;

#define LOAD_STAGE(chunk, st) do {                                         \
        const uint32_t asw = smb + (st)*STAGE_BYTES;                       \
        const uint32_t bsw = asw + TILE_BYTES;                             \
        const int kt = (chunk) * 32;                                       \
        _Pragma("unroll")                                                  \
        for (int j = 0; j < 4; j++) {                                      \
            const int f = tid + j * 128;                                   \
            const int row = f >> 2, c4 = f & 3;                            \
            CP_ASYNC16(asw + (uint32_t)(row*80 + c4*16),                   \
                       Ab + (size_t)row * K + kt + c4*8);                  \
            CP_ASYNC16(bsw + (uint32_t)(row*80 + c4*16),                   \
                       Bb + (size_t)row * K + kt + c4*8);                  \
        }                                                                  \
        CP_COMMIT();                                                       \
    } while (0)

    float acc[4][8][4];
#pragma unroll
    for (int mf = 0; mf < 4; mf++)
#pragma unroll
        for (int nf = 0; nf < 8; nf++)
#pragma unroll
            for (int q = 0; q < 4; q++) acc[mf][nf][q] = 0.f;

    LOAD_STAGE(0, 0);
    LOAD_STAGE(1, 1);
    LOAD_STAGE(2, 2);

    for (int i = 0; i < NC; i++) {
        if (i < NC - 2)       CP_WAIT2();
        else if (i == NC - 2) CP_WAIT1();
        else                  CP_WAIT0();
        __syncthreads();
        if (i + 3 < NC) LOAD_STAGE(i + 3, (i + 3) & 3);

        const uint32_t abase = smb + (i & 3) * STAGE_BYTES;
        const uint32_t bbase = abase + TILE_BYTES;

#pragma unroll
        for (int ks = 0; ks < 2; ks++) {
            uint32_t a[4][4], b[8][2];
#pragma unroll
            for (int mf = 0; mf < 4; mf++)
                LDSM_X4(a[mf][0], a[mf][1], a[mf][2], a[mf][3],
                        abase + aoff + mf*1280 + ks*32);
#pragma unroll
            for (int p = 0; p < 4; p++)
                LDSM_X4(b[2*p][0], b[2*p][1], b[2*p+1][0], b[2*p+1][1],
                        bbase + boff + p*1280 + ks*32);
#pragma unroll
            for (int mf = 0; mf < 4; mf++)
#pragma unroll
                for (int nf = 0; nf < 8; nf++)
                    MMA_F16(acc[mf][nf], a[mf], b[nf]);
        }
    }
#undef LOAD_STAGE

#pragma unroll
    for (int mf = 0; mf < 4; mf++) {
#pragma unroll
        for (int nf = 0; nf < 8; nf++) {
            const int row = m0 + wm + mf * 16 + g;
            const int col = n0 + wn + nf * 8 + cc * 2;
            float2 v0 = { acc[mf][nf][0], acc[mf][nf][1] };
            float2 v1 = { acc[mf][nf][2], acc[mf][nf][3] };
            if (OUT == 2) {
                __half* Gp = (__half*)Cv;
                const int gcol = col >> 1;
                const float s0 = v0.x / (1.0f + __expf(-v0.x)) * v0.y;
                const float s1 = v1.x / (1.0f + __expf(-v1.x)) * v1.y;
                Gp[(size_t)row * FFN + gcol]       = __float2half_rn(s0);
                Gp[(size_t)(row + 8) * FFN + gcol] = __float2half_rn(s1);
            } else {
                const size_t o0 = (size_t)row * N + col;
                const size_t o1 = (size_t)(row + 8) * N + col;
                if (EPI == 1) {
                    float2 r0 = *(const float2*)&R[o0];
                    float2 r1 = *(const float2*)&R[o1];
                    v0.x += r0.x; v0.y += r0.y;
                    v1.x += r1.x; v1.y += r1.y;
                }
                if (OUT == 1) {
                    __half* C = (__half*)Cv;
                    const __half2 h0 = __floats2half2_rn(v0.x, v0.y);
                    const __half2 h1 = __floats2half2_rn(v1.x, v1.y);
                    *(uint32_t*)&C[o0] = *(const uint32_t*)&h0;
                    *(uint32_t*)&C[o1] = *(const uint32_t*)&h1;
                } else {
                    float* C = (float*)Cv;
                    *(float2*)&C[o0] = v0;
                    *(float2*)&C[o1] = v1;
                }
            }
        }
    }
}

// ---------------------------------------------------------------------------
// LayerNorm: fp32 in, fp16 out
// ---------------------------------------------------------------------------
__global__ void __launch_bounds__(256) ln_kernel(
    const float* __restrict__ X, const float* __restrict__ g,
    const float* __restrict__ b, __half* __restrict__ Y)
{
    const int tid = threadIdx.x;
    const float* x = X + (size_t)blockIdx.x * DD;
    __half* y = Y + (size_t)blockIdx.x * DD;

    float v[8];
    *(float4*)&v[0] = *(const float4*)&x[tid*8];
    *(float4*)&v[4] = *(const float4*)&x[tid*8 + 4];

    float s = 0.f, sq = 0.f;
#pragma unroll
    for (int i = 0; i < 8; i++) { s += v[i]; sq += v[i]*v[i]; }
#pragma unroll
    for (int o = 16; o; o >>= 1) {
        s  += __shfl_xor_sync(0xffffffffu, s,  o);
        sq += __shfl_xor_sync(0xffffffffu, sq, o);
    }
    __shared__ float red[2][8];
    __shared__ float stats[2];
    const int w = tid >> 5, l = tid & 31;
    if (l == 0) { red[0][w] = s; red[1][w] = sq; }
    __syncthreads();
    if (tid == 0) {
        float S = 0.f, SQ = 0.f;
#pragma unroll
        for (int i = 0; i < 8; i++) { S += red[0][i]; SQ += red[1][i]; }
        const float mean = S * (1.0f/DD);
        const float var  = SQ * (1.0f/DD) - mean*mean;
        stats[0] = mean;
        stats[1] = rsqrtf(var + 1e-5f);
    }
    __syncthreads();
    const float mean = stats[0], rstd = stats[1];

    float gv[8], bv[8];
    *(float4*)&gv[0] = *(const float4*)&g[tid*8];
    *(float4*)&gv[4] = *(const float4*)&g[tid*8+4];
    *(float4*)&bv[0] = *(const float4*)&b[tid*8];
    *(float4*)&bv[4] = *(const float4*)&b[tid*8+4];

    __half2 h[4];
#pragma unroll
    for (int i = 0; i < 4; i++) {
        const float a0 = (v[2*i]   - mean) * rstd * gv[2*i]   + bv[2*i];
        const float a1 = (v[2*i+1] - mean) * rstd * gv[2*i+1] + bv[2*i+1];
        h[i] = __floats2half2_rn(a0, a1);
    }
    *(uint4*)&y[tid*8] = *(uint4*)h;
}

// ---------------------------------------------------------------------------
// RoPE + scatter: QKV f16 [B,S,H,3*DH] -> Q/K/V f16 [B,H,S,DH]
// ---------------------------------------------------------------------------
__global__ void __launch_bounds__(128) rope_kernel(
    const __half* __restrict__ QKV, const int* __restrict__ pos_ids,
    __half* __restrict__ Q, __half* __restrict__ K, __half* __restrict__ V)
{
    const int bs = blockIdx.x;
    const int h  = blockIdx.y;
    const int d  = threadIdx.x;
    const int pos = pos_ids[bs];

    const __half* row = QKV + (size_t)bs * NQKV + h * (3*DHH);
    const float q = __half2float(row[d]);
    const float k = __half2float(row[DHH + d]);
    const __half v = row[2*DHH + d];

    const int j = d & 63;
    const float inv = 1.0f / powf(10000.0f, (float)(2*j) * (1.0f/128.0f));
    const float fr = (float)pos * inv;
    const float sn = sinf(fr), cs = cosf(fr);

    float qo, ko;
    if (d < 64) {
        qo = q * cs - __half2float(row[d + 64]) * sn;
        ko = k * cs - __half2float(row[DHH + d + 64]) * sn;
    } else {
        qo = q * cs + __half2float(row[d - 64]) * sn;
        ko = k * cs + __half2float(row[DHH + d - 64]) * sn;
    }
    const int b = bs >> 11, s = bs & 2047;
    const size_t o = (((size_t)(b*HH + h)) * SS + s) * DHH + d;
    Q[o] = __float2half_rn(qo);
    K[o] = __float2half_rn(ko);
    V[o] = v;
}

// ---------------------------------------------------------------------------
// Flash attention: fp16 mma + ldmatrix, cp.async double-buffered K/V tiles,
// V via ldmatrix.trans, Q frags in registers.  (R8 champion)
// ---------------------------------------------------------------------------
#define AT_SMEM_BYTES (26112*4)

__global__ void __launch_bounds__(256) attn_kernel(
    const __half* __restrict__ Q, const __half* __restrict__ K,
    const __half* __restrict__ V, const unsigned char* __restrict__ mask,
    __half* __restrict__ CTX)
{
    extern __shared__ uint32_t smu[];
    uint32_t* QPs = smu;
    const uint32_t smb = smem_u32(smu);
    const uint32_t kB0 = smb + 8704*4;
    const uint32_t vB0 = smb + 17408*4;
#define KBUF(bf) (kB0 + (bf)*17408)
#define VBUF(bf) (vB0 + (bf)*17408)

    const int tid  = threadIdx.x;
    const int lane = tid & 31;
    const int wid  = tid >> 5;
    const int g    = lane >> 2;
    const int cc   = lane & 3;
    const int wm   = wid * 16;

    const int qt = blockIdx.x, h = blockIdx.y, b = blockIdx.z;
    const size_t headoff = ((size_t)(b*HH + h)) * SS * DHH;
    const __half* Qg    = Q + headoff + (size_t)qt * 128 * DHH;
    const __half* Kbase = K + headoff;
    const __half* Vbase = V + headoff;

#pragma unroll
    for (int j = 0; j < 8; j++) {
        const int f = tid + j * 256;
        const int r = f >> 4, c = f & 15;
        CP_ASYNC16(smb + (uint32_t)(r*272 + c*16), Qg + r*DHH + c*8);
    }
    CP_COMMIT();

#define LOAD_KV(t, bf) do {                                                \
        const __half* Kg_ = Kbase + (size_t)(t) * 64 * DHH;                \
        const __half* Vg_ = Vbase + (size_t)(t) * 64 * DHH;                \
        _Pragma("unroll")                                                  \
        for (int j = 0; j < 4; j++) {                                      \
            const int f = tid + j * 256;                                   \
            const int r = f >> 4, c = f & 15;                              \
            CP_ASYNC16(KBUF(bf) + (uint32_t)(r*272 + c*16),                \
                       Kg_ + r*DHH + c*8);                                 \
            CP_ASYNC16(VBUF(bf) + (uint32_t)(r*272 + c*16),                \
                       Vg_ + r*DHH + c*8);                                 \
        }                                                                  \
        CP_COMMIT();                                                       \
    } while (0)

    LOAD_KV(0, 0);
    LOAD_KV(1, 1);

    CP_WAIT1();
    __syncthreads();

    uint32_t qf[8][4];
    {
        const uint32_t qaddr = smb + (uint32_t)(wm + (lane & 15)) * 272
                             + (lane >> 4) * 16;
#pragma unroll
        for (int ks = 0; ks < 8; ks++)
            LDSM_X4(qf[ks][0], qf[ks][1], qf[ks][2], qf[ks][3], qaddr + ks*32);
    }
    __syncthreads();

    const uint32_t kaddrL = (uint32_t)(lane & 7) * 272 + ((lane >> 3) & 1) * 16;
    const uint32_t vaddrL = (uint32_t)(lane & 15) * 272;
    const uint32_t paddr  = smb + (uint32_t)(wm + (lane & 15)) * 144
                          + (lane >> 4) * 16;

    float m0r = -1e30f, m1r = -1e30f, l0r = 0.f, l1r = 0.f;
    float O[16][4];
#pragma unroll
    for (int nf = 0; nf < 16; nf++)
#pragma unroll
        for (int q = 0; q < 4; q++) O[nf][q] = 0.f;

    const float scale = 0.08838834764831845f;
    const unsigned char* mrow = mask + (size_t)b * SS * SS;
    const int qg0 = qt * 128 + wm + g;
    const int qg8 = qg0 + 8;

    for (int t = 0; t < 32; t++) {
        const int bf = t & 1;
        const int kt = t * 64;

        unsigned short mRa[8], mRb[8];
        {
            const unsigned char* mpA = mrow + (size_t)qg0 * SS + kt + 2*cc;
            const unsigned char* mpB = mrow + (size_t)qg8 * SS + kt + 2*cc;
#pragma unroll
            for (int nf = 0; nf < 8; nf++) {
                mRa[nf] = *(const unsigned short*)(mpA + nf*8);
                mRb[nf] = *(const unsigned short*)(mpB + nf*8);
            }
        }

        float s[8][4];
#pragma unroll
        for (int nf = 0; nf < 8; nf++)
#pragma unroll
            for (int q = 0; q < 4; q++) s[nf][q] = 0.f;

        const uint32_t kb = KBUF(bf) + kaddrL;
#pragma unroll
        for (int ks = 0; ks < 8; ks++) {
            uint32_t bb[8][2];
#pragma unroll
            for (int nf = 0; nf < 8; nf++)
                LDSM_X2(bb[nf][0], bb[nf][1], kb + nf*2176 + ks*32);
#pragma unroll
            for (int nf = 0; nf < 8; nf++)
                MMA_F16(s[nf], qf[ks], bb[nf]);
        }

        float rmax0 = -1e30f, rmax1 = -1e30f;
#pragma unroll
        for (int nf = 0; nf < 8; nf++) {
            float s0 = s[nf][0]*scale, s1 = s[nf][1]*scale;
            float s2 = s[nf][2]*scale, s3 = s[nf][3]*scale;
            if (mRa[nf] & 0x00ffu) s0 = -10000.f;
            if (mRa[nf] & 0xff00u) s1 = -10000.f;
            if (mRb[nf] & 0x00ffu) s2 = -10000.f;
            if (mRb[nf] & 0xff00u) s3 = -10000.f;
            s[nf][0] = s0; s[nf][1] = s1; s[nf][2] = s2; s[nf][3] = s3;
            rmax0 = fmaxf(rmax0, fmaxf(s0, s1));
            rmax1 = fmaxf(rmax1, fmaxf(s2, s3));
        }
        rmax0 = fmaxf(rmax0, __shfl_xor_sync(0xffffffffu, rmax0, 1));
        rmax0 = fmaxf(rmax0, __shfl_xor_sync(0xffffffffu, rmax0, 2));
        rmax1 = fmaxf(rmax1, __shfl_xor_sync(0xffffffffu, rmax1, 1));
        rmax1 = fmaxf(rmax1, __shfl_xor_sync(0xffffffffu, rmax1, 2));

        const float mn0 = fmaxf(m0r, rmax0);
        const float mn1 = fmaxf(m1r, rmax1);
        const float cf0 = __expf(m0r - mn0);
        const float cf1 = __expf(m1r - mn1);
        m0r = mn0; m1r = mn1;

        float ls0 = 0.f, ls1 = 0.f;
#pragma unroll
        for (int nf = 0; nf < 8; nf++) {
            const float p0 = __expf(s[nf][0] - mn0);
            const float p1 = __expf(s[nf][1] - mn0);
            const float p2 = __expf(s[nf][2] - mn1);
            const float p3 = __expf(s[nf][3] - mn1);
            ls0 += p0 + p1; ls1 += p2 + p3;
            const __half2 h01 = __floats2half2_rn(p0, p1);
            const __half2 h23 = __floats2half2_rn(p2, p3);
            QPs[(wm+g)*36 + nf*4 + cc]   = *(const uint32_t*)&h01;
            QPs[(wm+g+8)*36 + nf*4 + cc] = *(const uint32_t*)&h23;
        }
        ls0 += __shfl_xor_sync(0xffffffffu, ls0, 1);
        ls0 += __shfl_xor_sync(0xffffffffu, ls0, 2);
        ls1 += __shfl_xor_sync(0xffffffffu, ls1, 1);
        ls1 += __shfl_xor_sync(0xffffffffu, ls1, 2);
        l0r = l0r * cf0 + ls0;
        l1r = l1r * cf1 + ls1;

#pragma unroll
        for (int nf = 0; nf < 16; nf++) {
            O[nf][0] *= cf0; O[nf][1] *= cf0;
            O[nf][2] *= cf1; O[nf][3] *= cf1;
        }
        __syncthreads();

        const uint32_t vb = VBUF(bf) + vaddrL;
#pragma unroll
        for (int ks = 0; ks < 4; ks++) {
            uint32_t a[4], bb[16][2];
            LDSM_X4(a[0], a[1], a[2], a[3], paddr + ks*32);
#pragma unroll
            for (int nf = 0; nf < 16; nf++)
                LDSM_X2T(bb[nf][0], bb[nf][1], vb + ks*4352 + nf*16);
#pragma unroll
            for (int nf = 0; nf < 16; nf++)
                MMA_F16(O[nf], a, bb[nf]);
        }
        __syncthreads();

        if (t + 2 < 32) LOAD_KV(t + 2, bf);
        CP_WAIT1();
    }
#undef LOAD_KV

    const float inv0 = 1.0f / l0r;
    const float inv1 = 1.0f / l1r;
    __half* C0 = CTX + ((size_t)(b*SS + qg0)) * DD + h*DHH;
    __half* C1 = CTX + ((size_t)(b*SS + qg8)) * DD + h*DHH;
#pragma unroll
    for (int nf = 0; nf < 16; nf++) {
        const int c2 = nf*8 + 2*cc;
        const __half2 h0 = __floats2half2_rn(O[nf][0]*inv0, O[nf][1]*inv0);
        const __half2 h1 = __floats2half2_rn(O[nf][2]*inv1, O[nf][3]*inv1);
        *(uint32_t*)(C0 + c2) = *(const uint32_t*)&h0;
        *(uint32_t*)(C1 + c2) = *(const uint32_t*)&h1;
    }
}

// ---------------------------------------------------------------------------
// Launch
// ---------------------------------------------------------------------------
extern "C" void kernel_launch(void* const* d_in, const int* in_sizes, int n_in,
                              void* d_out, int out_size)
{
    const float*         hidden  = (const float*)d_in[0];
    const unsigned char* mask    = (const unsigned char*)d_in[1];
    const int*           pos     = (const int*)d_in[2];
    const float*         ln1_g   = (const float*)d_in[3];
    const float*         ln1_b   = (const float*)d_in[4];
    const float*         Wqkv    = (const float*)d_in[5];
    const float*         Wo      = (const float*)d_in[6];
    const float*         ln2_g   = (const float*)d_in[7];
    const float*         ln2_b   = (const float*)d_in[8];
    const float*         Wfc_in  = (const float*)d_in[9];
    const float*         Wfc_out = (const float*)d_in[10];
    float*               out     = (float*)d_out;

    __half *X, *QKV, *Q, *K, *V, *CTX, *X2, *G;
    __half *WqkvT, *WoT, *WfciT, *WfcoT;
    float *H1;
    cudaGetSymbolAddress((void**)&X,     g_X);
    cudaGetSymbolAddress((void**)&QKV,   g_QKV);
    cudaGetSymbolAddress((void**)&Q,     g_Q);
    cudaGetSymbolAddress((void**)&K,     g_K);
    cudaGetSymbolAddress((void**)&V,     g_V);
    cudaGetSymbolAddress((void**)&CTX,   g_CTX);
    cudaGetSymbolAddress((void**)&H1,    g_H1);
    cudaGetSymbolAddress((void**)&X2,    g_X2);
    cudaGetSymbolAddress((void**)&G,     g_G);
    cudaGetSymbolAddress((void**)&WqkvT, g_WqkvT);
    cudaGetSymbolAddress((void**)&WoT,   g_WoT);
    cudaGetSymbolAddress((void**)&WfciT, g_WfciT);
    cudaGetSymbolAddress((void**)&WfcoT, g_WfcoT);

    cudaFuncSetAttribute(attn_kernel,
                         cudaFuncAttributeMaxDynamicSharedMemorySize,
                         AT_SMEM_BYTES);
    cudaFuncSetAttribute((tgemm<0,1>),
                         cudaFuncAttributeMaxDynamicSharedMemorySize,
                         GM_SMEM_BYTES);
    cudaFuncSetAttribute((tgemm<1,0>),
                         cudaFuncAttributeMaxDynamicSharedMemorySize,
                         GM_SMEM_BYTES);
    cudaFuncSetAttribute((tgemm<0,2>),
                         cudaFuncAttributeMaxDynamicSharedMemorySize,
                         GM_SMEM_BYTES);

    // 0) transpose + fp16 weights -> [N,K]
    transpose_h<<<dim3(NQKV/32, DD/32),  dim3(32,8)>>>(Wqkv,    WqkvT, DD,  NQKV);
    transpose_h<<<dim3(DD/32,   DD/32),  dim3(32,8)>>>(Wo,      WoT,   DD,  DD);
    transpose_h<<<dim3(DD/32,   FFN/32), dim3(32,8)>>>(Wfc_out, WfcoT, FFN, DD);
    transpose_h_pair2<<<dim3(FFN/32, DD/32), dim3(32,8)>>>(Wfc_in, WfciT);

    // 1) LN1 (fp16 out)
    ln_kernel<<<ROWS, 256>>>(hidden, ln1_g, ln1_b, X);
    // 2) QKV projection (fp16 out)
    tgemm<0,1><<<dim3(NQKV/128, ROWS/128), 128, GM_SMEM_BYTES>>>(
        X, WqkvT, nullptr, QKV, DD, NQKV);
    // 3) RoPE + scatter
    rope_kernel<<<dim3(ROWS, HH), 128>>>(QKV, pos, Q, K, V);
    // 4) attention -> ctx (fp16)
    attn_kernel<<<dim3(SS/128, HH, BB), 256, AT_SMEM_BYTES>>>(Q, K, V, mask, CTX);
    // 5) Wo projection + residual (f32 out)
    tgemm<1,0><<<dim3(DD/128, ROWS/128), 128, GM_SMEM_BYTES>>>(
        CTX, WoT, hidden, H1, DD, DD);
    // 6) LN2 (fp16 out)
    ln_kernel<<<ROWS, 256>>>(H1, ln2_g, ln2_b, X2);
    // 7) fc_in + fused SwiGLU (fp16 G out)
    tgemm<0,2><<<dim3(NFC/128, ROWS/128), 128, GM_SMEM_BYTES>>>(
        X2, WfciT, nullptr, G, DD, NFC);
    // 8) fc_out + residual (final output, f32)
    tgemm<1,0><<<dim3(DD/128, ROWS/128), 128, GM_SMEM_BYTES>>>(
        G, WfcoT, H1, out, FFN, DD);
}

// round 11
// speedup vs baseline: 1.2629x; 1.0197x over previous
#include <cuda_runtime.h>
#include <cuda_fp16.h>
#include <math.h>
#include <stdint.h>

// ---------------------------------------------------------------------------
// Problem constants
// ---------------------------------------------------------------------------
#define BB   2
#define SS   2048
#define DD   2048
#define HH   16
#define DHH  128
#define FFN  5632
#define ROWS (BB*SS)           // 4096
#define NQKV (3*HH*DHH)        // 6144
#define NFC  (2*FFN)           // 11264

// ---------------------------------------------------------------------------
// Scratch
// ---------------------------------------------------------------------------
__device__ __half g_X  [ROWS*DD];    // LN1 out
__device__ __half g_QKV[ROWS*NQKV];  // qkv proj (fp16)
__device__ __half g_Q  [ROWS*DD];    // [B,H,S,DH]
__device__ __half g_K  [ROWS*DD];
__device__ __half g_V  [ROWS*DD];    // [B,H,S,DH]
__device__ __half g_CTX[ROWS*DD];    // [B,S,H*DH]
__device__ float  g_H1 [ROWS*DD];    // residual 1 (fp32)
__device__ __half g_X2 [ROWS*DD];    // LN2 out
__device__ __half g_G  [ROWS*FFN];   // swiglu out (written by fused fc_in)
__device__ float2 g_rtab[ROWS*64];   // rope (cos, sin) table per (row, freq)
// transposed weights [N,K] K-major, fp16
__device__ __half g_WqkvT [NQKV*DD];
__device__ __half g_WoT   [DD*DD];
__device__ __half g_WfciT [NFC*DD];  // interleaved: row 2j = a_j, 2j+1 = b_j
__device__ __half g_WfcoT [DD*FFN];

// ---------------------------------------------------------------------------
// Helpers
// ---------------------------------------------------------------------------
__device__ __forceinline__ uint32_t smem_u32(const void* p) {
    uint32_t a;
    asm("{ .reg .u64 t; cvta.to.shared.u64 t, %1; cvt.u32.u64 %0, t; }"
        : "=r"(a) : "l"(p));
    return a;
}

#define CP_ASYNC16(dst, src) \
    asm volatile("cp.async.cg.shared.global [%0], [%1], 16;" \
                 :: "r"(dst), "l"(src))
#define CP_COMMIT() asm volatile("cp.async.commit_group;" ::: "memory")
#define CP_WAIT2()  asm volatile("cp.async.wait_group 2;" ::: "memory")
#define CP_WAIT1()  asm volatile("cp.async.wait_group 1;" ::: "memory")
#define CP_WAIT0()  asm volatile("cp.async.wait_group 0;" ::: "memory")

#define MMA_F16(d, a, b)                                                   \
    asm volatile(                                                          \
        "mma.sync.aligned.m16n8k16.row.col.f32.f16.f16.f32 "               \
        "{%0,%1,%2,%3}, {%4,%5,%6,%7}, {%8,%9}, {%0,%1,%2,%3};"            \
        : "+f"((d)[0]), "+f"((d)[1]), "+f"((d)[2]), "+f"((d)[3])           \
        : "r"((a)[0]), "r"((a)[1]), "r"((a)[2]), "r"((a)[3]),              \
          "r"((b)[0]), "r"((b)[1]))

#define LDSM_X4(r0, r1, r2, r3, addr)                                      \
    asm volatile("ldmatrix.sync.aligned.m8n8.x4.shared.b16 "               \
                 "{%0,%1,%2,%3}, [%4];"                                    \
                 : "=r"(r0), "=r"(r1), "=r"(r2), "=r"(r3) : "r"(addr))

#define LDSM_X2(r0, r1, addr)                                              \
    asm volatile("ldmatrix.sync.aligned.m8n8.x2.shared.b16 "               \
                 "{%0,%1}, [%2];"                                          \
                 : "=r"(r0), "=r"(r1) : "r"(addr))

#define LDSM_X2T(r0, r1, addr)                                             \
    asm volatile("ldmatrix.sync.aligned.m8n8.x2.trans.shared.b16 "         \
                 "{%0,%1}, [%2];"                                          \
                 : "=r"(r0), "=r"(r1) : "r"(addr))

// ---------------------------------------------------------------------------
// Weight transpose + fp16 round: W[K,N] f32 -> Wt[N,K] f16
// ---------------------------------------------------------------------------
__global__ void __launch_bounds__(256) transpose_h(
    const float* __restrict__ W, __half* __restrict__ Wt, int K, int N)
{
    __shared__ float t[32][33];
    const int tx = threadIdx.x, ty = threadIdx.y;
    const int n0 = blockIdx.x * 32, k0 = blockIdx.y * 32;
#pragma unroll
    for (int j = 0; j < 4; j++)
        t[ty + j*8][tx] = W[(size_t)(k0 + ty + j*8) * N + n0 + tx];
    __syncthreads();
#pragma unroll
    for (int j = 0; j < 4; j++)
        Wt[(size_t)(n0 + ty + j*8) * K + k0 + tx] = __float2half_rn(t[tx][ty + j*8]);
}

// Merged paired transpose for fc_in: a-col j -> row 2j, b-col j -> row 2j+1.
__global__ void __launch_bounds__(256) transpose_h_pair2(
    const float* __restrict__ W, __half* __restrict__ Wt)
{
    __shared__ float ta[32][33];
    __shared__ float tb[32][33];
    const int tx = threadIdx.x, ty = threadIdx.y;
    const int n0 = blockIdx.x * 32, k0 = blockIdx.y * 32;
#pragma unroll
    for (int j = 0; j < 4; j++) {
        const size_t rbase = (size_t)(k0 + ty + j*8) * NFC;
        ta[ty + j*8][tx] = W[rbase + n0 + tx];
        tb[ty + j*8][tx] = W[rbase + FFN + n0 + tx];
    }
    __syncthreads();
#pragma unroll
    for (int j = 0; j < 4; j++) {
        const int n = n0 + ty + j*8;
        Wt[(size_t)(2*n)     * DD + k0 + tx] = __float2half_rn(ta[tx][ty + j*8]);
        Wt[(size_t)(2*n + 1) * DD + k0 + tx] = __float2half_rn(tb[tx][ty + j*8]);
    }
}

// ---------------------------------------------------------------------------
// Rope sin/cos table: tab[row][j] = (cos, sin) of pos_ids[row] * inv_freq(j)
// ---------------------------------------------------------------------------
__global__ void __launch_bounds__(64) rtab_kernel(
    const int* __restrict__ pos_ids, float2* __restrict__ tab)
{
    const int r = blockIdx.x;      // 0..ROWS-1
    const int j = threadIdx.x;     // 0..63
    const float pos = (float)pos_ids[r];
    const float inv = 1.0f / powf(10000.0f, (float)(2*j) * (1.0f/128.0f));
    float sn, cs;
    sincosf(pos * inv, &sn, &cs);
    tab[r*64 + j] = make_float2(cs, sn);
}

// ---------------------------------------------------------------------------
// FP16 mma.sync GEMM, ldmatrix fragments, 4-stage cp.async pipeline.
// CTA tile 128x128x32, 4 warps (2M x 2N), warp tile 64x64.  (champion)
// OUT: 0 = f32 (+residual if EPI), 1 = f16, 2 = f16 fused swiglu (paired cols)
// ---------------------------------------------------------------------------
#define TILE_BYTES 10240              // 128 rows * 80 B
#define STAGE_BYTES (2*TILE_BYTES)
#define GM_SMEM_BYTES (4*STAGE_BYTES) // 81920

template<int EPI, int OUT>
__global__ void __launch_bounds__(128, 2) tgemm(
    const __half* __restrict__ A, const __half* __restrict__ Bt,
    const float* __restrict__ R, void* __restrict__ Cv,
    int K, int N)
{
    extern __shared__ char smc[];
    const uint32_t smb = smem_u32(smc);

    const int tid  = threadIdx.x;
    const int wid  = tid >> 5;
    const int lane = tid & 31;
    const int g    = lane >> 2;
    const int cc   = lane & 3;
    const int wm   = (wid & 1) * 64;
    const int wn   = (wid >> 1) * 64;

    const int m0 = blockIdx.y * 128;
    const int n0 = blockIdx.x * 128;

    const __half* Ab = A  + (size_t)m0 * K;
    const __half* Bb = Bt + (size_t)n0 * K;

    const int NC = K / 32;

    const uint32_t aoff = (uint32_t)(wm + (lane & 15)) * 80 + (lane >> 4) * 16;
    const uint32_t boff = (uint32_t)(wn + (lane & 7) + ((lane >> 4) * 8)) * 80
                        + ((lane >> 3) & 1) * 16;

#define LOAD_STAGE(chunk, st) do {                                         \
        const uint32_t asw = smb + (st)*STAGE_BYTES;                       \
        const uint32_t bsw = asw + TILE_BYTES;                             \
        const int kt = (chunk) * 32;                                       \
        _Pragma("unroll")                                                  \
        for (int j = 0; j < 4; j++) {                                      \
            const int f = tid + j * 128;                                   \
            const int row = f >> 2, c4 = f & 3;                            \
            CP_ASYNC16(asw + (uint32_t)(row*80 + c4*16),                   \
                       Ab + (size_t)row * K + kt + c4*8);                  \
            CP_ASYNC16(bsw + (uint32_t)(row*80 + c4*16),                   \
                       Bb + (size_t)row * K + kt + c4*8);                  \
        }                                                                  \
        CP_COMMIT();                                                       \
    } while (0)

    float acc[4][8][4];
#pragma unroll
    for (int mf = 0; mf < 4; mf++)
#pragma unroll
        for (int nf = 0; nf < 8; nf++)
#pragma unroll
            for (int q = 0; q < 4; q++) acc[mf][nf][q] = 0.f;

    LOAD_STAGE(0, 0);
    LOAD_STAGE(1, 1);
    LOAD_STAGE(2, 2);

    for (int i = 0; i < NC; i++) {
        if (i < NC - 2)       CP_WAIT2();
        else if (i == NC - 2) CP_WAIT1();
        else                  CP_WAIT0();
        __syncthreads();
        if (i + 3 < NC) LOAD_STAGE(i + 3, (i + 3) & 3);

        const uint32_t abase = smb + (i & 3) * STAGE_BYTES;
        const uint32_t bbase = abase + TILE_BYTES;

#pragma unroll
        for (int ks = 0; ks < 2; ks++) {
            uint32_t a[4][4], b[8][2];
#pragma unroll
            for (int mf = 0; mf < 4; mf++)
                LDSM_X4(a[mf][0], a[mf][1], a[mf][2], a[mf][3],
                        abase + aoff + mf*1280 + ks*32);
#pragma unroll
            for (int p = 0; p < 4; p++)
                LDSM_X4(b[2*p][0], b[2*p][1], b[2*p+1][0], b[2*p+1][1],
                        bbase + boff + p*1280 + ks*32);
#pragma unroll
            for (int mf = 0; mf < 4; mf++)
#pragma unroll
                for (int nf = 0; nf < 8; nf++)
                    MMA_F16(acc[mf][nf], a[mf], b[nf]);
        }
    }
#undef LOAD_STAGE

#pragma unroll
    for (int mf = 0; mf < 4; mf++) {
#pragma unroll
        for (int nf = 0; nf < 8; nf++) {
            const int row = m0 + wm + mf * 16 + g;
            const int col = n0 + wn + nf * 8 + cc * 2;
            float2 v0 = { acc[mf][nf][0], acc[mf][nf][1] };
            float2 v1 = { acc[mf][nf][2], acc[mf][nf][3] };
            if (OUT == 2) {
                __half* Gp = (__half*)Cv;
                const int gcol = col >> 1;
                const float s0 = v0.x / (1.0f + __expf(-v0.x)) * v0.y;
                const float s1 = v1.x / (1.0f + __expf(-v1.x)) * v1.y;
                Gp[(size_t)row * FFN + gcol]       = __float2half_rn(s0);
                Gp[(size_t)(row + 8) * FFN + gcol] = __float2half_rn(s1);
            } else {
                const size_t o0 = (size_t)row * N + col;
                const size_t o1 = (size_t)(row + 8) * N + col;
                if (EPI == 1) {
                    float2 r0 = *(const float2*)&R[o0];
                    float2 r1 = *(const float2*)&R[o1];
                    v0.x += r0.x; v0.y += r0.y;
                    v1.x += r1.x; v1.y += r1.y;
                }
                if (OUT == 1) {
                    __half* C = (__half*)Cv;
                    const __half2 h0 = __floats2half2_rn(v0.x, v0.y);
                    const __half2 h1 = __floats2half2_rn(v1.x, v1.y);
                    *(uint32_t*)&C[o0] = *(const uint32_t*)&h0;
                    *(uint32_t*)&C[o1] = *(const uint32_t*)&h1;
                } else {
                    float* C = (float*)Cv;
                    *(float2*)&C[o0] = v0;
                    *(float2*)&C[o1] = v1;
                }
            }
        }
    }
}

// ---------------------------------------------------------------------------
// LayerNorm: fp32 in, fp16 out
// ---------------------------------------------------------------------------
__global__ void __launch_bounds__(256) ln_kernel(
    const float* __restrict__ X, const float* __restrict__ g,
    const float* __restrict__ b, __half* __restrict__ Y)
{
    const int tid = threadIdx.x;
    const float* x = X + (size_t)blockIdx.x * DD;
    __half* y = Y + (size_t)blockIdx.x * DD;

    float v[8];
    *(float4*)&v[0] = *(const float4*)&x[tid*8];
    *(float4*)&v[4] = *(const float4*)&x[tid*8 + 4];

    float s = 0.f, sq = 0.f;
#pragma unroll
    for (int i = 0; i < 8; i++) { s += v[i]; sq += v[i]*v[i]; }
#pragma unroll
    for (int o = 16; o; o >>= 1) {
        s  += __shfl_xor_sync(0xffffffffu, s,  o);
        sq += __shfl_xor_sync(0xffffffffu, sq, o);
    }
    __shared__ float red[2][8];
    __shared__ float stats[2];
    const int w = tid >> 5, l = tid & 31;
    if (l == 0) { red[0][w] = s; red[1][w] = sq; }
    __syncthreads();
    if (tid == 0) {
        float S = 0.f, SQ = 0.f;
#pragma unroll
        for (int i = 0; i < 8; i++) { S += red[0][i]; SQ += red[1][i]; }
        const float mean = S * (1.0f/DD);
        const float var  = SQ * (1.0f/DD) - mean*mean;
        stats[0] = mean;
        stats[1] = rsqrtf(var + 1e-5f);
    }
    __syncthreads();
    const float mean = stats[0], rstd = stats[1];

    float gv[8], bv[8];
    *(float4*)&gv[0] = *(const float4*)&g[tid*8];
    *(float4*)&gv[4] = *(const float4*)&g[tid*8+4];
    *(float4*)&bv[0] = *(const float4*)&b[tid*8];
    *(float4*)&bv[4] = *(const float4*)&b[tid*8+4];

    __half2 h[4];
#pragma unroll
    for (int i = 0; i < 4; i++) {
        const float a0 = (v[2*i]   - mean) * rstd * gv[2*i]   + bv[2*i];
        const float a1 = (v[2*i+1] - mean) * rstd * gv[2*i+1] + bv[2*i+1];
        h[i] = __floats2half2_rn(a0, a1);
    }
    *(uint4*)&y[tid*8] = *(uint4*)h;
}

// ---------------------------------------------------------------------------
// RoPE + scatter (table-driven, trig-free): 64 threads per (bs, h).
// Each thread handles the (d, d+64) pair -> one table entry, 6 outputs.
// ---------------------------------------------------------------------------
__global__ void __launch_bounds__(64) rope_kernel(
    const __half* __restrict__ QKV, const float2* __restrict__ tab,
    __half* __restrict__ Q, __half* __restrict__ K, __half* __restrict__ V)
{
    const int bs = blockIdx.x;      // 0..4095
    const int h  = blockIdx.y;      // 0..15
    const int d2 = threadIdx.x;     // 0..63

    const __half* row = QKV + (size_t)bs * NQKV + h * (3*DHH);
    const float2 t = tab[bs*64 + d2];
    const float cs = t.x, sn = t.y;

    const float q0 = __half2float(row[d2]);
    const float q1 = __half2float(row[d2 + 64]);
    const float k0 = __half2float(row[DHH + d2]);
    const float k1 = __half2float(row[DHH + d2 + 64]);

    const int b = bs >> 11, s = bs & 2047;
    const size_t o = (((size_t)(b*HH + h)) * SS + s) * DHH;

    Q[o + d2]      = __float2half_rn(q0*cs - q1*sn);
    Q[o + d2 + 64] = __float2half_rn(q1*cs + q0*sn);
    K[o + d2]      = __float2half_rn(k0*cs - k1*sn);
    K[o + d2 + 64] = __float2half_rn(k1*cs + k0*sn);
    V[o + d2]      = row[2*DHH + d2];
    V[o + d2 + 64] = row[2*DHH + d2 + 64];
}

// ---------------------------------------------------------------------------
// Flash attention: fp16 mma + ldmatrix, cp.async double-buffered K/V tiles,
// V via ldmatrix.trans, Q frags in registers, P kept in REGISTERS
// (S-accumulator layout == PV A-fragment layout) -> 1 sync per tile.
// ---------------------------------------------------------------------------
#define AT_SMEM_BYTES (26112*4)

__global__ void __launch_bounds__(256) attn_kernel(
    const __half* __restrict__ Q, const __half* __restrict__ K,
    const __half* __restrict__ V, const unsigned char* __restrict__ mask,
    __half* __restrict__ CTX)
{
    extern __shared__ uint32_t smu[];
    const uint32_t smb = smem_u32(smu);
    const uint32_t kB0 = smb + 8704*4;
    const uint32_t vB0 = smb + 17408*4;
#define KBUF(bf) (kB0 + (bf)*17408)
#define VBUF(bf) (vB0 + (bf)*17408)

    const int tid  = threadIdx.x;
    const int lane = tid & 31;
    const int wid  = tid >> 5;
    const int g    = lane >> 2;
    const int cc   = lane & 3;
    const int wm   = wid * 16;

    const int qt = blockIdx.x, h = blockIdx.y, b = blockIdx.z;
    const size_t headoff = ((size_t)(b*HH + h)) * SS * DHH;
    const __half* Qg    = Q + headoff + (size_t)qt * 128 * DHH;
    const __half* Kbase = K + headoff;
    const __half* Vbase = V + headoff;

#pragma unroll
    for (int j = 0; j < 8; j++) {
        const int f = tid + j * 256;
        const int r = f >> 4, c = f & 15;
        CP_ASYNC16(smb + (uint32_t)(r*272 + c*16), Qg + r*DHH + c*8);
    }
    CP_COMMIT();

#define LOAD_KV(t, bf) do {                                                \
        const __half* Kg_ = Kbase + (size_t)(t) * 64 * DHH;                \
        const __half* Vg_ = Vbase + (size_t)(t) * 64 * DHH;                \
        _Pragma("unroll")                                                  \
        for (int j = 0; j < 4; j++) {                                      \
            const int f = tid + j * 256;                                   \
            const int r = f >> 4, c = f & 15;                              \
            CP_ASYNC16(KBUF(bf) + (uint32_t)(r*272 + c*16),                \
                       Kg_ + r*DHH + c*8);                                 \
            CP_ASYNC16(VBUF(bf) + (uint32_t)(r*272 + c*16),                \
                       Vg_ + r*DHH + c*8);                                 \
        }                                                                  \
        CP_COMMIT();                                                       \
    } while (0)

    LOAD_KV(0, 0);
    LOAD_KV(1, 1);

    CP_WAIT1();
    __syncthreads();

    uint32_t qf[8][4];
    {
        const uint32_t qaddr = smb + (uint32_t)(wm + (lane & 15)) * 272
                             + (lane >> 4) * 16;
#pragma unroll
        for (int ks = 0; ks < 8; ks++)
            LDSM_X4(qf[ks][0], qf[ks][1], qf[ks][2], qf[ks][3], qaddr + ks*32);
    }

    const uint32_t kaddrL = (uint32_t)(lane & 7) * 272 + ((lane >> 3) & 1) * 16;
    const uint32_t vaddrL = (uint32_t)(lane & 15) * 272;

    float m0r = -1e30f, m1r = -1e30f, l0r = 0.f, l1r = 0.f;
    float O[16][4];
#pragma unroll
    for (int nf = 0; nf < 16; nf++)
#pragma unroll
        for (int q = 0; q < 4; q++) O[nf][q] = 0.f;

    const float scale = 0.08838834764831845f;
    const unsigned char* mrow = mask + (size_t)b * SS * SS;
    const int qg0 = qt * 128 + wm + g;
    const int qg8 = qg0 + 8;

    for (int t = 0; t < 32; t++) {
        const int bf = t & 1;
        const int kt = t * 64;

        unsigned short mRa[8], mRb[8];
        {
            const unsigned char* mpA = mrow + (size_t)qg0 * SS + kt + 2*cc;
            const unsigned char* mpB = mrow + (size_t)qg8 * SS + kt + 2*cc;
#pragma unroll
            for (int nf = 0; nf < 8; nf++) {
                mRa[nf] = *(const unsigned short*)(mpA + nf*8);
                mRb[nf] = *(const unsigned short*)(mpB + nf*8);
            }
        }

        float s[8][4];
#pragma unroll
        for (int nf = 0; nf < 8; nf++)
#pragma unroll
            for (int q = 0; q < 4; q++) s[nf][q] = 0.f;

        const uint32_t kb = KBUF(bf) + kaddrL;
#pragma unroll
        for (int ks = 0; ks < 8; ks++) {
            uint32_t bb[8][2];
#pragma unroll
            for (int nf = 0; nf < 8; nf++)
                LDSM_X2(bb[nf][0], bb[nf][1], kb + nf*2176 + ks*32);
#pragma unroll
            for (int nf = 0; nf < 8; nf++)
                MMA_F16(s[nf], qf[ks], bb[nf]);
        }

        float rmax0 = -1e30f, rmax1 = -1e30f;
#pragma unroll
        for (int nf = 0; nf < 8; nf++) {
            float s0 = s[nf][0]*scale, s1 = s[nf][1]*scale;
            float s2 = s[nf][2]*scale, s3 = s[nf][3]*scale;
            if (mRa[nf] & 0x00ffu) s0 = -10000.f;
            if (mRa[nf] & 0xff00u) s1 = -10000.f;
            if (mRb[nf] & 0x00ffu) s2 = -10000.f;
            if (mRb[nf] & 0xff00u) s3 = -10000.f;
            s[nf][0] = s0; s[nf][1] = s1; s[nf][2] = s2; s[nf][3] = s3;
            rmax0 = fmaxf(rmax0, fmaxf(s0, s1));
            rmax1 = fmaxf(rmax1, fmaxf(s2, s3));
        }
        rmax0 = fmaxf(rmax0, __shfl_xor_sync(0xffffffffu, rmax0, 1));
        rmax0 = fmaxf(rmax0, __shfl_xor_sync(0xffffffffu, rmax0, 2));
        rmax1 = fmaxf(rmax1, __shfl_xor_sync(0xffffffffu, rmax1, 1));
        rmax1 = fmaxf(rmax1, __shfl_xor_sync(0xffffffffu, rmax1, 2));

        const float mn0 = fmaxf(m0r, rmax0);
        const float mn1 = fmaxf(m1r, rmax1);
        const float cf0 = __expf(m0r - mn0);
        const float cf1 = __expf(m1r - mn1);
        m0r = mn0; m1r = mn1;

        // P stays in registers: S-accumulator layout == PV A-fragment layout
        uint32_t pfrag[8][2];
        float ls0 = 0.f, ls1 = 0.f;
#pragma unroll
        for (int nf = 0; nf < 8; nf++) {
            const float p0 = __expf(s[nf][0] - mn0);
            const float p1 = __expf(s[nf][1] - mn0);
            const float p2 = __expf(s[nf][2] - mn1);
            const float p3 = __expf(s[nf][3] - mn1);
            ls0 += p0 + p1; ls1 += p2 + p3;
            const __half2 h01 = __floats2half2_rn(p0, p1);
            const __half2 h23 = __floats2half2_rn(p2, p3);
            pfrag[nf][0] = *(const uint32_t*)&h01;   // rows g
            pfrag[nf][1] = *(const uint32_t*)&h23;   // rows g+8
        }
        ls0 += __shfl_xor_sync(0xffffffffu, ls0, 1);
        ls0 += __shfl_xor_sync(0xffffffffu, ls0, 2);
        ls1 += __shfl_xor_sync(0xffffffffu, ls1, 1);
        ls1 += __shfl_xor_sync(0xffffffffu, ls1, 2);
        l0r = l0r * cf0 + ls0;
        l1r = l1r * cf1 + ls1;

#pragma unroll
        for (int nf = 0; nf < 16; nf++) {
            O[nf][0] *= cf0; O[nf][1] *= cf0;
            O[nf][2] *= cf1; O[nf][3] *= cf1;
        }

        // ---- O += P @ V : 4 k-steps of 16 kv, A from registers ----
        const uint32_t vb = VBUF(bf) + vaddrL;
#pragma unroll
        for (int ks = 0; ks < 4; ks++) {
            uint32_t a[4] = { pfrag[2*ks][0],   pfrag[2*ks][1],
                              pfrag[2*ks+1][0], pfrag[2*ks+1][1] };
            uint32_t bb[16][2];
#pragma unroll
            for (int nf = 0; nf < 16; nf++)
                LDSM_X2T(bb[nf][0], bb[nf][1], vb + ks*4352 + nf*16);
#pragma unroll
            for (int nf = 0; nf < 16; nf++)
                MMA_F16(O[nf], a, bb[nf]);
        }
        __syncthreads();   // K/V buffers fully consumed by all warps

        if (t + 2 < 32) LOAD_KV(t + 2, bf);
        CP_WAIT1();
    }
#undef LOAD_KV

    const float inv0 = 1.0f / l0r;
    const float inv1 = 1.0f / l1r;
    __half* C0 = CTX + ((size_t)(b*SS + qg0)) * DD + h*DHH;
    __half* C1 = CTX + ((size_t)(b*SS + qg8)) * DD + h*DHH;
#pragma unroll
    for (int nf = 0; nf < 16; nf++) {
        const int c2 = nf*8 + 2*cc;
        const __half2 h0 = __floats2half2_rn(O[nf][0]*inv0, O[nf][1]*inv0);
        const __half2 h1 = __floats2half2_rn(O[nf][2]*inv1, O[nf][3]*inv1);
        *(uint32_t*)(C0 + c2) = *(const uint32_t*)&h0;
        *(uint32_t*)(C1 + c2) = *(const uint32_t*)&h1;
    }
}

// ---------------------------------------------------------------------------
// Launch
// ---------------------------------------------------------------------------
extern "C" void kernel_launch(void* const* d_in, const int* in_sizes, int n_in,
                              void* d_out, int out_size)
{
    const float*         hidden  = (const float*)d_in[0];
    const unsigned char* mask    = (const unsigned char*)d_in[1];
    const int*           pos     = (const int*)d_in[2];
    const float*         ln1_g   = (const float*)d_in[3];
    const float*         ln1_b   = (const float*)d_in[4];
    const float*         Wqkv    = (const float*)d_in[5];
    const float*         Wo      = (const float*)d_in[6];
    const float*         ln2_g   = (const float*)d_in[7];
    const float*         ln2_b   = (const float*)d_in[8];
    const float*         Wfc_in  = (const float*)d_in[9];
    const float*         Wfc_out = (const float*)d_in[10];
    float*               out     = (float*)d_out;

    __half *X, *QKV, *Q, *K, *V, *CTX, *X2, *G;
    __half *WqkvT, *WoT, *WfciT, *WfcoT;
    float *H1;
    float2 *RTAB;
    cudaGetSymbolAddress((void**)&X,     g_X);
    cudaGetSymbolAddress((void**)&QKV,   g_QKV);
    cudaGetSymbolAddress((void**)&Q,     g_Q);
    cudaGetSymbolAddress((void**)&K,     g_K);
    cudaGetSymbolAddress((void**)&V,     g_V);
    cudaGetSymbolAddress((void**)&CTX,   g_CTX);
    cudaGetSymbolAddress((void**)&H1,    g_H1);
    cudaGetSymbolAddress((void**)&X2,    g_X2);
    cudaGetSymbolAddress((void**)&G,     g_G);
    cudaGetSymbolAddress((void**)&RTAB,  g_rtab);
    cudaGetSymbolAddress((void**)&WqkvT, g_WqkvT);
    cudaGetSymbolAddress((void**)&WoT,   g_WoT);
    cudaGetSymbolAddress((void**)&WfciT, g_WfciT);
    cudaGetSymbolAddress((void**)&WfcoT, g_WfcoT);

    cudaFuncSetAttribute(attn_kernel,
                         cudaFuncAttributeMaxDynamicSharedMemorySize,
                         AT_SMEM_BYTES);
    cudaFuncSetAttribute((tgemm<0,1>),
                         cudaFuncAttributeMaxDynamicSharedMemorySize,
                         GM_SMEM_BYTES);
    cudaFuncSetAttribute((tgemm<1,0>),
                         cudaFuncAttributeMaxDynamicSharedMemorySize,
                         GM_SMEM_BYTES);
    cudaFuncSetAttribute((tgemm<0,2>),
                         cudaFuncAttributeMaxDynamicSharedMemorySize,
                         GM_SMEM_BYTES);

    // 0) weight transposes + rope table
    transpose_h<<<dim3(NQKV/32, DD/32),  dim3(32,8)>>>(Wqkv,    WqkvT, DD,  NQKV);
    transpose_h<<<dim3(DD/32,   DD/32),  dim3(32,8)>>>(Wo,      WoT,   DD,  DD);
    transpose_h<<<dim3(DD/32,   FFN/32), dim3(32,8)>>>(Wfc_out, WfcoT, FFN, DD);
    transpose_h_pair2<<<dim3(FFN/32, DD/32), dim3(32,8)>>>(Wfc_in, WfciT);
    rtab_kernel<<<ROWS, 64>>>(pos, RTAB);

    // 1) LN1 (fp16 out)
    ln_kernel<<<ROWS, 256>>>(hidden, ln1_g, ln1_b, X);
    // 2) QKV projection (fp16 out)
    tgemm<0,1><<<dim3(NQKV/128, ROWS/128), 128, GM_SMEM_BYTES>>>(
        X, WqkvT, nullptr, QKV, DD, NQKV);
    // 3) RoPE + scatter (table-driven)
    rope_kernel<<<dim3(ROWS, HH), 64>>>(QKV, RTAB, Q, K, V);
    // 4) attention -> ctx (fp16)
    attn_kernel<<<dim3(SS/128, HH, BB), 256, AT_SMEM_BYTES>>>(Q, K, V, mask, CTX);
    // 5) Wo projection + residual (f32 out)
    tgemm<1,0><<<dim3(DD/128, ROWS/128), 128, GM_SMEM_BYTES>>>(
        CTX, WoT, hidden, H1, DD, DD);
    // 6) LN2 (fp16 out)
    ln_kernel<<<ROWS, 256>>>(H1, ln2_g, ln2_b, X2);
    // 7) fc_in + fused SwiGLU (fp16 G out)
    tgemm<0,2><<<dim3(NFC/128, ROWS/128), 128, GM_SMEM_BYTES>>>(
        X2, WfciT, nullptr, G, DD, NFC);
    // 8) fc_out + residual (final output, f32)
    tgemm<1,0><<<dim3(DD/128, ROWS/128), 128, GM_SMEM_BYTES>>>(
        G, WfcoT, H1, out, FFN, DD);
}

// round 12
// speedup vs baseline: 1.2708x; 1.0063x over previous
#include <cuda_runtime.h>
#include <cuda_fp16.h>
#include <math.h>
#include <stdint.h>

// ---------------------------------------------------------------------------
// Problem constants
// ---------------------------------------------------------------------------
#define BB   2
#define SS   2048
#define DD   2048
#define HH   16
#define DHH  128
#define FFN  5632
#define ROWS (BB*SS)           // 4096
#define NQKV (3*HH*DHH)        // 6144
#define NFC  (2*FFN)           // 11264

// ---------------------------------------------------------------------------
// Scratch
// ---------------------------------------------------------------------------
__device__ __half g_X  [ROWS*DD];    // LN1 out
__device__ __half g_Q  [ROWS*DD];    // [B,H,S,DH]
__device__ __half g_K  [ROWS*DD];
__device__ __half g_V  [ROWS*DD];    // [B,H,S,DH]
__device__ __half g_CTX[ROWS*DD];    // [B,S,H*DH]
__device__ float  g_H1 [ROWS*DD];    // residual 1 (fp32)
__device__ __half g_X2 [ROWS*DD];    // LN2 out
__device__ __half g_G  [ROWS*FFN];   // swiglu out (written by fused fc_in)
__device__ float2 g_rtab[ROWS*64];   // rope (cos, sin) table per (row, freq)
// transposed weights [N,K] K-major, fp16
__device__ __half g_WqkvT [NQKV*DD];
__device__ __half g_WoT   [DD*DD];
__device__ __half g_WfciT [NFC*DD];  // interleaved: row 2j = a_j, 2j+1 = b_j
__device__ __half g_WfcoT [DD*FFN];

// ---------------------------------------------------------------------------
// Helpers
// ---------------------------------------------------------------------------
__device__ __forceinline__ uint32_t smem_u32(const void* p) {
    uint32_t a;
    asm("{ .reg .u64 t; cvta.to.shared.u64 t, %1; cvt.u32.u64 %0, t; }"
        : "=r"(a) : "l"(p));
    return a;
}

#define CP_ASYNC16(dst, src) \
    asm volatile("cp.async.cg.shared.global [%0], [%1], 16;" \
                 :: "r"(dst), "l"(src))
#define CP_COMMIT() asm volatile("cp.async.commit_group;" ::: "memory")
#define CP_WAIT2()  asm volatile("cp.async.wait_group 2;" ::: "memory")
#define CP_WAIT1()  asm volatile("cp.async.wait_group 1;" ::: "memory")
#define CP_WAIT0()  asm volatile("cp.async.wait_group 0;" ::: "memory")

#define MMA_F16(d, a, b)                                                   \
    asm volatile(                                                          \
        "mma.sync.aligned.m16n8k16.row.col.f32.f16.f16.f32 "               \
        "{%0,%1,%2,%3}, {%4,%5,%6,%7}, {%8,%9}, {%0,%1,%2,%3};"            \
        : "+f"((d)[0]), "+f"((d)[1]), "+f"((d)[2]), "+f"((d)[3])           \
        : "r"((a)[0]), "r"((a)[1]), "r"((a)[2]), "r"((a)[3]),              \
          "r"((b)[0]), "r"((b)[1]))

#define LDSM_X4(r0, r1, r2, r3, addr)                                      \
    asm volatile("ldmatrix.sync.aligned.m8n8.x4.shared.b16 "               \
                 "{%0,%1,%2,%3}, [%4];"                                    \
                 : "=r"(r0), "=r"(r1), "=r"(r2), "=r"(r3) : "r"(addr))

#define LDSM_X2(r0, r1, addr)                                              \
    asm volatile("ldmatrix.sync.aligned.m8n8.x2.shared.b16 "               \
                 "{%0,%1}, [%2];"                                          \
                 : "=r"(r0), "=r"(r1) : "r"(addr))

#define LDSM_X2T(r0, r1, addr)                                             \
    asm volatile("ldmatrix.sync.aligned.m8n8.x2.trans.shared.b16 "         \
                 "{%0,%1}, [%2];"                                          \
                 : "=r"(r0), "=r"(r1) : "r"(addr))

// ---------------------------------------------------------------------------
// Weight transpose + fp16 round: W[K,N] f32 -> Wt[N,K] f16
// ---------------------------------------------------------------------------
__global__ void __launch_bounds__(256) transpose_h(
    const float* __restrict__ W, __half* __restrict__ Wt, int K, int N)
{
    __shared__ float t[32][33];
    const int tx = threadIdx.x, ty = threadIdx.y;
    const int n0 = blockIdx.x * 32, k0 = blockIdx.y * 32;
#pragma unroll
    for (int j = 0; j < 4; j++)
        t[ty + j*8][tx] = W[(size_t)(k0 + ty + j*8) * N + n0 + tx];
    __syncthreads();
#pragma unroll
    for (int j = 0; j < 4; j++)
        Wt[(size_t)(n0 + ty + j*8) * K + k0 + tx] = __float2half_rn(t[tx][ty + j*8]);
}

// Merged paired transpose for fc_in: a-col j -> row 2j, b-col j -> row 2j+1.
__global__ void __launch_bounds__(256) transpose_h_pair2(
    const float* __restrict__ W, __half* __restrict__ Wt)
{
    __shared__ float ta[32][33];
    __shared__ float tb[32][33];
    const int tx = threadIdx.x, ty = threadIdx.y;
    const int n0 = blockIdx.x * 32, k0 = blockIdx.y * 32;
#pragma unroll
    for (int j = 0; j < 4; j++) {
        const size_t rbase = (size_t)(k0 + ty + j*8) * NFC;
        ta[ty + j*8][tx] = W[rbase + n0 + tx];
        tb[ty + j*8][tx] = W[rbase + FFN + n0 + tx];
    }
    __syncthreads();
#pragma unroll
    for (int j = 0; j < 4; j++) {
        const int n = n0 + ty + j*8;
        Wt[(size_t)(2*n)     * DD + k0 + tx] = __float2half_rn(ta[tx][ty + j*8]);
        Wt[(size_t)(2*n + 1) * DD + k0 + tx] = __float2half_rn(tb[tx][ty + j*8]);
    }
}

// ---------------------------------------------------------------------------
// Rope sin/cos table: tab[row][j] = (cos, sin) of pos_ids[row] * inv_freq(j)
// ---------------------------------------------------------------------------
__global__ void __launch_bounds__(64) rtab_kernel(
    const int* __restrict__ pos_ids, float2* __restrict__ tab)
{
    const int r = blockIdx.x;
    const int j = threadIdx.x;
    const float pos = (float)pos_ids[r];
    const float inv = 1.0f / powf(10000.0f, (float)(2*j) * (1.0f/128.0f));
    float sn, cs;
    sincosf(pos * inv, &sn, &cs);
    tab[r*64 + j] = make_float2(cs, sn);
}

// ---------------------------------------------------------------------------
// FP16 mma.sync GEMM, ldmatrix fragments, 4-stage cp.async pipeline.
// CTA tile 128x128x32, 4 warps (2M x 2N), warp tile 64x64.  (champion)
// OUT: 0 = f32 (+residual if EPI), 1 = f16,
//      2 = f16 fused swiglu (paired cols),
//      3 = fused rope+scatter to Q/K/V (each tile = one {q,k,v} of one head)
// ---------------------------------------------------------------------------
#define TILE_BYTES 10240              // 128 rows * 80 B
#define STAGE_BYTES (2*TILE_BYTES)
#define GM_SMEM_BYTES (4*STAGE_BYTES) // 81920

template<int EPI, int OUT>
__global__ void __launch_bounds__(128, 2) tgemm(
    const __half* __restrict__ A, const __half* __restrict__ Bt,
    const float* __restrict__ R, void* __restrict__ Cv,
    int K, int N,
    const float2* __restrict__ rtab,
    __half* __restrict__ Qo, __half* __restrict__ Ko,
    __half* __restrict__ Vo)
{
    extern __shared__ char smc[];
    const uint32_t smb = smem_u32(smc);

    const int tid  = threadIdx.x;
    const int wid  = tid >> 5;
    const int lane = tid & 31;
    const int g    = lane >> 2;
    const int cc   = lane & 3;
    const int wm   = (wid & 1) * 64;
    const int wn   = (wid >> 1) * 64;

    const int m0 = blockIdx.y * 128;
    const int n0 = blockIdx.x * 128;

    const __half* Ab = A  + (size_t)m0 * K;
    const __half* Bb = Bt + (size_t)n0 * K;

    const int NC = K / 32;

    const uint32_t aoff = (uint32_t)(wm + (lane & 15)) * 80 + (lane >> 4) * 16;
    const uint32_t boff = (uint32_t)(wn + (lane & 7) + ((lane >> 4) * 8)) * 80
                        + ((lane >> 3) & 1) * 16;

#define LOAD_STAGE(chunk, st) do {                                         \
        const uint32_t asw = smb + (st)*STAGE_BYTES;                       \
        const uint32_t bsw = asw + TILE_BYTES;                             \
        const int kt = (chunk) * 32;                                       \
        _Pragma("unroll")                                                  \
        for (int j = 0; j < 4; j++) {                                      \
            const int f = tid + j * 128;                                   \
            const int row = f >> 2, c4 = f & 3;                            \
            CP_ASYNC16(asw + (uint32_t)(row*80 + c4*16),                   \
                       Ab + (size_t)row * K + kt + c4*8);                  \
            CP_ASYNC16(bsw + (uint32_t)(row*80 + c4*16),                   \
                       Bb + (size_t)row * K + kt + c4*8);                  \
        }                                                                  \
        CP_COMMIT();                                                       \
    } while (0)

    float acc[4][8][4];
#pragma unroll
    for (int mf = 0; mf < 4; mf++)
#pragma unroll
        for (int nf = 0; nf < 8; nf++)
#pragma unroll
            for (int q = 0; q < 4; q++) acc[mf][nf][q] = 0.f;

    LOAD_STAGE(0, 0);
    LOAD_STAGE(1, 1);
    LOAD_STAGE(2, 2);

    for (int i = 0; i < NC; i++) {
        if (i < NC - 2)       CP_WAIT2();
        else if (i == NC - 2) CP_WAIT1();
        else                  CP_WAIT0();
        __syncthreads();
        if (i + 3 < NC) LOAD_STAGE(i + 3, (i + 3) & 3);

        const uint32_t abase = smb + (i & 3) * STAGE_BYTES;
        const uint32_t bbase = abase + TILE_BYTES;

#pragma unroll
        for (int ks = 0; ks < 2; ks++) {
            uint32_t a[4][4], b[8][2];
#pragma unroll
            for (int mf = 0; mf < 4; mf++)
                LDSM_X4(a[mf][0], a[mf][1], a[mf][2], a[mf][3],
                        abase + aoff + mf*1280 + ks*32);
#pragma unroll
            for (int p = 0; p < 4; p++)
                LDSM_X4(b[2*p][0], b[2*p][1], b[2*p+1][0], b[2*p+1][1],
                        bbase + boff + p*1280 + ks*32);
#pragma unroll
            for (int mf = 0; mf < 4; mf++)
#pragma unroll
                for (int nf = 0; nf < 8; nf++)
                    MMA_F16(acc[mf][nf], a[mf], b[nf]);
        }
    }
#undef LOAD_STAGE

    if (OUT == 3) {
        // ---- fused rope + scatter epilogue ----
        // tile n0 covers exactly one part of one head: 384 = 3*128
        const int head = n0 / 384;
        const int part = (n0 - head*384) / 128;   // 0=q, 1=k, 2=v
        __half* sh = (__half*)smc;                // stage [128][132] halfs

        __syncthreads();   // mainloop smem fully consumed by all warps
#pragma unroll
        for (int mf = 0; mf < 4; mf++) {
#pragma unroll
            for (int nf = 0; nf < 8; nf++) {
                const int row = wm + mf * 16 + g;
                const int col = wn + nf * 8 + cc * 2;
                const __half2 h0 = __floats2half2_rn(acc[mf][nf][0], acc[mf][nf][1]);
                const __half2 h1 = __floats2half2_rn(acc[mf][nf][2], acc[mf][nf][3]);
                *(uint32_t*)&sh[row*132 + col]       = *(const uint32_t*)&h0;
                *(uint32_t*)&sh[(row + 8)*132 + col] = *(const uint32_t*)&h1;
            }
        }
        __syncthreads();

        __half* dst = (part == 0) ? Qo : (part == 1) ? Ko : Vo;
        const int rr = tid >> 6;         // 0..1
        const int dd = tid & 63;         // 0..63
#pragma unroll 4
        for (int i = 0; i < 64; i++) {
            const int r  = rr * 64 + i;
            const int bs = m0 + r;
            const int bI = bs >> 11, sI = bs & 2047;
            const size_t o = (((size_t)(bI*HH + head)) * SS + sI) * DHH;
            const float h0 = __half2float(sh[r*132 + dd]);
            const float h1 = __half2float(sh[r*132 + dd + 64]);
            if (part < 2) {
                const float2 t = rtab[(size_t)bs*64 + dd];
                dst[o + dd]      = __float2half_rn(h0*t.x - h1*t.y);
                dst[o + dd + 64] = __float2half_rn(h1*t.x + h0*t.y);
            } else {
                dst[o + dd]      = __float2half_rn(h0);
                dst[o + dd + 64] = __float2half_rn(h1);
            }
        }
        return;
    }

#pragma unroll
    for (int mf = 0; mf < 4; mf++) {
#pragma unroll
        for (int nf = 0; nf < 8; nf++) {
            const int row = m0 + wm + mf * 16 + g;
            const int col = n0 + wn + nf * 8 + cc * 2;
            float2 v0 = { acc[mf][nf][0], acc[mf][nf][1] };
            float2 v1 = { acc[mf][nf][2], acc[mf][nf][3] };
            if (OUT == 2) {
                __half* Gp = (__half*)Cv;
                const int gcol = col >> 1;
                const float s0 = v0.x / (1.0f + __expf(-v0.x)) * v0.y;
                const float s1 = v1.x / (1.0f + __expf(-v1.x)) * v1.y;
                Gp[(size_t)row * FFN + gcol]       = __float2half_rn(s0);
                Gp[(size_t)(row + 8) * FFN + gcol] = __float2half_rn(s1);
            } else {
                const size_t o0 = (size_t)row * N + col;
                const size_t o1 = (size_t)(row + 8) * N + col;
                if (EPI == 1) {
                    float2 r0 = *(const float2*)&R[o0];
                    float2 r1 = *(const float2*)&R[o1];
                    v0.x += r0.x; v0.y += r0.y;
                    v1.x += r1.x; v1.y += r1.y;
                }
                if (OUT == 1) {
                    __half* C = (__half*)Cv;
                    const __half2 h0 = __floats2half2_rn(v0.x, v0.y);
                    const __half2 h1 = __floats2half2_rn(v1.x, v1.y);
                    *(uint32_t*)&C[o0] = *(const uint32_t*)&h0;
                    *(uint32_t*)&C[o1] = *(const uint32_t*)&h1;
                } else {
                    float* C = (float*)Cv;
                    *(float2*)&C[o0] = v0;
                    *(float2*)&C[o1] = v1;
                }
            }
        }
    }
}

// ---------------------------------------------------------------------------
// LayerNorm: fp32 in, fp16 out
// ---------------------------------------------------------------------------
__global__ void __launch_bounds__(256) ln_kernel(
    const float* __restrict__ X, const float* __restrict__ g,
    const float* __restrict__ b, __half* __restrict__ Y)
{
    const int tid = threadIdx.x;
    const float* x = X + (size_t)blockIdx.x * DD;
    __half* y = Y + (size_t)blockIdx.x * DD;

    float v[8];
    *(float4*)&v[0] = *(const float4*)&x[tid*8];
    *(float4*)&v[4] = *(const float4*)&x[tid*8 + 4];

    float s = 0.f, sq = 0.f;
#pragma unroll
    for (int i = 0; i < 8; i++) { s += v[i]; sq += v[i]*v[i]; }
#pragma unroll
    for (int o = 16; o; o >>= 1) {
        s  += __shfl_xor_sync(0xffffffffu, s,  o);
        sq += __shfl_xor_sync(0xffffffffu, sq, o);
    }
    __shared__ float red[2][8];
    __shared__ float stats[2];
    const int w = tid >> 5, l = tid & 31;
    if (l == 0) { red[0][w] = s; red[1][w] = sq; }
    __syncthreads();
    if (tid == 0) {
        float S = 0.f, SQ = 0.f;
#pragma unroll
        for (int i = 0; i < 8; i++) { S += red[0][i]; SQ += red[1][i]; }
        const float mean = S * (1.0f/DD);
        const float var  = SQ * (1.0f/DD) - mean*mean;
        stats[0] = mean;
        stats[1] = rsqrtf(var + 1e-5f);
    }
    __syncthreads();
    const float mean = stats[0], rstd = stats[1];

    float gv[8], bv[8];
    *(float4*)&gv[0] = *(const float4*)&g[tid*8];
    *(float4*)&gv[4] = *(const float4*)&g[tid*8+4];
    *(float4*)&bv[0] = *(const float4*)&b[tid*8];
    *(float4*)&bv[4] = *(const float4*)&b[tid*8+4];

    __half2 h[4];
#pragma unroll
    for (int i = 0; i < 4; i++) {
        const float a0 = (v[2*i]   - mean) * rstd * gv[2*i]   + bv[2*i];
        const float a1 = (v[2*i+1] - mean) * rstd * gv[2*i+1] + bv[2*i+1];
        h[i] = __floats2half2_rn(a0, a1);
    }
    *(uint4*)&y[tid*8] = *(uint4*)h;
}

// ---------------------------------------------------------------------------
// Flash attention: fp16 mma + ldmatrix, cp.async double-buffered K/V tiles,
// V via ldmatrix.trans, Q frags in registers, P in registers, 1 sync/tile.
// ---------------------------------------------------------------------------
#define AT_SMEM_BYTES (26112*4)

__global__ void __launch_bounds__(256) attn_kernel(
    const __half* __restrict__ Q, const __half* __restrict__ K,
    const __half* __restrict__ V, const unsigned char* __restrict__ mask,
    __half* __restrict__ CTX)
{
    extern __shared__ uint32_t smu[];
    const uint32_t smb = smem_u32(smu);
    const uint32_t kB0 = smb + 8704*4;
    const uint32_t vB0 = smb + 17408*4;
#define KBUF(bf) (kB0 + (bf)*17408)
#define VBUF(bf) (vB0 + (bf)*17408)

    const int tid  = threadIdx.x;
    const int lane = tid & 31;
    const int wid  = tid >> 5;
    const int g    = lane >> 2;
    const int cc   = lane & 3;
    const int wm   = wid * 16;

    const int qt = blockIdx.x, h = blockIdx.y, b = blockIdx.z;
    const size_t headoff = ((size_t)(b*HH + h)) * SS * DHH;
    const __half* Qg    = Q + headoff + (size_t)qt * 128 * DHH;
    const __half* Kbase = K + headoff;
    const __half* Vbase = V + headoff;

#pragma unroll
    for (int j = 0; j < 8; j++) {
        const int f = tid + j * 256;
        const int r = f >> 4, c = f & 15;
        CP_ASYNC16(smb + (uint32_t)(r*272 + c*16), Qg + r*DHH + c*8);
    }
    CP_COMMIT();

#define LOAD_KV(t, bf) do {                                                \
        const __half* Kg_ = Kbase + (size_t)(t) * 64 * DHH;                \
        const __half* Vg_ = Vbase + (size_t)(t) * 64 * DHH;                \
        _Pragma("unroll")                                                  \
        for (int j = 0; j < 4; j++) {                                      \
            const int f = tid + j * 256;                                   \
            const int r = f >> 4, c = f & 15;                              \
            CP_ASYNC16(KBUF(bf) + (uint32_t)(r*272 + c*16),                \
                       Kg_ + r*DHH + c*8);                                 \
            CP_ASYNC16(VBUF(bf) + (uint32_t)(r*272 + c*16),                \
                       Vg_ + r*DHH + c*8);                                 \
        }                                                                  \
        CP_COMMIT();                                                       \
    } while (0)

    LOAD_KV(0, 0);
    LOAD_KV(1, 1);

    CP_WAIT1();
    __syncthreads();

    uint32_t qf[8][4];
    {
        const uint32_t qaddr = smb + (uint32_t)(wm + (lane & 15)) * 272
                             + (lane >> 4) * 16;
#pragma unroll
        for (int ks = 0; ks < 8; ks++)
            LDSM_X4(qf[ks][0], qf[ks][1], qf[ks][2], qf[ks][3], qaddr + ks*32);
    }

    const uint32_t kaddrL = (uint32_t)(lane & 7) * 272 + ((lane >> 3) & 1) * 16;
    const uint32_t vaddrL = (uint32_t)(lane & 15) * 272;

    float m0r = -1e30f, m1r = -1e30f, l0r = 0.f, l1r = 0.f;
    float O[16][4];
#pragma unroll
    for (int nf = 0; nf < 16; nf++)
#pragma unroll
        for (int q = 0; q < 4; q++) O[nf][q] = 0.f;

    const float scale = 0.08838834764831845f;
    const unsigned char* mrow = mask + (size_t)b * SS * SS;
    const int qg0 = qt * 128 + wm + g;
    const int qg8 = qg0 + 8;

    for (int t = 0; t < 32; t++) {
        const int bf = t & 1;
        const int kt = t * 64;

        unsigned short mRa[8], mRb[8];
        {
            const unsigned char* mpA = mrow + (size_t)qg0 * SS + kt + 2*cc;
            const unsigned char* mpB = mrow + (size_t)qg8 * SS + kt + 2*cc;
#pragma unroll
            for (int nf = 0; nf < 8; nf++) {
                mRa[nf] = *(const unsigned short*)(mpA + nf*8);
                mRb[nf] = *(const unsigned short*)(mpB + nf*8);
            }
        }

        float s[8][4];
#pragma unroll
        for (int nf = 0; nf < 8; nf++)
#pragma unroll
            for (int q = 0; q < 4; q++) s[nf][q] = 0.f;

        const uint32_t kb = KBUF(bf) + kaddrL;
#pragma unroll
        for (int ks = 0; ks < 8; ks++) {
            uint32_t bb[8][2];
#pragma unroll
            for (int nf = 0; nf < 8; nf++)
                LDSM_X2(bb[nf][0], bb[nf][1], kb + nf*2176 + ks*32);
#pragma unroll
            for (int nf = 0; nf < 8; nf++)
                MMA_F16(s[nf], qf[ks], bb[nf]);
        }

        float rmax0 = -1e30f, rmax1 = -1e30f;
#pragma unroll
        for (int nf = 0; nf < 8; nf++) {
            float s0 = s[nf][0]*scale, s1 = s[nf][1]*scale;
            float s2 = s[nf][2]*scale, s3 = s[nf][3]*scale;
            if (mRa[nf] & 0x00ffu) s0 = -10000.f;
            if (mRa[nf] & 0xff00u) s1 = -10000.f;
            if (mRb[nf] & 0x00ffu) s2 = -10000.f;
            if (mRb[nf] & 0xff00u) s3 = -10000.f;
            s[nf][0] = s0; s[nf][1] = s1; s[nf][2] = s2; s[nf][3] = s3;
            rmax0 = fmaxf(rmax0, fmaxf(s0, s1));
            rmax1 = fmaxf(rmax1, fmaxf(s2, s3));
        }
        rmax0 = fmaxf(rmax0, __shfl_xor_sync(0xffffffffu, rmax0, 1));
        rmax0 = fmaxf(rmax0, __shfl_xor_sync(0xffffffffu, rmax0, 2));
        rmax1 = fmaxf(rmax1, __shfl_xor_sync(0xffffffffu, rmax1, 1));
        rmax1 = fmaxf(rmax1, __shfl_xor_sync(0xffffffffu, rmax1, 2));

        const float mn0 = fmaxf(m0r, rmax0);
        const float mn1 = fmaxf(m1r, rmax1);
        const float cf0 = __expf(m0r - mn0);
        const float cf1 = __expf(m1r - mn1);
        m0r = mn0; m1r = mn1;

        uint32_t pfrag[8][2];
        float ls0 = 0.f, ls1 = 0.f;
#pragma unroll
        for (int nf = 0; nf < 8; nf++) {
            const float p0 = __expf(s[nf][0] - mn0);
            const float p1 = __expf(s[nf][1] - mn0);
            const float p2 = __expf(s[nf][2] - mn1);
            const float p3 = __expf(s[nf][3] - mn1);
            ls0 += p0 + p1; ls1 += p2 + p3;
            const __half2 h01 = __floats2half2_rn(p0, p1);
            const __half2 h23 = __floats2half2_rn(p2, p3);
            pfrag[nf][0] = *(const uint32_t*)&h01;
            pfrag[nf][1] = *(const uint32_t*)&h23;
        }
        ls0 += __shfl_xor_sync(0xffffffffu, ls0, 1);
        ls0 += __shfl_xor_sync(0xffffffffu, ls0, 2);
        ls1 += __shfl_xor_sync(0xffffffffu, ls1, 1);
        ls1 += __shfl_xor_sync(0xffffffffu, ls1, 2);
        l0r = l0r * cf0 + ls0;
        l1r = l1r * cf1 + ls1;

#pragma unroll
        for (int nf = 0; nf < 16; nf++) {
            O[nf][0] *= cf0; O[nf][1] *= cf0;
            O[nf][2] *= cf1; O[nf][3] *= cf1;
        }

        const uint32_t vb = VBUF(bf) + vaddrL;
#pragma unroll
        for (int ks = 0; ks < 4; ks++) {
            uint32_t a[4] = { pfrag[2*ks][0],   pfrag[2*ks][1],
                              pfrag[2*ks+1][0], pfrag[2*ks+1][1] };
            uint32_t bb[16][2];
#pragma unroll
            for (int nf = 0; nf < 16; nf++)
                LDSM_X2T(bb[nf][0], bb[nf][1], vb + ks*4352 + nf*16);
#pragma unroll
            for (int nf = 0; nf < 16; nf++)
                MMA_F16(O[nf], a, bb[nf]);
        }
        __syncthreads();

        if (t + 2 < 32) LOAD_KV(t + 2, bf);
        CP_WAIT1();
    }
#undef LOAD_KV

    const float inv0 = 1.0f / l0r;
    const float inv1 = 1.0f / l1r;
    __half* C0 = CTX + ((size_t)(b*SS + qg0)) * DD + h*DHH;
    __half* C1 = CTX + ((size_t)(b*SS + qg8)) * DD + h*DHH;
#pragma unroll
    for (int nf = 0; nf < 16; nf++) {
        const int c2 = nf*8 + 2*cc;
        const __half2 h0 = __floats2half2_rn(O[nf][0]*inv0, O[nf][1]*inv0);
        const __half2 h1 = __floats2half2_rn(O[nf][2]*inv1, O[nf][3]*inv1);
        *(uint32_t*)(C0 + c2) = *(const uint32_t*)&h0;
        *(uint32_t*)(C1 + c2) = *(const uint32_t*)&h1;
    }
}

// ---------------------------------------------------------------------------
// Launch
// ---------------------------------------------------------------------------
extern "C" void kernel_launch(void* const* d_in, const int* in_sizes, int n_in,
                              void* d_out, int out_size)
{
    const float*         hidden  = (const float*)d_in[0];
    const unsigned char* mask    = (const unsigned char*)d_in[1];
    const int*           pos     = (const int*)d_in[2];
    const float*         ln1_g   = (const float*)d_in[3];
    const float*         ln1_b   = (const float*)d_in[4];
    const float*         Wqkv    = (const float*)d_in[5];
    const float*         Wo      = (const float*)d_in[6];
    const float*         ln2_g   = (const float*)d_in[7];
    const float*         ln2_b   = (const float*)d_in[8];
    const float*         Wfc_in  = (const float*)d_in[9];
    const float*         Wfc_out = (const float*)d_in[10];
    float*               out     = (float*)d_out;

    __half *X, *Q, *K, *V, *CTX, *X2, *G;
    __half *WqkvT, *WoT, *WfciT, *WfcoT;
    float *H1;
    float2 *RTAB;
    cudaGetSymbolAddress((void**)&X,     g_X);
    cudaGetSymbolAddress((void**)&Q,     g_Q);
    cudaGetSymbolAddress((void**)&K,     g_K);
    cudaGetSymbolAddress((void**)&V,     g_V);
    cudaGetSymbolAddress((void**)&CTX,   g_CTX);
    cudaGetSymbolAddress((void**)&H1,    g_H1);
    cudaGetSymbolAddress((void**)&X2,    g_X2);
    cudaGetSymbolAddress((void**)&G,     g_G);
    cudaGetSymbolAddress((void**)&RTAB,  g_rtab);
    cudaGetSymbolAddress((void**)&WqkvT, g_WqkvT);
    cudaGetSymbolAddress((void**)&WoT,   g_WoT);
    cudaGetSymbolAddress((void**)&WfciT, g_WfciT);
    cudaGetSymbolAddress((void**)&WfcoT, g_WfcoT);

    cudaFuncSetAttribute(attn_kernel,
                         cudaFuncAttributeMaxDynamicSharedMemorySize,
                         AT_SMEM_BYTES);
    cudaFuncSetAttribute((tgemm<0,1>),
                         cudaFuncAttributeMaxDynamicSharedMemorySize,
                         GM_SMEM_BYTES);
    cudaFuncSetAttribute((tgemm<1,0>),
                         cudaFuncAttributeMaxDynamicSharedMemorySize,
                         GM_SMEM_BYTES);
    cudaFuncSetAttribute((tgemm<0,2>),
                         cudaFuncAttributeMaxDynamicSharedMemorySize,
                         GM_SMEM_BYTES);
    cudaFuncSetAttribute((tgemm<0,3>),
                         cudaFuncAttributeMaxDynamicSharedMemorySize,
                         GM_SMEM_BYTES);

    // 0) weight transposes + rope table
    transpose_h<<<dim3(NQKV/32, DD/32),  dim3(32,8)>>>(Wqkv,    WqkvT, DD,  NQKV);
    transpose_h<<<dim3(DD/32,   DD/32),  dim3(32,8)>>>(Wo,      WoT,   DD,  DD);
    transpose_h<<<dim3(DD/32,   FFN/32), dim3(32,8)>>>(Wfc_out, WfcoT, FFN, DD);
    transpose_h_pair2<<<dim3(FFN/32, DD/32), dim3(32,8)>>>(Wfc_in, WfciT);
    rtab_kernel<<<ROWS, 64>>>(pos, RTAB);

    // 1) LN1 (fp16 out)
    ln_kernel<<<ROWS, 256>>>(hidden, ln1_g, ln1_b, X);
    // 2) QKV projection + fused rope + scatter to Q/K/V
    tgemm<0,3><<<dim3(NQKV/128, ROWS/128), 128, GM_SMEM_BYTES>>>(
        X, WqkvT, nullptr, nullptr, DD, NQKV, RTAB, Q, K, V);
    // 3) attention -> ctx (fp16)
    attn_kernel<<<dim3(SS/128, HH, BB), 256, AT_SMEM_BYTES>>>(Q, K, V, mask, CTX);
    // 4) Wo projection + residual (f32 out)
    tgemm<1,0><<<dim3(DD/128, ROWS/128), 128, GM_SMEM_BYTES>>>(
        CTX, WoT, hidden, H1, DD, DD, nullptr, nullptr, nullptr, nullptr);
    // 5) LN2 (fp16 out)
    ln_kernel<<<ROWS, 256>>>(H1, ln2_g, ln2_b, X2);
    // 6) fc_in + fused SwiGLU (fp16 G out)
    tgemm<0,2><<<dim3(NFC/128, ROWS/128), 128, GM_SMEM_BYTES>>>(
        X2, WfciT, nullptr, G, DD, NFC, nullptr, nullptr, nullptr, nullptr);
    // 7) fc_out + residual (final output, f32)
    tgemm<1,0><<<dim3(DD/128, ROWS/128), 128, GM_SMEM_BYTES>>>(
        G, WfcoT, H1, out, FFN, DD, nullptr, nullptr, nullptr, nullptr);
}

// round 13
// speedup vs baseline: 1.2741x; 1.0026x over previous
#include <cuda_runtime.h>
#include <cuda_fp16.h>
#include <math.h>
#include <stdint.h>

// ---------------------------------------------------------------------------
// Problem constants
// ---------------------------------------------------------------------------
#define BB   2
#define SS   2048
#define DD   2048
#define HH   16
#define DHH  128
#define FFN  5632
#define ROWS (BB*SS)           // 4096
#define NQKV (3*HH*DHH)        // 6144
#define NFC  (2*FFN)           // 11264

// ---------------------------------------------------------------------------
// Scratch
// ---------------------------------------------------------------------------
__device__ __half g_X  [ROWS*DD];    // LN1 out
__device__ __half g_Q  [ROWS*DD];    // [B,H,S,DH]
__device__ __half g_K  [ROWS*DD];
__device__ __half g_V  [ROWS*DD];    // [B,H,S,DH]
__device__ __half g_CTX[ROWS*DD];    // [B,S,H*DH]
__device__ float  g_H1 [ROWS*DD];    // residual 1 (fp32)
__device__ __half g_X2 [ROWS*DD];    // LN2 out
__device__ __half g_G  [ROWS*FFN];   // swiglu out (written by fused fc_in)
__device__ float2 g_rtab[ROWS*64];   // rope (cos, sin) table per (row, freq)
// transposed weights [N,K] K-major, fp16
__device__ __half g_WqkvT [NQKV*DD];
__device__ __half g_WoT   [DD*DD];
__device__ __half g_WfciT [NFC*DD];  // interleaved: row 2j = a_j, 2j+1 = b_j
__device__ __half g_WfcoT [DD*FFN];

// ---------------------------------------------------------------------------
// Helpers
// ---------------------------------------------------------------------------
__device__ __forceinline__ uint32_t smem_u32(const void* p) {
    uint32_t a;
    asm("{ .reg .u64 t; cvta.to.shared.u64 t, %1; cvt.u32.u64 %0, t; }"
        : "=r"(a) : "l"(p));
    return a;
}

#define CP_ASYNC16(dst, src) \
    asm volatile("cp.async.cg.shared.global [%0], [%1], 16;" \
                 :: "r"(dst), "l"(src))
#define CP_COMMIT() asm volatile("cp.async.commit_group;" ::: "memory")
#define CP_WAIT2()  asm volatile("cp.async.wait_group 2;" ::: "memory")
#define CP_WAIT1()  asm volatile("cp.async.wait_group 1;" ::: "memory")
#define CP_WAIT0()  asm volatile("cp.async.wait_group 0;" ::: "memory")

#define MMA_F16(d, a, b)                                                   \
    asm volatile(                                                          \
        "mma.sync.aligned.m16n8k16.row.col.f32.f16.f16.f32 "               \
        "{%0,%1,%2,%3}, {%4,%5,%6,%7}, {%8,%9}, {%0,%1,%2,%3};"            \
        : "+f"((d)[0]), "+f"((d)[1]), "+f"((d)[2]), "+f"((d)[3])           \
        : "r"((a)[0]), "r"((a)[1]), "r"((a)[2]), "r"((a)[3]),              \
          "r"((b)[0]), "r"((b)[1]))

#define LDSM_X4(r0, r1, r2, r3, addr)                                      \
    asm volatile("ldmatrix.sync.aligned.m8n8.x4.shared.b16 "               \
                 "{%0,%1,%2,%3}, [%4];"                                    \
                 : "=r"(r0), "=r"(r1), "=r"(r2), "=r"(r3) : "r"(addr))

#define LDSM_X2(r0, r1, addr)                                              \
    asm volatile("ldmatrix.sync.aligned.m8n8.x2.shared.b16 "               \
                 "{%0,%1}, [%2];"                                          \
                 : "=r"(r0), "=r"(r1) : "r"(addr))

#define LDSM_X2T(r0, r1, addr)                                             \
    asm volatile("ldmatrix.sync.aligned.m8n8.x2.trans.shared.b16 "         \
                 "{%0,%1}, [%2];"                                          \
                 : "=r"(r0), "=r"(r1) : "r"(addr))

// ---------------------------------------------------------------------------
// Weight transpose + fp16 round: W[K,N] f32 -> Wt[N,K] f16
// ---------------------------------------------------------------------------
__global__ void __launch_bounds__(256) transpose_h(
    const float* __restrict__ W, __half* __restrict__ Wt, int K, int N)
{
    __shared__ float t[32][33];
    const int tx = threadIdx.x, ty = threadIdx.y;
    const int n0 = blockIdx.x * 32, k0 = blockIdx.y * 32;
#pragma unroll
    for (int j = 0; j < 4; j++)
        t[ty + j*8][tx] = W[(size_t)(k0 + ty + j*8) * N + n0 + tx];
    __syncthreads();
#pragma unroll
    for (int j = 0; j < 4; j++)
        Wt[(size_t)(n0 + ty + j*8) * K + k0 + tx] = __float2half_rn(t[tx][ty + j*8]);
}

// Merged paired transpose for fc_in: a-col j -> row 2j, b-col j -> row 2j+1.
__global__ void __launch_bounds__(256) transpose_h_pair2(
    const float* __restrict__ W, __half* __restrict__ Wt)
{
    __shared__ float ta[32][33];
    __shared__ float tb[32][33];
    const int tx = threadIdx.x, ty = threadIdx.y;
    const int n0 = blockIdx.x * 32, k0 = blockIdx.y * 32;
#pragma unroll
    for (int j = 0; j < 4; j++) {
        const size_t rbase = (size_t)(k0 + ty + j*8) * NFC;
        ta[ty + j*8][tx] = W[rbase + n0 + tx];
        tb[ty + j*8][tx] = W[rbase + FFN + n0 + tx];
    }
    __syncthreads();
#pragma unroll
    for (int j = 0; j < 4; j++) {
        const int n = n0 + ty + j*8;
        Wt[(size_t)(2*n)     * DD + k0 + tx] = __float2half_rn(ta[tx][ty + j*8]);
        Wt[(size_t)(2*n + 1) * DD + k0 + tx] = __float2half_rn(tb[tx][ty + j*8]);
    }
}

// ---------------------------------------------------------------------------
// Rope sin/cos table: tab[row][j] = (cos, sin) of pos_ids[row] * inv_freq(j)
// ---------------------------------------------------------------------------
__global__ void __launch_bounds__(64) rtab_kernel(
    const int* __restrict__ pos_ids, float2* __restrict__ tab)
{
    const int r = blockIdx.x;
    const int j = threadIdx.x;
    const float pos = (float)pos_ids[r];
    const float inv = 1.0f / powf(10000.0f, (float)(2*j) * (1.0f/128.0f));
    float sn, cs;
    sincosf(pos * inv, &sn, &cs);
    tab[r*64 + j] = make_float2(cs, sn);
}

// ---------------------------------------------------------------------------
// FP16 mma.sync GEMM, ldmatrix fragments, 4-stage cp.async pipeline.
// CTA tile 128x128x32, 4 warps (2M x 2N), warp tile 64x64.  (champion)
// OUT: 0 = f32 (+residual if EPI), 1 = f16,
//      2 = f16 fused swiglu (paired cols),
//      3 = fused rope+scatter to Q/K/V (each tile = one {q,k,v} of one head)
// ---------------------------------------------------------------------------
#define TILE_BYTES 10240              // 128 rows * 80 B
#define STAGE_BYTES (2*TILE_BYTES)
#define GM_SMEM_BYTES (4*STAGE_BYTES) // 81920

template<int EPI, int OUT>
__global__ void __launch_bounds__(128, 2) tgemm(
    const __half* __restrict__ A, const __half* __restrict__ Bt,
    const float* __restrict__ R, void* __restrict__ Cv,
    int K, int N,
    const float2* __restrict__ rtab,
    __half* __restrict__ Qo, __half* __restrict__ Ko,
    __half* __restrict__ Vo)
{
    extern __shared__ char smc[];
    const uint32_t smb = smem_u32(smc);

    const int tid  = threadIdx.x;
    const int wid  = tid >> 5;
    const int lane = tid & 31;
    const int g    = lane >> 2;
    const int cc   = lane & 3;
    const int wm   = (wid & 1) * 64;
    const int wn   = (wid >> 1) * 64;

    const int m0 = blockIdx.y * 128;
    const int n0 = blockIdx.x * 128;

    const __half* Ab = A  + (size_t)m0 * K;
    const __half* Bb = Bt + (size_t)n0 * K;

    const int NC = K / 32;

    const uint32_t aoff = (uint32_t)(wm + (lane & 15)) * 80 + (lane >> 4) * 16;
    const uint32_t boff = (uint32_t)(wn + (lane & 7) + ((lane >> 4) * 8)) * 80
                        + ((lane >> 3) & 1) * 16;

#define LOAD_STAGE(chunk, st) do {                                         \
        const uint32_t asw = smb + (st)*STAGE_BYTES;                       \
        const uint32_t bsw = asw + TILE_BYTES;                             \
        const int kt = (chunk) * 32;                                       \
        _Pragma("unroll")                                                  \
        for (int j = 0; j < 4; j++) {                                      \
            const int f = tid + j * 128;                                   \
            const int row = f >> 2, c4 = f & 3;                            \
            CP_ASYNC16(asw + (uint32_t)(row*80 + c4*16),                   \
                       Ab + (size_t)row * K + kt + c4*8);                  \
            CP_ASYNC16(bsw + (uint32_t)(row*80 + c4*16),                   \
                       Bb + (size_t)row * K + kt + c4*8);                  \
        }                                                                  \
        CP_COMMIT();                                                       \
    } while (0)

    float acc[4][8][4];
#pragma unroll
    for (int mf = 0; mf < 4; mf++)
#pragma unroll
        for (int nf = 0; nf < 8; nf++)
#pragma unroll
            for (int q = 0; q < 4; q++) acc[mf][nf][q] = 0.f;

    LOAD_STAGE(0, 0);
    LOAD_STAGE(1, 1);
    LOAD_STAGE(2, 2);

    for (int i = 0; i < NC; i++) {
        if (i < NC - 2)       CP_WAIT2();
        else if (i == NC - 2) CP_WAIT1();
        else                  CP_WAIT0();
        __syncthreads();
        if (i + 3 < NC) LOAD_STAGE(i + 3, (i + 3) & 3);

        const uint32_t abase = smb + (i & 3) * STAGE_BYTES;
        const uint32_t bbase = abase + TILE_BYTES;

#pragma unroll
        for (int ks = 0; ks < 2; ks++) {
            uint32_t a[4][4], b[8][2];
#pragma unroll
            for (int mf = 0; mf < 4; mf++)
                LDSM_X4(a[mf][0], a[mf][1], a[mf][2], a[mf][3],
                        abase + aoff + mf*1280 + ks*32);
#pragma unroll
            for (int p = 0; p < 4; p++)
                LDSM_X4(b[2*p][0], b[2*p][1], b[2*p+1][0], b[2*p+1][1],
                        bbase + boff + p*1280 + ks*32);
#pragma unroll
            for (int mf = 0; mf < 4; mf++)
#pragma unroll
                for (int nf = 0; nf < 8; nf++)
                    MMA_F16(acc[mf][nf], a[mf], b[nf]);
        }
    }
#undef LOAD_STAGE

    if (OUT == 3) {
        // ---- fused rope + scatter epilogue ----
        // tile n0 covers exactly one part of one head: 384 = 3*128
        const int head = n0 / 384;
        const int part = (n0 - head*384) / 128;   // 0=q, 1=k, 2=v
        __half* sh = (__half*)smc;                // stage [128][132] halfs

        __syncthreads();   // mainloop smem fully consumed by all warps
#pragma unroll
        for (int mf = 0; mf < 4; mf++) {
#pragma unroll
            for (int nf = 0; nf < 8; nf++) {
                const int row = wm + mf * 16 + g;
                const int col = wn + nf * 8 + cc * 2;
                const __half2 h0 = __floats2half2_rn(acc[mf][nf][0], acc[mf][nf][1]);
                const __half2 h1 = __floats2half2_rn(acc[mf][nf][2], acc[mf][nf][3]);
                *(uint32_t*)&sh[row*132 + col]       = *(const uint32_t*)&h0;
                *(uint32_t*)&sh[(row + 8)*132 + col] = *(const uint32_t*)&h1;
            }
        }
        __syncthreads();

        __half* dst = (part == 0) ? Qo : (part == 1) ? Ko : Vo;
        const int rr = tid >> 6;         // 0..1
        const int dd = tid & 63;         // 0..63
#pragma unroll 4
        for (int i = 0; i < 64; i++) {
            const int r  = rr * 64 + i;
            const int bs = m0 + r;
            const int bI = bs >> 11, sI = bs & 2047;
            const size_t o = (((size_t)(bI*HH + head)) * SS + sI) * DHH;
            const float h0 = __half2float(sh[r*132 + dd]);
            const float h1 = __half2float(sh[r*132 + dd + 64]);
            if (part < 2) {
                const float2 t = rtab[(size_t)bs*64 + dd];
                dst[o + dd]      = __float2half_rn(h0*t.x - h1*t.y);
                dst[o + dd + 64] = __float2half_rn(h1*t.x + h0*t.y);
            } else {
                dst[o + dd]      = __float2half_rn(h0);
                dst[o + dd + 64] = __float2half_rn(h1);
            }
        }
        return;
    }

#pragma unroll
    for (int mf = 0; mf < 4; mf++) {
#pragma unroll
        for (int nf = 0; nf < 8; nf++) {
            const int row = m0 + wm + mf * 16 + g;
            const int col = n0 + wn + nf * 8 + cc * 2;
            float2 v0 = { acc[mf][nf][0], acc[mf][nf][1] };
            float2 v1 = { acc[mf][nf][2], acc[mf][nf][3] };
            if (OUT == 2) {
                __half* Gp = (__half*)Cv;
                const int gcol = col >> 1;
                const float s0 = v0.x / (1.0f + __expf(-v0.x)) * v0.y;
                const float s1 = v1.x / (1.0f + __expf(-v1.x)) * v1.y;
                Gp[(size_t)row * FFN + gcol]       = __float2half_rn(s0);
                Gp[(size_t)(row + 8) * FFN + gcol] = __float2half_rn(s1);
            } else {
                const size_t o0 = (size_t)row * N + col;
                const size_t o1 = (size_t)(row + 8) * N + col;
                if (EPI == 1) {
                    float2 r0 = *(const float2*)&R[o0];
                    float2 r1 = *(const float2*)&R[o1];
                    v0.x += r0.x; v0.y += r0.y;
                    v1.x += r1.x; v1.y += r1.y;
                }
                if (OUT == 1) {
                    __half* C = (__half*)Cv;
                    const __half2 h0 = __floats2half2_rn(v0.x, v0.y);
                    const __half2 h1 = __floats2half2_rn(v1.x, v1.y);
                    *(uint32_t*)&C[o0] = *(const uint32_t*)&h0;
                    *(uint32_t*)&C[o1] = *(const uint32_t*)&h1;
                } else {
                    float* C = (float*)Cv;
                    *(float2*)&C[o0] = v0;
                    *(float2*)&C[o1] = v1;
                }
            }
        }
    }
}

// ---------------------------------------------------------------------------
// LayerNorm: fp32 in, fp16 out
// ---------------------------------------------------------------------------
__global__ void __launch_bounds__(256) ln_kernel(
    const float* __restrict__ X, const float* __restrict__ g,
    const float* __restrict__ b, __half* __restrict__ Y)
{
    const int tid = threadIdx.x;
    const float* x = X + (size_t)blockIdx.x * DD;
    __half* y = Y + (size_t)blockIdx.x * DD;

    float v[8];
    *(float4*)&v[0] = *(const float4*)&x[tid*8];
    *(float4*)&v[4] = *(const float4*)&x[tid*8 + 4];

    float s = 0.f, sq = 0.f;
#pragma unroll
    for (int i = 0; i < 8; i++) { s += v[i]; sq += v[i]*v[i]; }
#pragma unroll
    for (int o = 16; o; o >>= 1) {
        s  += __shfl_xor_sync(0xffffffffu, s,  o);
        sq += __shfl_xor_sync(0xffffffffu, sq, o);
    }
    __shared__ float red[2][8];
    __shared__ float stats[2];
    const int w = tid >> 5, l = tid & 31;
    if (l == 0) { red[0][w] = s; red[1][w] = sq; }
    __syncthreads();
    if (tid == 0) {
        float S = 0.f, SQ = 0.f;
#pragma unroll
        for (int i = 0; i < 8; i++) { S += red[0][i]; SQ += red[1][i]; }
        const float mean = S * (1.0f/DD);
        const float var  = SQ * (1.0f/DD) - mean*mean;
        stats[0] = mean;
        stats[1] = rsqrtf(var + 1e-5f);
    }
    __syncthreads();
    const float mean = stats[0], rstd = stats[1];

    float gv[8], bv[8];
    *(float4*)&gv[0] = *(const float4*)&g[tid*8];
    *(float4*)&gv[4] = *(const float4*)&g[tid*8+4];
    *(float4*)&bv[0] = *(const float4*)&b[tid*8];
    *(float4*)&bv[4] = *(const float4*)&b[tid*8+4];

    __half2 h[4];
#pragma unroll
    for (int i = 0; i < 4; i++) {
        const float a0 = (v[2*i]   - mean) * rstd * gv[2*i]   + bv[2*i];
        const float a1 = (v[2*i+1] - mean) * rstd * gv[2*i+1] + bv[2*i+1];
        h[i] = __floats2half2_rn(a0, a1);
    }
    *(uint4*)&y[tid*8] = *(uint4*)h;
}

// ---------------------------------------------------------------------------
// Flash attention: fp16 mma + ldmatrix, cp.async double-buffered K/V tiles,
// V via ldmatrix.trans, Q frags in registers, P in registers, 1 sync/tile.
// ---------------------------------------------------------------------------
#define AT_SMEM_BYTES (26112*4)

__global__ void __launch_bounds__(256) attn_kernel(
    const __half* __restrict__ Q, const __half* __restrict__ K,
    const __half* __restrict__ V, const unsigned char* __restrict__ mask,
    __half* __restrict__ CTX)
{
    extern __shared__ uint32_t smu[];
    const uint32_t smb = smem_u32(smu);
    const uint32_t kB0 = smb + 8704*4;
    const uint32_t vB0 = smb + 17408*4;
#define KBUF(bf) (kB0 + (bf)*17408)
#define VBUF(bf) (vB0 + (bf)*17408)

    const int tid  = threadIdx.x;
    const int lane = tid & 31;
    const int wid  = tid >> 5;
    const int g    = lane >> 2;
    const int cc   = lane & 3;
    const int wm   = wid * 16;

    const int qt = blockIdx.x, h = blockIdx.y, b = blockIdx.z;
    const size_t headoff = ((size_t)(b*HH + h)) * SS * DHH;
    const __half* Qg    = Q + headoff + (size_t)qt * 128 * DHH;
    const __half* Kbase = K + headoff;
    const __half* Vbase = V + headoff;

#pragma unroll
    for (int j = 0; j < 8; j++) {
        const int f = tid + j * 256;
        const int r = f >> 4, c = f & 15;
        CP_ASYNC16(smb + (uint32_t)(r*272 + c*16), Qg + r*DHH + c*8);
    }
    CP_COMMIT();

#define LOAD_KV(t, bf) do {                                                \
        const __half* Kg_ = Kbase + (size_t)(t) * 64 * DHH;                \
        const __half* Vg_ = Vbase + (size_t)(t) * 64 * DHH;                \
        _Pragma("unroll")                                                  \
        for (int j = 0; j < 4; j++) {                                      \
            const int f = tid + j * 256;                                   \
            const int r = f >> 4, c = f & 15;                              \
            CP_ASYNC16(KBUF(bf) + (uint32_t)(r*272 + c*16),                \
                       Kg_ + r*DHH + c*8);                                 \
            CP_ASYNC16(VBUF(bf) + (uint32_t)(r*272 + c*16),                \
                       Vg_ + r*DHH + c*8);                                 \
        }                                                                  \
        CP_COMMIT();                                                       \
    } while (0)

    LOAD_KV(0, 0);
    LOAD_KV(1, 1);

    CP_WAIT1();
    __syncthreads();

    uint32_t qf[8][4];
    {
        const uint32_t qaddr = smb + (uint32_t)(wm + (lane & 15)) * 272
                             + (lane >> 4) * 16;
#pragma unroll
        for (int ks = 0; ks < 8; ks++)
            LDSM_X4(qf[ks][0], qf[ks][1], qf[ks][2], qf[ks][3], qaddr + ks*32);
    }

    const uint32_t kaddrL = (uint32_t)(lane & 7) * 272 + ((lane >> 3) & 1) * 16;
    const uint32_t vaddrL = (uint32_t)(lane & 15) * 272;

    float m0r = -1e30f, m1r = -1e30f, l0r = 0.f, l1r = 0.f;
    float O[16][4];
#pragma unroll
    for (int nf = 0; nf < 16; nf++)
#pragma unroll
        for (int q = 0; q < 4; q++) O[nf][q] = 0.f;

    const float scale = 0.08838834764831845f;
    const unsigned char* mrow = mask + (size_t)b * SS * SS;
    const int qg0 = qt * 128 + wm + g;
    const int qg8 = qg0 + 8;

    for (int t = 0; t < 32; t++) {
        const int bf = t & 1;
        const int kt = t * 64;

        unsigned short mRa[8], mRb[8];
        {
            const unsigned char* mpA = mrow + (size_t)qg0 * SS + kt + 2*cc;
            const unsigned char* mpB = mrow + (size_t)qg8 * SS + kt + 2*cc;
#pragma unroll
            for (int nf = 0; nf < 8; nf++) {
                mRa[nf] = *(const unsigned short*)(mpA + nf*8);
                mRb[nf] = *(const unsigned short*)(mpB + nf*8);
            }
        }

        float s[8][4];
#pragma unroll
        for (int nf = 0; nf < 8; nf++)
#pragma unroll
            for (int q = 0; q < 4; q++) s[nf][q] = 0.f;

        const uint32_t kb = KBUF(bf) + kaddrL;
#pragma unroll
        for (int ks = 0; ks < 8; ks++) {
            uint32_t bb[8][2];
#pragma unroll
            for (int nf = 0; nf < 8; nf++)
                LDSM_X2(bb[nf][0], bb[nf][1], kb + nf*2176 + ks*32);
#pragma unroll
            for (int nf = 0; nf < 8; nf++)
                MMA_F16(s[nf], qf[ks], bb[nf]);
        }

        float rmax0 = -1e30f, rmax1 = -1e30f;
#pragma unroll
        for (int nf = 0; nf < 8; nf++) {
            float s0 = s[nf][0]*scale, s1 = s[nf][1]*scale;
            float s2 = s[nf][2]*scale, s3 = s[nf][3]*scale;
            if (mRa[nf] & 0x00ffu) s0 = -10000.f;
            if (mRa[nf] & 0xff00u) s1 = -10000.f;
            if (mRb[nf] & 0x00ffu) s2 = -10000.f;
            if (mRb[nf] & 0xff00u) s3 = -10000.f;
            s[nf][0] = s0; s[nf][1] = s1; s[nf][2] = s2; s[nf][3] = s3;
            rmax0 = fmaxf(rmax0, fmaxf(s0, s1));
            rmax1 = fmaxf(rmax1, fmaxf(s2, s3));
        }
        rmax0 = fmaxf(rmax0, __shfl_xor_sync(0xffffffffu, rmax0, 1));
        rmax0 = fmaxf(rmax0, __shfl_xor_sync(0xffffffffu, rmax0, 2));
        rmax1 = fmaxf(rmax1, __shfl_xor_sync(0xffffffffu, rmax1, 1));
        rmax1 = fmaxf(rmax1, __shfl_xor_sync(0xffffffffu, rmax1, 2));

        const float mn0 = fmaxf(m0r, rmax0);
        const float mn1 = fmaxf(m1r, rmax1);
        const float cf0 = __expf(m0r - mn0);
        const float cf1 = __expf(m1r - mn1);
        m0r = mn0; m1r = mn1;

        uint32_t pfrag[8][2];
        float ls0 = 0.f, ls1 = 0.f;
#pragma unroll
        for (int nf = 0; nf < 8; nf++) {
            const float p0 = __expf(s[nf][0] - mn0);
            const float p1 = __expf(s[nf][1] - mn0);
            const float p2 = __expf(s[nf][2] - mn1);
            const float p3 = __expf(s[nf][3] - mn1);
            ls0 += p0 + p1; ls1 += p2 + p3;
            const __half2 h01 = __floats2half2_rn(p0, p1);
            const __half2 h23 = __floats2half2_rn(p2, p3);
            pfrag[nf][0] = *(const uint32_t*)&h01;
            pfrag[nf][1] = *(const uint32_t*)&h23;
        }
        ls0 += __shfl_xor_sync(0xffffffffu, ls0, 1);
        ls0 += __shfl_xor_sync(0xffffffffu, ls0, 2);
        ls1 += __shfl_xor_sync(0xffffffffu, ls1, 1);
        ls1 += __shfl_xor_sync(0xffffffffu, ls1, 2);
        l0r = l0r * cf0 + ls0;
        l1r = l1r * cf1 + ls1;

#pragma unroll
        for (int nf = 0; nf < 16; nf++) {
            O[nf][0] *= cf0; O[nf][1] *= cf0;
            O[nf][2] *= cf1; O[nf][3] *= cf1;
        }

        const uint32_t vb = VBUF(bf) + vaddrL;
#pragma unroll
        for (int ks = 0; ks < 4; ks++) {
            uint32_t a[4] = { pfrag[2*ks][0],   pfrag[2*ks][1],
                              pfrag[2*ks+1][0], pfrag[2*ks+1][1] };
            uint32_t bb[16][2];
#pragma unroll
            for (int nf = 0; nf < 16; nf++)
                LDSM_X2T(bb[nf][0], bb[nf][1], vb + ks*4352 + nf*16);
#pragma unroll
            for (int nf = 0; nf < 16; nf++)
                MMA_F16(O[nf], a, bb[nf]);
        }
        __syncthreads();

        if (t + 2 < 32) LOAD_KV(t + 2, bf);
        CP_WAIT1();
    }
#undef LOAD_KV

    const float inv0 = 1.0f / l0r;
    const float inv1 = 1.0f / l1r;
    __half* C0 = CTX + ((size_t)(b*SS + qg0)) * DD + h*DHH;
    __half* C1 = CTX + ((size_t)(b*SS + qg8)) * DD + h*DHH;
#pragma unroll
    for (int nf = 0; nf < 16; nf++) {
        const int c2 = nf*8 + 2*cc;
        const __half2 h0 = __floats2half2_rn(O[nf][0]*inv0, O[nf][1]*inv0);
        const __half2 h1 = __floats2half2_rn(O[nf][2]*inv1, O[nf][3]*inv1);
        *(uint32_t*)(C0 + c2) = *(const uint32_t*)&h0;
        *(uint32_t*)(C1 + c2) = *(const uint32_t*)&h1;
    }
}

// ---------------------------------------------------------------------------
// Launch
// ---------------------------------------------------------------------------
extern "C" void kernel_launch(void* const* d_in, const int* in_sizes, int n_in,
                              void* d_out, int out_size)
{
    const float*         hidden  = (const float*)d_in[0];
    const unsigned char* mask    = (const unsigned char*)d_in[1];
    const int*           pos     = (const int*)d_in[2];
    const float*         ln1_g   = (const float*)d_in[3];
    const float*         ln1_b   = (const float*)d_in[4];
    const float*         Wqkv    = (const float*)d_in[5];
    const float*         Wo      = (const float*)d_in[6];
    const float*         ln2_g   = (const float*)d_in[7];
    const float*         ln2_b   = (const float*)d_in[8];
    const float*         Wfc_in  = (const float*)d_in[9];
    const float*         Wfc_out = (const float*)d_in[10];
    float*               out     = (float*)d_out;

    __half *X, *Q, *K, *V, *CTX, *X2, *G;
    __half *WqkvT, *WoT, *WfciT, *WfcoT;
    float *H1;
    float2 *RTAB;
    cudaGetSymbolAddress((void**)&X,     g_X);
    cudaGetSymbolAddress((void**)&Q,     g_Q);
    cudaGetSymbolAddress((void**)&K,     g_K);
    cudaGetSymbolAddress((void**)&V,     g_V);
    cudaGetSymbolAddress((void**)&CTX,   g_CTX);
    cudaGetSymbolAddress((void**)&H1,    g_H1);
    cudaGetSymbolAddress((void**)&X2,    g_X2);
    cudaGetSymbolAddress((void**)&G,     g_G);
    cudaGetSymbolAddress((void**)&RTAB,  g_rtab);
    cudaGetSymbolAddress((void**)&WqkvT, g_WqkvT);
    cudaGetSymbolAddress((void**)&WoT,   g_WoT);
    cudaGetSymbolAddress((void**)&WfciT, g_WfciT);
    cudaGetSymbolAddress((void**)&WfcoT, g_WfcoT);

    cudaFuncSetAttribute(attn_kernel,
                         cudaFuncAttributeMaxDynamicSharedMemorySize,
                         AT_SMEM_BYTES);
    cudaFuncSetAttribute((tgemm<0,1>),
                         cudaFuncAttributeMaxDynamicSharedMemorySize,
                         GM_SMEM_BYTES);
    cudaFuncSetAttribute((tgemm<1,0>),
                         cudaFuncAttributeMaxDynamicSharedMemorySize,
                         GM_SMEM_BYTES);
    cudaFuncSetAttribute((tgemm<0,2>),
                         cudaFuncAttributeMaxDynamicSharedMemorySize,
                         GM_SMEM_BYTES);
    cudaFuncSetAttribute((tgemm<0,3>),
                         cudaFuncAttributeMaxDynamicSharedMemorySize,
                         GM_SMEM_BYTES);

    // 0) weight transposes + rope table
    transpose_h<<<dim3(NQKV/32, DD/32),  dim3(32,8)>>>(Wqkv,    WqkvT, DD,  NQKV);
    transpose_h<<<dim3(DD/32,   DD/32),  dim3(32,8)>>>(Wo,      WoT,   DD,  DD);
    transpose_h<<<dim3(DD/32,   FFN/32), dim3(32,8)>>>(Wfc_out, WfcoT, FFN, DD);
    transpose_h_pair2<<<dim3(FFN/32, DD/32), dim3(32,8)>>>(Wfc_in, WfciT);
    rtab_kernel<<<ROWS, 64>>>(pos, RTAB);

    // 1) LN1 (fp16 out)
    ln_kernel<<<ROWS, 256>>>(hidden, ln1_g, ln1_b, X);
    // 2) QKV projection + fused rope + scatter to Q/K/V
    tgemm<0,3><<<dim3(NQKV/128, ROWS/128), 128, GM_SMEM_BYTES>>>(
        X, WqkvT, nullptr, nullptr, DD, NQKV, RTAB, Q, K, V);
    // 3) attention -> ctx (fp16)
    attn_kernel<<<dim3(SS/128, HH, BB), 256, AT_SMEM_BYTES>>>(Q, K, V, mask, CTX);
    // 4) Wo projection + residual (f32 out)
    tgemm<1,0><<<dim3(DD/128, ROWS/128), 128, GM_SMEM_BYTES>>>(
        CTX, WoT, hidden, H1, DD, DD, nullptr, nullptr, nullptr, nullptr);
    // 5) LN2 (fp16 out)
    ln_kernel<<<ROWS, 256>>>(H1, ln2_g, ln2_b, X2);
    // 6) fc_in + fused SwiGLU (fp16 G out)
    tgemm<0,2><<<dim3(NFC/128, ROWS/128), 128, GM_SMEM_BYTES>>>(
        X2, WfciT, nullptr, G, DD, NFC, nullptr, nullptr, nullptr, nullptr);
    // 7) fc_out + residual (final output, f32)
    tgemm<1,0><<<dim3(DD/128, ROWS/128), 128, GM_SMEM_BYTES>>>(
        G, WfcoT, H1, out, FFN, DD, nullptr, nullptr, nullptr, nullptr);
}

// round 14
// speedup vs baseline: 1.2774x; 1.0026x over previous
#include <cuda_runtime.h>
#include <cuda_fp16.h>
#include <math.h>
#include <stdint.h>

// ---------------------------------------------------------------------------
// Problem constants
// ---------------------------------------------------------------------------
#define BB   2
#define SS   2048
#define DD   2048
#define HH   16
#define DHH  128
#define FFN  5632
#define ROWS (BB*SS)           // 4096
#define NQKV (3*HH*DHH)        // 6144
#define NFC  (2*FFN)           // 11264

// ---------------------------------------------------------------------------
// Scratch
// ---------------------------------------------------------------------------
__device__ __half g_X  [ROWS*DD];    // LN1 out
__device__ __half g_Q  [ROWS*DD];    // [B,H,S,DH]
__device__ __half g_K  [ROWS*DD];
__device__ __half g_V  [ROWS*DD];    // [B,H,S,DH]
__device__ __half g_CTX[ROWS*DD];    // [B,S,H*DH]
__device__ float  g_H1 [ROWS*DD];    // residual 1 (fp32)
__device__ __half g_X2 [ROWS*DD];    // LN2 out
__device__ __half g_G  [ROWS*FFN];   // swiglu out (written by fused fc_in)
__device__ float2 g_rtab[ROWS*64];   // rope (cos, sin) table per (row, freq)
// transposed weights [N,K] K-major, fp16
__device__ __half g_WqkvT [NQKV*DD];
__device__ __half g_WoT   [DD*DD];
__device__ __half g_WfciT [NFC*DD];  // interleaved: row 2j = a_j, 2j+1 = b_j
__device__ __half g_WfcoT [DD*FFN];

// ---------------------------------------------------------------------------
// Helpers
// ---------------------------------------------------------------------------
__device__ __forceinline__ uint32_t smem_u32(const void* p) {
    uint32_t a;
    asm("{ .reg .u64 t; cvta.to.shared.u64 t, %1; cvt.u32.u64 %0, t; }"
        : "=r"(a) : "l"(p));
    return a;
}

#define CP_ASYNC16(dst, src) \
    asm volatile("cp.async.cg.shared.global [%0], [%1], 16;" \
                 :: "r"(dst), "l"(src))
#define CP_COMMIT() asm volatile("cp.async.commit_group;" ::: "memory")
#define CP_WAIT1()  asm volatile("cp.async.wait_group 1;" ::: "memory")
#define CP_WAIT0()  asm volatile("cp.async.wait_group 0;" ::: "memory")

#define MMA_F16(d, a, b)                                                   \
    asm volatile(                                                          \
        "mma.sync.aligned.m16n8k16.row.col.f32.f16.f16.f32 "               \
        "{%0,%1,%2,%3}, {%4,%5,%6,%7}, {%8,%9}, {%0,%1,%2,%3};"            \
        : "+f"((d)[0]), "+f"((d)[1]), "+f"((d)[2]), "+f"((d)[3])           \
        : "r"((a)[0]), "r"((a)[1]), "r"((a)[2]), "r"((a)[3]),              \
          "r"((b)[0]), "r"((b)[1]))

#define LDSM_X4(r0, r1, r2, r3, addr)                                      \
    asm volatile("ldmatrix.sync.aligned.m8n8.x4.shared.b16 "               \
                 "{%0,%1,%2,%3}, [%4];"                                    \
                 : "=r"(r0), "=r"(r1), "=r"(r2), "=r"(r3) : "r"(addr))

#define LDSM_X2(r0, r1, addr)                                              \
    asm volatile("ldmatrix.sync.aligned.m8n8.x2.shared.b16 "               \
                 "{%0,%1}, [%2];"                                          \
                 : "=r"(r0), "=r"(r1) : "r"(addr))

#define LDSM_X2T(r0, r1, addr)                                             \
    asm volatile("ldmatrix.sync.aligned.m8n8.x2.trans.shared.b16 "         \
                 "{%0,%1}, [%2];"                                          \
                 : "=r"(r0), "=r"(r1) : "r"(addr))

// ---------------------------------------------------------------------------
// Weight transpose + fp16 round: W[K,N] f32 -> Wt[N,K] f16.
// 64x64 tiles: fp32 loads 256 B/row, fp16 stores 128 B/row (full sectors).
// ---------------------------------------------------------------------------
__global__ void __launch_bounds__(256) transpose_h(
    const float* __restrict__ W, __half* __restrict__ Wt, int K, int N)
{
    __shared__ float t[64][65];
    const int tx = threadIdx.x;    // 0..63
    const int ty = threadIdx.y;    // 0..3
    const int n0 = blockIdx.x * 64, k0 = blockIdx.y * 64;
#pragma unroll
    for (int j = 0; j < 16; j++)
        t[ty + j*4][tx] = W[(size_t)(k0 + ty + j*4) * N + n0 + tx];
    __syncthreads();
#pragma unroll
    for (int j = 0; j < 16; j++)
        Wt[(size_t)(n0 + ty + j*4) * K + k0 + tx] =
            __float2half_rn(t[tx][ty + j*4]);
}

// Merged paired transpose for fc_in (64x64 tiles):
// a-col j -> row 2j, b-col j -> row 2j+1.  W: [DD][NFC]
__global__ void __launch_bounds__(256) transpose_h_pair2(
    const float* __restrict__ W, __half* __restrict__ Wt)
{
    __shared__ float ta[64][65];
    __shared__ float tb[64][65];
    const int tx = threadIdx.x, ty = threadIdx.y;
    const int n0 = blockIdx.x * 64, k0 = blockIdx.y * 64;
#pragma unroll
    for (int j = 0; j < 16; j++) {
        const size_t rbase = (size_t)(k0 + ty + j*4) * NFC;
        ta[ty + j*4][tx] = W[rbase + n0 + tx];
        tb[ty + j*4][tx] = W[rbase + FFN + n0 + tx];
    }
    __syncthreads();
#pragma unroll
    for (int j = 0; j < 16; j++) {
        const int n = n0 + ty + j*4;
        Wt[(size_t)(2*n)     * DD + k0 + tx] = __float2half_rn(ta[tx][ty + j*4]);
        Wt[(size_t)(2*n + 1) * DD + k0 + tx] = __float2half_rn(tb[tx][ty + j*4]);
    }
}

// ---------------------------------------------------------------------------
// Rope sin/cos table
// ---------------------------------------------------------------------------
__global__ void __launch_bounds__(64) rtab_kernel(
    const int* __restrict__ pos_ids, float2* __restrict__ tab)
{
    const int r = blockIdx.x;
    const int j = threadIdx.x;
    const float pos = (float)pos_ids[r];
    const float inv = 1.0f / powf(10000.0f, (float)(2*j) * (1.0f/128.0f));
    float sn, cs;
    sincosf(pos * inv, &sn, &cs);
    tab[r*64 + j] = make_float2(cs, sn);
}

// ---------------------------------------------------------------------------
// FP16 mma.sync GEMM, ldmatrix fragments, 3-stage cp.async, k-chunk 64.
// CTA tile 128x128x64, 4 warps (2M x 2N), warp tile 64x64, 2 CTAs/SM.
// Smem rows: 64 halfs padded to 144 B (granule stride 9 -> conflict-free).
// OUT: 0 = f32 (+residual if EPI), 1 = f16,
//      2 = f16 fused swiglu (paired cols),
//      3 = fused rope+scatter to Q/K/V
// ---------------------------------------------------------------------------
#define TILE_BYTES 18432              // 128 rows * 144 B
#define STAGE_BYTES (2*TILE_BYTES)    // 36864
#define GM_SMEM_BYTES (3*STAGE_BYTES) // 110592 (x2 CTAs = 216 KB <= 228 KB)

template<int EPI, int OUT>
__global__ void __launch_bounds__(128, 2) tgemm(
    const __half* __restrict__ A, const __half* __restrict__ Bt,
    const float* __restrict__ R, void* __restrict__ Cv,
    int K, int N,
    const float2* __restrict__ rtab,
    __half* __restrict__ Qo, __half* __restrict__ Ko,
    __half* __restrict__ Vo)
{
    extern __shared__ char smc[];
    const uint32_t smb = smem_u32(smc);

    const int tid  = threadIdx.x;
    const int wid  = tid >> 5;
    const int lane = tid & 31;
    const int g    = lane >> 2;
    const int cc   = lane & 3;
    const int wm   = (wid & 1) * 64;
    const int wn   = (wid >> 1) * 64;

    const int m0 = blockIdx.y * 128;
    const int n0 = blockIdx.x * 128;

    const __half* Ab = A  + (size_t)m0 * K;
    const __half* Bb = Bt + (size_t)n0 * K;

    const int NC = K / 64;

    const uint32_t aoff = (uint32_t)(wm + (lane & 15)) * 144 + (lane >> 4) * 16;
    const uint32_t boff = (uint32_t)(wn + (lane & 7) + ((lane >> 4) * 8)) * 144
                        + ((lane >> 3) & 1) * 16;

#define LOAD_STAGE(chunk, st) do {                                         \
        const uint32_t asw = smb + (st)*STAGE_BYTES;                       \
        const uint32_t bsw = asw + TILE_BYTES;                             \
        const int kt = (chunk) * 64;                                       \
        _Pragma("unroll")                                                  \
        for (int j = 0; j < 8; j++) {                                      \
            const int f = tid + j * 128;                                   \
            const int row = f >> 3, c8 = f & 7;                            \
            CP_ASYNC16(asw + (uint32_t)(row*144 + c8*16),                  \
                       Ab + (size_t)row * K + kt + c8*8);                  \
            CP_ASYNC16(bsw + (uint32_t)(row*144 + c8*16),                  \
                       Bb + (size_t)row * K + kt + c8*8);                  \
        }                                                                  \
        CP_COMMIT();                                                       \
    } while (0)

    float acc[4][8][4];
#pragma unroll
    for (int mf = 0; mf < 4; mf++)
#pragma unroll
        for (int nf = 0; nf < 8; nf++)
#pragma unroll
            for (int q = 0; q < 4; q++) acc[mf][nf][q] = 0.f;

    LOAD_STAGE(0, 0);
    LOAD_STAGE(1, 1);

    int st = 0;
    for (int i = 0; i < NC; i++) {
        if (i == NC - 1) CP_WAIT0(); else CP_WAIT1();
        __syncthreads();
        if (i + 2 < NC) {
            const int st2 = (st + 2 >= 3) ? st - 1 : st + 2;
            LOAD_STAGE(i + 2, st2);
        }

        const uint32_t abase = smb + st * STAGE_BYTES;
        const uint32_t bbase = abase + TILE_BYTES;

#pragma unroll
        for (int ks = 0; ks < 4; ks++) {
            uint32_t a[4][4], b[8][2];
#pragma unroll
            for (int mf = 0; mf < 4; mf++)
                LDSM_X4(a[mf][0], a[mf][1], a[mf][2], a[mf][3],
                        abase + aoff + mf*2304 + ks*32);
#pragma unroll
            for (int p = 0; p < 4; p++)
                LDSM_X4(b[2*p][0], b[2*p][1], b[2*p+1][0], b[2*p+1][1],
                        bbase + boff + p*2304 + ks*32);
#pragma unroll
            for (int mf = 0; mf < 4; mf++)
#pragma unroll
                for (int nf = 0; nf < 8; nf++)
                    MMA_F16(acc[mf][nf], a[mf], b[nf]);
        }
        st = (st + 1 >= 3) ? 0 : st + 1;
    }
#undef LOAD_STAGE

    if (OUT == 3) {
        // ---- fused rope + scatter epilogue (tile = one {q,k,v} of a head) --
        const int head = n0 / 384;
        const int part = (n0 - head*384) / 128;   // 0=q, 1=k, 2=v
        __half* sh = (__half*)smc;                // stage [128][132] halfs

        __syncthreads();
#pragma unroll
        for (int mf = 0; mf < 4; mf++) {
#pragma unroll
            for (int nf = 0; nf < 8; nf++) {
                const int row = wm + mf * 16 + g;
                const int col = wn + nf * 8 + cc * 2;
                const __half2 h0 = __floats2half2_rn(acc[mf][nf][0], acc[mf][nf][1]);
                const __half2 h1 = __floats2half2_rn(acc[mf][nf][2], acc[mf][nf][3]);
                *(uint32_t*)&sh[row*132 + col]       = *(const uint32_t*)&h0;
                *(uint32_t*)&sh[(row + 8)*132 + col] = *(const uint32_t*)&h1;
            }
        }
        __syncthreads();

        __half* dst = (part == 0) ? Qo : (part == 1) ? Ko : Vo;
        const int rr = tid >> 6;
        const int dd = tid & 63;
#pragma unroll 4
        for (int i = 0; i < 64; i++) {
            const int r  = rr * 64 + i;
            const int bs = m0 + r;
            const int bI = bs >> 11, sI = bs & 2047;
            const size_t o = (((size_t)(bI*HH + head)) * SS + sI) * DHH;
            const float h0 = __half2float(sh[r*132 + dd]);
            const float h1 = __half2float(sh[r*132 + dd + 64]);
            if (part < 2) {
                const float2 t = rtab[(size_t)bs*64 + dd];
                dst[o + dd]      = __float2half_rn(h0*t.x - h1*t.y);
                dst[o + dd + 64] = __float2half_rn(h1*t.x + h0*t.y);
            } else {
                dst[o + dd]      = __float2half_rn(h0);
                dst[o + dd + 64] = __float2half_rn(h1);
            }
        }
        return;
    }

#pragma unroll
    for (int mf = 0; mf < 4; mf++) {
#pragma unroll
        for (int nf = 0; nf < 8; nf++) {
            const int row = m0 + wm + mf * 16 + g;
            const int col = n0 + wn + nf * 8 + cc * 2;
            float2 v0 = { acc[mf][nf][0], acc[mf][nf][1] };
            float2 v1 = { acc[mf][nf][2], acc[mf][nf][3] };
            if (OUT == 2) {
                __half* Gp = (__half*)Cv;
                const int gcol = col >> 1;
                const float s0 = v0.x / (1.0f + __expf(-v0.x)) * v0.y;
                const float s1 = v1.x / (1.0f + __expf(-v1.x)) * v1.y;
                Gp[(size_t)row * FFN + gcol]       = __float2half_rn(s0);
                Gp[(size_t)(row + 8) * FFN + gcol] = __float2half_rn(s1);
            } else {
                const size_t o0 = (size_t)row * N + col;
                const size_t o1 = (size_t)(row + 8) * N + col;
                if (EPI == 1) {
                    float2 r0 = *(const float2*)&R[o0];
                    float2 r1 = *(const float2*)&R[o1];
                    v0.x += r0.x; v0.y += r0.y;
                    v1.x += r1.x; v1.y += r1.y;
                }
                if (OUT == 1) {
                    __half* C = (__half*)Cv;
                    const __half2 h0 = __floats2half2_rn(v0.x, v0.y);
                    const __half2 h1 = __floats2half2_rn(v1.x, v1.y);
                    *(uint32_t*)&C[o0] = *(const uint32_t*)&h0;
                    *(uint32_t*)&C[o1] = *(const uint32_t*)&h1;
                } else {
                    float* C = (float*)Cv;
                    *(float2*)&C[o0] = v0;
                    *(float2*)&C[o1] = v1;
                }
            }
        }
    }
}

// ---------------------------------------------------------------------------
// LayerNorm: fp32 in, fp16 out
// ---------------------------------------------------------------------------
__global__ void __launch_bounds__(256) ln_kernel(
    const float* __restrict__ X, const float* __restrict__ g,
    const float* __restrict__ b, __half* __restrict__ Y)
{
    const int tid = threadIdx.x;
    const float* x = X + (size_t)blockIdx.x * DD;
    __half* y = Y + (size_t)blockIdx.x * DD;

    float v[8];
    *(float4*)&v[0] = *(const float4*)&x[tid*8];
    *(float4*)&v[4] = *(const float4*)&x[tid*8 + 4];

    float s = 0.f, sq = 0.f;
#pragma unroll
    for (int i = 0; i < 8; i++) { s += v[i]; sq += v[i]*v[i]; }
#pragma unroll
    for (int o = 16; o; o >>= 1) {
        s  += __shfl_xor_sync(0xffffffffu, s,  o);
        sq += __shfl_xor_sync(0xffffffffu, sq, o);
    }
    __shared__ float red[2][8];
    __shared__ float stats[2];
    const int w = tid >> 5, l = tid & 31;
    if (l == 0) { red[0][w] = s; red[1][w] = sq; }
    __syncthreads();
    if (tid == 0) {
        float S = 0.f, SQ = 0.f;
#pragma unroll
        for (int i = 0; i < 8; i++) { S += red[0][i]; SQ += red[1][i]; }
        const float mean = S * (1.0f/DD);
        const float var  = SQ * (1.0f/DD) - mean*mean;
        stats[0] = mean;
        stats[1] = rsqrtf(var + 1e-5f);
    }
    __syncthreads();
    const float mean = stats[0], rstd = stats[1];

    float gv[8], bv[8];
    *(float4*)&gv[0] = *(const float4*)&g[tid*8];
    *(float4*)&gv[4] = *(const float4*)&g[tid*8+4];
    *(float4*)&bv[0] = *(const float4*)&b[tid*8];
    *(float4*)&bv[4] = *(const float4*)&b[tid*8+4];

    __half2 h[4];
#pragma unroll
    for (int i = 0; i < 4; i++) {
        const float a0 = (v[2*i]   - mean) * rstd * gv[2*i]   + bv[2*i];
        const float a1 = (v[2*i+1] - mean) * rstd * gv[2*i+1] + bv[2*i+1];
        h[i] = __floats2half2_rn(a0, a1);
    }
    *(uint4*)&y[tid*8] = *(uint4*)h;
}

// ---------------------------------------------------------------------------
// Flash attention: fp16 mma + ldmatrix, cp.async double-buffered K/V tiles,
// V via ldmatrix.trans, Q frags in registers, P in registers, 1 sync/tile.
// ---------------------------------------------------------------------------
#define AT_SMEM_BYTES (26112*4)

__global__ void __launch_bounds__(256) attn_kernel(
    const __half* __restrict__ Q, const __half* __restrict__ K,
    const __half* __restrict__ V, const unsigned char* __restrict__ mask,
    __half* __restrict__ CTX)
{
    extern __shared__ uint32_t smu[];
    const uint32_t smb = smem_u32(smu);
    const uint32_t kB0 = smb + 8704*4;
    const uint32_t vB0 = smb + 17408*4;
#define KBUF(bf) (kB0 + (bf)*17408)
#define VBUF(bf) (vB0 + (bf)*17408)

    const int tid  = threadIdx.x;
    const int lane = tid & 31;
    const int wid  = tid >> 5;
    const int g    = lane >> 2;
    const int cc   = lane & 3;
    const int wm   = wid * 16;

    const int qt = blockIdx.x, h = blockIdx.y, b = blockIdx.z;
    const size_t headoff = ((size_t)(b*HH + h)) * SS * DHH;
    const __half* Qg    = Q + headoff + (size_t)qt * 128 * DHH;
    const __half* Kbase = K + headoff;
    const __half* Vbase = V + headoff;

#pragma unroll
    for (int j = 0; j < 8; j++) {
        const int f = tid + j * 256;
        const int r = f >> 4, c = f & 15;
        CP_ASYNC16(smb + (uint32_t)(r*272 + c*16), Qg + r*DHH + c*8);
    }
    CP_COMMIT();

#define LOAD_KV(t, bf) do {                                                \
        const __half* Kg_ = Kbase + (size_t)(t) * 64 * DHH;                \
        const __half* Vg_ = Vbase + (size_t)(t) * 64 * DHH;                \
        _Pragma("unroll")                                                  \
        for (int j = 0; j < 4; j++) {                                      \
            const int f = tid + j * 256;                                   \
            const int r = f >> 4, c = f & 15;                              \
            CP_ASYNC16(KBUF(bf) + (uint32_t)(r*272 + c*16),                \
                       Kg_ + r*DHH + c*8);                                 \
            CP_ASYNC16(VBUF(bf) + (uint32_t)(r*272 + c*16),                \
                       Vg_ + r*DHH + c*8);                                 \
        }                                                                  \
        CP_COMMIT();                                                       \
    } while (0)

    LOAD_KV(0, 0);
    LOAD_KV(1, 1);

    CP_WAIT1();
    __syncthreads();

    uint32_t qf[8][4];
    {
        const uint32_t qaddr = smb + (uint32_t)(wm + (lane & 15)) * 272
                             + (lane >> 4) * 16;
#pragma unroll
        for (int ks = 0; ks < 8; ks++)
            LDSM_X4(qf[ks][0], qf[ks][1], qf[ks][2], qf[ks][3], qaddr + ks*32);
    }

    const uint32_t kaddrL = (uint32_t)(lane & 7) * 272 + ((lane >> 3) & 1) * 16;
    const uint32_t vaddrL = (uint32_t)(lane & 15) * 272;

    float m0r = -1e30f, m1r = -1e30f, l0r = 0.f, l1r = 0.f;
    float O[16][4];
#pragma unroll
    for (int nf = 0; nf < 16; nf++)
#pragma unroll
        for (int q = 0; q < 4; q++) O[nf][q] = 0.f;

    const float scale = 0.08838834764831845f;
    const unsigned char* mrow = mask + (size_t)b * SS * SS;
    const int qg0 = qt * 128 + wm + g;
    const int qg8 = qg0 + 8;

    for (int t = 0; t < 32; t++) {
        const int bf = t & 1;
        const int kt = t * 64;

        unsigned short mRa[8], mRb[8];
        {
            const unsigned char* mpA = mrow + (size_t)qg0 * SS + kt + 2*cc;
            const unsigned char* mpB = mrow + (size_t)qg8 * SS + kt + 2*cc;
#pragma unroll
            for (int nf = 0; nf < 8; nf++) {
                mRa[nf] = *(const unsigned short*)(mpA + nf*8);
                mRb[nf] = *(const unsigned short*)(mpB + nf*8);
            }
        }

        float s[8][4];
#pragma unroll
        for (int nf = 0; nf < 8; nf++)
#pragma unroll
            for (int q = 0; q < 4; q++) s[nf][q] = 0.f;

        const uint32_t kb = KBUF(bf) + kaddrL;
#pragma unroll
        for (int ks = 0; ks < 8; ks++) {
            uint32_t bb[8][2];
#pragma unroll
            for (int nf = 0; nf < 8; nf++)
                LDSM_X2(bb[nf][0], bb[nf][1], kb + nf*2176 + ks*32);
#pragma unroll
            for (int nf = 0; nf < 8; nf++)
                MMA_F16(s[nf], qf[ks], bb[nf]);
        }

        float rmax0 = -1e30f, rmax1 = -1e30f;
#pragma unroll
        for (int nf = 0; nf < 8; nf++) {
            float s0 = s[nf][0]*scale, s1 = s[nf][1]*scale;
            float s2 = s[nf][2]*scale, s3 = s[nf][3]*scale;
            if (mRa[nf] & 0x00ffu) s0 = -10000.f;
            if (mRa[nf] & 0xff00u) s1 = -10000.f;
            if (mRb[nf] & 0x00ffu) s2 = -10000.f;
            if (mRb[nf] & 0xff00u) s3 = -10000.f;
            s[nf][0] = s0; s[nf][1] = s1; s[nf][2] = s2; s[nf][3] = s3;
            rmax0 = fmaxf(rmax0, fmaxf(s0, s1));
            rmax1 = fmaxf(rmax1, fmaxf(s2, s3));
        }
        rmax0 = fmaxf(rmax0, __shfl_xor_sync(0xffffffffu, rmax0, 1));
        rmax0 = fmaxf(rmax0, __shfl_xor_sync(0xffffffffu, rmax0, 2));
        rmax1 = fmaxf(rmax1, __shfl_xor_sync(0xffffffffu, rmax1, 1));
        rmax1 = fmaxf(rmax1, __shfl_xor_sync(0xffffffffu, rmax1, 2));

        const float mn0 = fmaxf(m0r, rmax0);
        const float mn1 = fmaxf(m1r, rmax1);
        const float cf0 = __expf(m0r - mn0);
        const float cf1 = __expf(m1r - mn1);
        m0r = mn0; m1r = mn1;

        uint32_t pfrag[8][2];
        float ls0 = 0.f, ls1 = 0.f;
#pragma unroll
        for (int nf = 0; nf < 8; nf++) {
            const float p0 = __expf(s[nf][0] - mn0);
            const float p1 = __expf(s[nf][1] - mn0);
            const float p2 = __expf(s[nf][2] - mn1);
            const float p3 = __expf(s[nf][3] - mn1);
            ls0 += p0 + p1; ls1 += p2 + p3;
            const __half2 h01 = __floats2half2_rn(p0, p1);
            const __half2 h23 = __floats2half2_rn(p2, p3);
            pfrag[nf][0] = *(const uint32_t*)&h01;
            pfrag[nf][1] = *(const uint32_t*)&h23;
        }
        ls0 += __shfl_xor_sync(0xffffffffu, ls0, 1);
        ls0 += __shfl_xor_sync(0xffffffffu, ls0, 2);
        ls1 += __shfl_xor_sync(0xffffffffu, ls1, 1);
        ls1 += __shfl_xor_sync(0xffffffffu, ls1, 2);
        l0r = l0r * cf0 + ls0;
        l1r = l1r * cf1 + ls1;

#pragma unroll
        for (int nf = 0; nf < 16; nf++) {
            O[nf][0] *= cf0; O[nf][1] *= cf0;
            O[nf][2] *= cf1; O[nf][3] *= cf1;
        }

        const uint32_t vb = VBUF(bf) + vaddrL;
#pragma unroll
        for (int ks = 0; ks < 4; ks++) {
            uint32_t a[4] = { pfrag[2*ks][0],   pfrag[2*ks][1],
                              pfrag[2*ks+1][0], pfrag[2*ks+1][1] };
            uint32_t bb[16][2];
#pragma unroll
            for (int nf = 0; nf < 16; nf++)
                LDSM_X2T(bb[nf][0], bb[nf][1], vb + ks*4352 + nf*16);
#pragma unroll
            for (int nf = 0; nf < 16; nf++)
                MMA_F16(O[nf], a, bb[nf]);
        }
        __syncthreads();

        if (t + 2 < 32) LOAD_KV(t + 2, bf);
        CP_WAIT1();
    }
#undef LOAD_KV

    const float inv0 = 1.0f / l0r;
    const float inv1 = 1.0f / l1r;
    __half* C0 = CTX + ((size_t)(b*SS + qg0)) * DD + h*DHH;
    __half* C1 = CTX + ((size_t)(b*SS + qg8)) * DD + h*DHH;
#pragma unroll
    for (int nf = 0; nf < 16; nf++) {
        const int c2 = nf*8 + 2*cc;
        const __half2 h0 = __floats2half2_rn(O[nf][0]*inv0, O[nf][1]*inv0);
        const __half2 h1 = __floats2half2_rn(O[nf][2]*inv1, O[nf][3]*inv1);
        *(uint32_t*)(C0 + c2) = *(const uint32_t*)&h0;
        *(uint32_t*)(C1 + c2) = *(const uint32_t*)&h1;
    }
}

// ---------------------------------------------------------------------------
// Launch
// ---------------------------------------------------------------------------
extern "C" void kernel_launch(void* const* d_in, const int* in_sizes, int n_in,
                              void* d_out, int out_size)
{
    const float*         hidden  = (const float*)d_in[0];
    const unsigned char* mask    = (const unsigned char*)d_in[1];
    const int*           pos     = (const int*)d_in[2];
    const float*         ln1_g   = (const float*)d_in[3];
    const float*         ln1_b   = (const float*)d_in[4];
    const float*         Wqkv    = (const float*)d_in[5];
    const float*         Wo      = (const float*)d_in[6];
    const float*         ln2_g   = (const float*)d_in[7];
    const float*         ln2_b   = (const float*)d_in[8];
    const float*         Wfc_in  = (const float*)d_in[9];
    const float*         Wfc_out = (const float*)d_in[10];
    float*               out     = (float*)d_out;

    __half *X, *Q, *K, *V, *CTX, *X2, *G;
    __half *WqkvT, *WoT, *WfciT, *WfcoT;
    float *H1;
    float2 *RTAB;
    cudaGetSymbolAddress((void**)&X,     g_X);
    cudaGetSymbolAddress((void**)&Q,     g_Q);
    cudaGetSymbolAddress((void**)&K,     g_K);
    cudaGetSymbolAddress((void**)&V,     g_V);
    cudaGetSymbolAddress((void**)&CTX,   g_CTX);
    cudaGetSymbolAddress((void**)&H1,    g_H1);
    cudaGetSymbolAddress((void**)&X2,    g_X2);
    cudaGetSymbolAddress((void**)&G,     g_G);
    cudaGetSymbolAddress((void**)&RTAB,  g_rtab);
    cudaGetSymbolAddress((void**)&WqkvT, g_WqkvT);
    cudaGetSymbolAddress((void**)&WoT,   g_WoT);
    cudaGetSymbolAddress((void**)&WfciT, g_WfciT);
    cudaGetSymbolAddress((void**)&WfcoT, g_WfcoT);

    cudaFuncSetAttribute(attn_kernel,
                         cudaFuncAttributeMaxDynamicSharedMemorySize,
                         AT_SMEM_BYTES);
    cudaFuncSetAttribute((tgemm<0,1>),
                         cudaFuncAttributeMaxDynamicSharedMemorySize,
                         GM_SMEM_BYTES);
    cudaFuncSetAttribute((tgemm<1,0>),
                         cudaFuncAttributeMaxDynamicSharedMemorySize,
                         GM_SMEM_BYTES);
    cudaFuncSetAttribute((tgemm<0,2>),
                         cudaFuncAttributeMaxDynamicSharedMemorySize,
                         GM_SMEM_BYTES);
    cudaFuncSetAttribute((tgemm<0,3>),
                         cudaFuncAttributeMaxDynamicSharedMemorySize,
                         GM_SMEM_BYTES);

    // 0) weight transposes (64x64 tiles) + rope table
    transpose_h<<<dim3(NQKV/64, DD/64),  dim3(64,4)>>>(Wqkv,    WqkvT, DD,  NQKV);
    transpose_h<<<dim3(DD/64,   DD/64),  dim3(64,4)>>>(Wo,      WoT,   DD,  DD);
    transpose_h<<<dim3(DD/64,   FFN/64), dim3(64,4)>>>(Wfc_out, WfcoT, FFN, DD);
    transpose_h_pair2<<<dim3(FFN/64, DD/64), dim3(64,4)>>>(Wfc_in, WfciT);
    rtab_kernel<<<ROWS, 64>>>(pos, RTAB);

    // 1) LN1 (fp16 out)
    ln_kernel<<<ROWS, 256>>>(hidden, ln1_g, ln1_b, X);
    // 2) QKV projection + fused rope + scatter to Q/K/V
    tgemm<0,3><<<dim3(NQKV/128, ROWS/128), 128, GM_SMEM_BYTES>>>(
        X, WqkvT, nullptr, nullptr, DD, NQKV, RTAB, Q, K, V);
    // 3) attention -> ctx (fp16)
    attn_kernel<<<dim3(SS/128, HH, BB), 256, AT_SMEM_BYTES>>>(Q, K, V, mask, CTX);
    // 4) Wo projection + residual (f32 out)
    tgemm<1,0><<<dim3(DD/128, ROWS/128), 128, GM_SMEM_BYTES>>>(
        CTX, WoT, hidden, H1, DD, DD, nullptr, nullptr, nullptr, nullptr);
    // 5) LN2 (fp16 out)
    ln_kernel<<<ROWS, 256>>>(H1, ln2_g, ln2_b, X2);
    // 6) fc_in + fused SwiGLU (fp16 G out)
    tgemm<0,2><<<dim3(NFC/128, ROWS/128), 128, GM_SMEM_BYTES>>>(
        X2, WfciT, nullptr, G, DD, NFC, nullptr, nullptr, nullptr, nullptr);
    // 7) fc_out + residual (final output, f32)
    tgemm<1,0><<<dim3(DD/128, ROWS/128), 128, GM_SMEM_BYTES>>>(
        G, WfcoT, H1, out, FFN, DD, nullptr, nullptr, nullptr, nullptr);
}

// round 15
// speedup vs baseline: 1.2952x; 1.0139x over previous
#include <cuda_runtime.h>
#include <cuda_fp16.h>
#include <math.h>
#include <stdint.h>

// ---------------------------------------------------------------------------
// Problem constants
// ---------------------------------------------------------------------------
#define BB   2
#define SS   2048
#define DD   2048
#define HH   16
#define DHH  128
#define FFN  5632
#define ROWS (BB*SS)           // 4096
#define NQKV (3*HH*DHH)        // 6144
#define NFC  (2*FFN)           // 11264

// ---------------------------------------------------------------------------
// Scratch
// ---------------------------------------------------------------------------
__device__ __half g_X  [ROWS*DD];    // LN1 out
__device__ __half g_Q  [ROWS*DD];    // [B,H,S,DH]
__device__ __half g_K  [ROWS*DD];
__device__ __half g_V  [ROWS*DD];    // [B,H,S,DH]
__device__ __half g_CTX[ROWS*DD];    // [B,S,H*DH]
__device__ float  g_H1 [ROWS*DD];    // residual 1 (fp32)
__device__ __half g_X2 [ROWS*DD];    // LN2 out
__device__ __half g_G  [ROWS*FFN];   // swiglu out (written by fused fc_in)
__device__ float2 g_rtab[ROWS*64];   // rope (cos, sin) table per (row, freq)
// transposed weights [N,K] K-major, fp16
__device__ __half g_WqkvT [NQKV*DD];
__device__ __half g_WoT   [DD*DD];
__device__ __half g_WfciT [NFC*DD];  // interleaved: row 2j = a_j, 2j+1 = b_j
__device__ __half g_WfcoT [DD*FFN];

// ---------------------------------------------------------------------------
// Helpers
// ---------------------------------------------------------------------------
__device__ __forceinline__ uint32_t smem_u32(const void* p) {
    uint32_t a;
    asm("{ .reg .u64 t; cvta.to.shared.u64 t, %1; cvt.u32.u64 %0, t; }"
        : "=r"(a) : "l"(p));
    return a;
}

#define CP_ASYNC16(dst, src) \
    asm volatile("cp.async.cg.shared.global [%0], [%1], 16;" \
                 :: "r"(dst), "l"(src))
#define CP_COMMIT() asm volatile("cp.async.commit_group;" ::: "memory")
#define CP_WAIT1()  asm volatile("cp.async.wait_group 1;" ::: "memory")
#define CP_WAIT0()  asm volatile("cp.async.wait_group 0;" ::: "memory")

#define MMA_F16(d, a, b)                                                   \
    asm volatile(                                                          \
        "mma.sync.aligned.m16n8k16.row.col.f32.f16.f16.f32 "               \
        "{%0,%1,%2,%3}, {%4,%5,%6,%7}, {%8,%9}, {%0,%1,%2,%3};"            \
        : "+f"((d)[0]), "+f"((d)[1]), "+f"((d)[2]), "+f"((d)[3])           \
        : "r"((a)[0]), "r"((a)[1]), "r"((a)[2]), "r"((a)[3]),              \
          "r"((b)[0]), "r"((b)[1]))

#define LDSM_X4(r0, r1, r2, r3, addr)                                      \
    asm volatile("ldmatrix.sync.aligned.m8n8.x4.shared.b16 "               \
                 "{%0,%1,%2,%3}, [%4];"                                    \
                 : "=r"(r0), "=r"(r1), "=r"(r2), "=r"(r3) : "r"(addr))

#define LDSM_X2(r0, r1, addr)                                              \
    asm volatile("ldmatrix.sync.aligned.m8n8.x2.shared.b16 "               \
                 "{%0,%1}, [%2];"                                          \
                 : "=r"(r0), "=r"(r1) : "r"(addr))

#define LDSM_X2T(r0, r1, addr)                                             \
    asm volatile("ldmatrix.sync.aligned.m8n8.x2.trans.shared.b16 "         \
                 "{%0,%1}, [%2];"                                          \
                 : "=r"(r0), "=r"(r1) : "r"(addr))

// ---------------------------------------------------------------------------
// Weight transpose + fp16 round: W[K,N] f32 -> Wt[N,K] f16 (64x64 tiles)
// ---------------------------------------------------------------------------
__global__ void __launch_bounds__(256) transpose_h(
    const float* __restrict__ W, __half* __restrict__ Wt, int K, int N)
{
    __shared__ float t[64][65];
    const int tx = threadIdx.x;
    const int ty = threadIdx.y;
    const int n0 = blockIdx.x * 64, k0 = blockIdx.y * 64;
#pragma unroll
    for (int j = 0; j < 16; j++)
        t[ty + j*4][tx] = W[(size_t)(k0 + ty + j*4) * N + n0 + tx];
    __syncthreads();
#pragma unroll
    for (int j = 0; j < 16; j++)
        Wt[(size_t)(n0 + ty + j*4) * K + k0 + tx] =
            __float2half_rn(t[tx][ty + j*4]);
}

// Merged paired transpose for fc_in (64x64 tiles)
__global__ void __launch_bounds__(256) transpose_h_pair2(
    const float* __restrict__ W, __half* __restrict__ Wt)
{
    __shared__ float ta[64][65];
    __shared__ float tb[64][65];
    const int tx = threadIdx.x, ty = threadIdx.y;
    const int n0 = blockIdx.x * 64, k0 = blockIdx.y * 64;
#pragma unroll
    for (int j = 0; j < 16; j++) {
        const size_t rbase = (size_t)(k0 + ty + j*4) * NFC;
        ta[ty + j*4][tx] = W[rbase + n0 + tx];
        tb[ty + j*4][tx] = W[rbase + FFN + n0 + tx];
    }
    __syncthreads();
#pragma unroll
    for (int j = 0; j < 16; j++) {
        const int n = n0 + ty + j*4;
        Wt[(size_t)(2*n)     * DD + k0 + tx] = __float2half_rn(ta[tx][ty + j*4]);
        Wt[(size_t)(2*n + 1) * DD + k0 + tx] = __float2half_rn(tb[tx][ty + j*4]);
    }
}

// ---------------------------------------------------------------------------
// Rope sin/cos table
// ---------------------------------------------------------------------------
__global__ void __launch_bounds__(64) rtab_kernel(
    const int* __restrict__ pos_ids, float2* __restrict__ tab)
{
    const int r = blockIdx.x;
    const int j = threadIdx.x;
    const float pos = (float)pos_ids[r];
    const float inv = 1.0f / powf(10000.0f, (float)(2*j) * (1.0f/128.0f));
    float sn, cs;
    sincosf(pos * inv, &sn, &cs);
    tab[r*64 + j] = make_float2(cs, sn);
}

// ---------------------------------------------------------------------------
// FP16 mma.sync GEMM, ldmatrix fragments, 3-stage cp.async, k-chunk 64.
// CTA tile 128x128x64, 4 warps (2M x 2N), warp tile 64x64, 2 CTAs/SM.
// OUT: 0 = f32 (+residual if EPI), 1 = f16,
//      2 = f16 fused swiglu (paired cols),
//      3 = fused rope+scatter to Q/K/V
// ---------------------------------------------------------------------------
#define TILE_BYTES 18432              // 128 rows * 144 B
#define STAGE_BYTES (2*TILE_BYTES)    // 36864
#define GM_SMEM_BYTES (3*STAGE_BYTES) // 110592

template<int EPI, int OUT>
__global__ void __launch_bounds__(128, 2) tgemm(
    const __half* __restrict__ A, const __half* __restrict__ Bt,
    const float* __restrict__ R, void* __restrict__ Cv,
    int K, int N,
    const float2* __restrict__ rtab,
    __half* __restrict__ Qo, __half* __restrict__ Ko,
    __half* __restrict__ Vo)
{
    extern __shared__ char smc[];
    const uint32_t smb = smem_u32(smc);

    const int tid  = threadIdx.x;
    const int wid  = tid >> 5;
    const int lane = tid & 31;
    const int g    = lane >> 2;
    const int cc   = lane & 3;
    const int wm   = (wid & 1) * 64;
    const int wn   = (wid >> 1) * 64;

    const int m0 = blockIdx.y * 128;
    const int n0 = blockIdx.x * 128;

    const __half* Ab = A  + (size_t)m0 * K;
    const __half* Bb = Bt + (size_t)n0 * K;

    const int NC = K / 64;

    const uint32_t aoff = (uint32_t)(wm + (lane & 15)) * 144 + (lane >> 4) * 16;
    const uint32_t boff = (uint32_t)(wn + (lane & 7) + ((lane >> 4) * 8)) * 144
                        + ((lane >> 3) & 1) * 16;

#define LOAD_STAGE(chunk, st) do {                                         \
        const uint32_t asw = smb + (st)*STAGE_BYTES;                       \
        const uint32_t bsw = asw + TILE_BYTES;                             \
        const int kt = (chunk) * 64;                                       \
        _Pragma("unroll")                                                  \
        for (int j = 0; j < 8; j++) {                                      \
            const int f = tid + j * 128;                                   \
            const int row = f >> 3, c8 = f & 7;                            \
            CP_ASYNC16(asw + (uint32_t)(row*144 + c8*16),                  \
                       Ab + (size_t)row * K + kt + c8*8);                  \
            CP_ASYNC16(bsw + (uint32_t)(row*144 + c8*16),                  \
                       Bb + (size_t)row * K + kt + c8*8);                  \
        }                                                                  \
        CP_COMMIT();                                                       \
    } while (0)

    float acc[4][8][4];
#pragma unroll
    for (int mf = 0; mf < 4; mf++)
#pragma unroll
        for (int nf = 0; nf < 8; nf++)
#pragma unroll
            for (int q = 0; q < 4; q++) acc[mf][nf][q] = 0.f;

    LOAD_STAGE(0, 0);
    LOAD_STAGE(1, 1);

    int st = 0;
    for (int i = 0; i < NC; i++) {
        if (i == NC - 1) CP_WAIT0(); else CP_WAIT1();
        __syncthreads();
        if (i + 2 < NC) {
            const int st2 = (st + 2 >= 3) ? st - 1 : st + 2;
            LOAD_STAGE(i + 2, st2);
        }

        const uint32_t abase = smb + st * STAGE_BYTES;
        const uint32_t bbase = abase + TILE_BYTES;

#pragma unroll
        for (int ks = 0; ks < 4; ks++) {
            uint32_t a[4][4], b[8][2];
#pragma unroll
            for (int mf = 0; mf < 4; mf++)
                LDSM_X4(a[mf][0], a[mf][1], a[mf][2], a[mf][3],
                        abase + aoff + mf*2304 + ks*32);
#pragma unroll
            for (int p = 0; p < 4; p++)
                LDSM_X4(b[2*p][0], b[2*p][1], b[2*p+1][0], b[2*p+1][1],
                        bbase + boff + p*2304 + ks*32);
#pragma unroll
            for (int mf = 0; mf < 4; mf++)
#pragma unroll
                for (int nf = 0; nf < 8; nf++)
                    MMA_F16(acc[mf][nf], a[mf], b[nf]);
        }
        st = (st + 1 >= 3) ? 0 : st + 1;
    }
#undef LOAD_STAGE

    if (OUT == 3) {
        const int head = n0 / 384;
        const int part = (n0 - head*384) / 128;   // 0=q, 1=k, 2=v
        __half* sh = (__half*)smc;

        __syncthreads();
#pragma unroll
        for (int mf = 0; mf < 4; mf++) {
#pragma unroll
            for (int nf = 0; nf < 8; nf++) {
                const int row = wm + mf * 16 + g;
                const int col = wn + nf * 8 + cc * 2;
                const __half2 h0 = __floats2half2_rn(acc[mf][nf][0], acc[mf][nf][1]);
                const __half2 h1 = __floats2half2_rn(acc[mf][nf][2], acc[mf][nf][3]);
                *(uint32_t*)&sh[row*132 + col]       = *(const uint32_t*)&h0;
                *(uint32_t*)&sh[(row + 8)*132 + col] = *(const uint32_t*)&h1;
            }
        }
        __syncthreads();

        __half* dst = (part == 0) ? Qo : (part == 1) ? Ko : Vo;
        const int rr = tid >> 6;
        const int dd = tid & 63;
#pragma unroll 4
        for (int i = 0; i < 64; i++) {
            const int r  = rr * 64 + i;
            const int bs = m0 + r;
            const int bI = bs >> 11, sI = bs & 2047;
            const size_t o = (((size_t)(bI*HH + head)) * SS + sI) * DHH;
            const float h0 = __half2float(sh[r*132 + dd]);
            const float h1 = __half2float(sh[r*132 + dd + 64]);
            if (part < 2) {
                const float2 t = rtab[(size_t)bs*64 + dd];
                dst[o + dd]      = __float2half_rn(h0*t.x - h1*t.y);
                dst[o + dd + 64] = __float2half_rn(h1*t.x + h0*t.y);
            } else {
                dst[o + dd]      = __float2half_rn(h0);
                dst[o + dd + 64] = __float2half_rn(h1);
            }
        }
        return;
    }

#pragma unroll
    for (int mf = 0; mf < 4; mf++) {
#pragma unroll
        for (int nf = 0; nf < 8; nf++) {
            const int row = m0 + wm + mf * 16 + g;
            const int col = n0 + wn + nf * 8 + cc * 2;
            float2 v0 = { acc[mf][nf][0], acc[mf][nf][1] };
            float2 v1 = { acc[mf][nf][2], acc[mf][nf][3] };
            if (OUT == 2) {
                __half* Gp = (__half*)Cv;
                const int gcol = col >> 1;
                const float s0 = v0.x / (1.0f + __expf(-v0.x)) * v0.y;
                const float s1 = v1.x / (1.0f + __expf(-v1.x)) * v1.y;
                Gp[(size_t)row * FFN + gcol]       = __float2half_rn(s0);
                Gp[(size_t)(row + 8) * FFN + gcol] = __float2half_rn(s1);
            } else {
                const size_t o0 = (size_t)row * N + col;
                const size_t o1 = (size_t)(row + 8) * N + col;
                if (EPI == 1) {
                    float2 r0 = *(const float2*)&R[o0];
                    float2 r1 = *(const float2*)&R[o1];
                    v0.x += r0.x; v0.y += r0.y;
                    v1.x += r1.x; v1.y += r1.y;
                }
                if (OUT == 1) {
                    __half* C = (__half*)Cv;
                    const __half2 h0 = __floats2half2_rn(v0.x, v0.y);
                    const __half2 h1 = __floats2half2_rn(v1.x, v1.y);
                    *(uint32_t*)&C[o0] = *(const uint32_t*)&h0;
                    *(uint32_t*)&C[o1] = *(const uint32_t*)&h1;
                } else {
                    float* C = (float*)Cv;
                    *(float2*)&C[o0] = v0;
                    *(float2*)&C[o1] = v1;
                }
            }
        }
    }
}

// ---------------------------------------------------------------------------
// LayerNorm: fp32 in, fp16 out
// ---------------------------------------------------------------------------
__global__ void __launch_bounds__(256) ln_kernel(
    const float* __restrict__ X, const float* __restrict__ g,
    const float* __restrict__ b, __half* __restrict__ Y)
{
    const int tid = threadIdx.x;
    const float* x = X + (size_t)blockIdx.x * DD;
    __half* y = Y + (size_t)blockIdx.x * DD;

    float v[8];
    *(float4*)&v[0] = *(const float4*)&x[tid*8];
    *(float4*)&v[4] = *(const float4*)&x[tid*8 + 4];

    float s = 0.f, sq = 0.f;
#pragma unroll
    for (int i = 0; i < 8; i++) { s += v[i]; sq += v[i]*v[i]; }
#pragma unroll
    for (int o = 16; o; o >>= 1) {
        s  += __shfl_xor_sync(0xffffffffu, s,  o);
        sq += __shfl_xor_sync(0xffffffffu, sq, o);
    }
    __shared__ float red[2][8];
    __shared__ float stats[2];
    const int w = tid >> 5, l = tid & 31;
    if (l == 0) { red[0][w] = s; red[1][w] = sq; }
    __syncthreads();
    if (tid == 0) {
        float S = 0.f, SQ = 0.f;
#pragma unroll
        for (int i = 0; i < 8; i++) { S += red[0][i]; SQ += red[1][i]; }
        const float mean = S * (1.0f/DD);
        const float var  = SQ * (1.0f/DD) - mean*mean;
        stats[0] = mean;
        stats[1] = rsqrtf(var + 1e-5f);
    }
    __syncthreads();
    const float mean = stats[0], rstd = stats[1];

    float gv[8], bv[8];
    *(float4*)&gv[0] = *(const float4*)&g[tid*8];
    *(float4*)&gv[4] = *(const float4*)&g[tid*8+4];
    *(float4*)&bv[0] = *(const float4*)&b[tid*8];
    *(float4*)&bv[4] = *(const float4*)&b[tid*8+4];

    __half2 h[4];
#pragma unroll
    for (int i = 0; i < 4; i++) {
        const float a0 = (v[2*i]   - mean) * rstd * gv[2*i]   + bv[2*i];
        const float a1 = (v[2*i+1] - mean) * rstd * gv[2*i+1] + bv[2*i+1];
        h[i] = __floats2half2_rn(a0, a1);
    }
    *(uint4*)&y[tid*8] = *(uint4*)h;
}

// ---------------------------------------------------------------------------
// Flash attention: fp16 mma + ldmatrix, cp.async double-buffered K/V tiles
// of 128 kv rows (16 tile iterations), V via ldmatrix.trans, Q frags and
// P in registers, 1 sync per tile.
// smem: Q 34816 | K 2x34816 | V 2x34816 = 174080 B
// ---------------------------------------------------------------------------
#define AT_SMEM_BYTES 174080

__global__ void __launch_bounds__(256) attn_kernel(
    const __half* __restrict__ Q, const __half* __restrict__ K,
    const __half* __restrict__ V, const unsigned char* __restrict__ mask,
    __half* __restrict__ CTX)
{
    extern __shared__ uint32_t smu[];
    const uint32_t smb = smem_u32(smu);
    const uint32_t kB0 = smb + 34816;
    const uint32_t vB0 = smb + 34816 + 69632;
#define KBUF(bf) (kB0 + (bf)*34816)
#define VBUF(bf) (vB0 + (bf)*34816)

    const int tid  = threadIdx.x;
    const int lane = tid & 31;
    const int wid  = tid >> 5;
    const int g    = lane >> 2;
    const int cc   = lane & 3;
    const int wm   = wid * 16;

    const int qt = blockIdx.x, h = blockIdx.y, b = blockIdx.z;
    const size_t headoff = ((size_t)(b*HH + h)) * SS * DHH;
    const __half* Qg    = Q + headoff + (size_t)qt * 128 * DHH;
    const __half* Kbase = K + headoff;
    const __half* Vbase = V + headoff;

#pragma unroll
    for (int j = 0; j < 8; j++) {
        const int f = tid + j * 256;
        const int r = f >> 4, c = f & 15;
        CP_ASYNC16(smb + (uint32_t)(r*272 + c*16), Qg + r*DHH + c*8);
    }
    CP_COMMIT();

    // one KV tile = 128 kv rows
#define LOAD_KV(t, bf) do {                                                \
        const __half* Kg_ = Kbase + (size_t)(t) * 128 * DHH;               \
        const __half* Vg_ = Vbase + (size_t)(t) * 128 * DHH;               \
        _Pragma("unroll")                                                  \
        for (int j = 0; j < 8; j++) {                                      \
            const int f = tid + j * 256;                                   \
            const int r = f >> 4, c = f & 15;                              \
            CP_ASYNC16(KBUF(bf) + (uint32_t)(r*272 + c*16),                \
                       Kg_ + r*DHH + c*8);                                 \
            CP_ASYNC16(VBUF(bf) + (uint32_t)(r*272 + c*16),                \
                       Vg_ + r*DHH + c*8);                                 \
        }                                                                  \
        CP_COMMIT();                                                       \
    } while (0)

    LOAD_KV(0, 0);
    LOAD_KV(1, 1);

    CP_WAIT1();
    __syncthreads();

    uint32_t qf[8][4];
    {
        const uint32_t qaddr = smb + (uint32_t)(wm + (lane & 15)) * 272
                             + (lane >> 4) * 16;
#pragma unroll
        for (int ks = 0; ks < 8; ks++)
            LDSM_X4(qf[ks][0], qf[ks][1], qf[ks][2], qf[ks][3], qaddr + ks*32);
    }

    const uint32_t kaddrL = (uint32_t)(lane & 7) * 272 + ((lane >> 3) & 1) * 16;
    const uint32_t vaddrL = (uint32_t)(lane & 15) * 272;

    float m0r = -1e30f, m1r = -1e30f, l0r = 0.f, l1r = 0.f;
    float O[16][4];
#pragma unroll
    for (int nf = 0; nf < 16; nf++)
#pragma unroll
        for (int q = 0; q < 4; q++) O[nf][q] = 0.f;

    const float scale = 0.08838834764831845f;
    const unsigned char* mrow = mask + (size_t)b * SS * SS;
    const int qg0 = qt * 128 + wm + g;
    const int qg8 = qg0 + 8;

    for (int t = 0; t < 16; t++) {
        const int bf = t & 1;
        const int kt = t * 128;

        unsigned short mRa[16], mRb[16];
        {
            const unsigned char* mpA = mrow + (size_t)qg0 * SS + kt + 2*cc;
            const unsigned char* mpB = mrow + (size_t)qg8 * SS + kt + 2*cc;
#pragma unroll
            for (int nf = 0; nf < 16; nf++) {
                mRa[nf] = *(const unsigned short*)(mpA + nf*8);
                mRb[nf] = *(const unsigned short*)(mpB + nf*8);
            }
        }

        // ---- S = Q @ K^T : per warp 16x128, 8 k-steps ----
        float s[16][4];
#pragma unroll
        for (int nf = 0; nf < 16; nf++)
#pragma unroll
            for (int q = 0; q < 4; q++) s[nf][q] = 0.f;

        const uint32_t kb = KBUF(bf) + kaddrL;
#pragma unroll
        for (int ks = 0; ks < 8; ks++) {
            uint32_t bb[16][2];
#pragma unroll
            for (int nf = 0; nf < 16; nf++)
                LDSM_X2(bb[nf][0], bb[nf][1], kb + nf*2176 + ks*32);
#pragma unroll
            for (int nf = 0; nf < 16; nf++)
                MMA_F16(s[nf], qf[ks], bb[nf]);
        }

        float rmax0 = -1e30f, rmax1 = -1e30f;
#pragma unroll
        for (int nf = 0; nf < 16; nf++) {
            float s0 = s[nf][0]*scale, s1 = s[nf][1]*scale;
            float s2 = s[nf][2]*scale, s3 = s[nf][3]*scale;
            if (mRa[nf] & 0x00ffu) s0 = -10000.f;
            if (mRa[nf] & 0xff00u) s1 = -10000.f;
            if (mRb[nf] & 0x00ffu) s2 = -10000.f;
            if (mRb[nf] & 0xff00u) s3 = -10000.f;
            s[nf][0] = s0; s[nf][1] = s1; s[nf][2] = s2; s[nf][3] = s3;
            rmax0 = fmaxf(rmax0, fmaxf(s0, s1));
            rmax1 = fmaxf(rmax1, fmaxf(s2, s3));
        }
        rmax0 = fmaxf(rmax0, __shfl_xor_sync(0xffffffffu, rmax0, 1));
        rmax0 = fmaxf(rmax0, __shfl_xor_sync(0xffffffffu, rmax0, 2));
        rmax1 = fmaxf(rmax1, __shfl_xor_sync(0xffffffffu, rmax1, 1));
        rmax1 = fmaxf(rmax1, __shfl_xor_sync(0xffffffffu, rmax1, 2));

        const float mn0 = fmaxf(m0r, rmax0);
        const float mn1 = fmaxf(m1r, rmax1);
        const float cf0 = __expf(m0r - mn0);
        const float cf1 = __expf(m1r - mn1);
        m0r = mn0; m1r = mn1;

        uint32_t pfrag[16][2];
        float ls0 = 0.f, ls1 = 0.f;
#pragma unroll
        for (int nf = 0; nf < 16; nf++) {
            const float p0 = __expf(s[nf][0] - mn0);
            const float p1 = __expf(s[nf][1] - mn0);
            const float p2 = __expf(s[nf][2] - mn1);
            const float p3 = __expf(s[nf][3] - mn1);
            ls0 += p0 + p1; ls1 += p2 + p3;
            const __half2 h01 = __floats2half2_rn(p0, p1);
            const __half2 h23 = __floats2half2_rn(p2, p3);
            pfrag[nf][0] = *(const uint32_t*)&h01;
            pfrag[nf][1] = *(const uint32_t*)&h23;
        }
        ls0 += __shfl_xor_sync(0xffffffffu, ls0, 1);
        ls0 += __shfl_xor_sync(0xffffffffu, ls0, 2);
        ls1 += __shfl_xor_sync(0xffffffffu, ls1, 1);
        ls1 += __shfl_xor_sync(0xffffffffu, ls1, 2);
        l0r = l0r * cf0 + ls0;
        l1r = l1r * cf1 + ls1;

#pragma unroll
        for (int nf = 0; nf < 16; nf++) {
            O[nf][0] *= cf0; O[nf][1] *= cf0;
            O[nf][2] *= cf1; O[nf][3] *= cf1;
        }

        // ---- O += P @ V : 8 k-steps of 16 kv, A from registers ----
        const uint32_t vb = VBUF(bf) + vaddrL;
#pragma unroll
        for (int ks = 0; ks < 8; ks++) {
            uint32_t a[4] = { pfrag[2*ks][0],   pfrag[2*ks][1],
                              pfrag[2*ks+1][0], pfrag[2*ks+1][1] };
            uint32_t bb[16][2];
#pragma unroll
            for (int nf = 0; nf < 16; nf++)
                LDSM_X2T(bb[nf][0], bb[nf][1], vb + ks*4352 + nf*16);
#pragma unroll
            for (int nf = 0; nf < 16; nf++)
                MMA_F16(O[nf], a, bb[nf]);
        }
        __syncthreads();

        if (t + 2 < 16) LOAD_KV(t + 2, bf);
        CP_WAIT1();
    }
#undef LOAD_KV

    const float inv0 = 1.0f / l0r;
    const float inv1 = 1.0f / l1r;
    __half* C0 = CTX + ((size_t)(b*SS + qg0)) * DD + h*DHH;
    __half* C1 = CTX + ((size_t)(b*SS + qg8)) * DD + h*DHH;
#pragma unroll
    for (int nf = 0; nf < 16; nf++) {
        const int c2 = nf*8 + 2*cc;
        const __half2 h0 = __floats2half2_rn(O[nf][0]*inv0, O[nf][1]*inv0);
        const __half2 h1 = __floats2half2_rn(O[nf][2]*inv1, O[nf][3]*inv1);
        *(uint32_t*)(C0 + c2) = *(const uint32_t*)&h0;
        *(uint32_t*)(C1 + c2) = *(const uint32_t*)&h1;
    }
}

// ---------------------------------------------------------------------------
// Launch
// ---------------------------------------------------------------------------
extern "C" void kernel_launch(void* const* d_in, const int* in_sizes, int n_in,
                              void* d_out, int out_size)
{
    const float*         hidden  = (const float*)d_in[0];
    const unsigned char* mask    = (const unsigned char*)d_in[1];
    const int*           pos     = (const int*)d_in[2];
    const float*         ln1_g   = (const float*)d_in[3];
    const float*         ln1_b   = (const float*)d_in[4];
    const float*         Wqkv    = (const float*)d_in[5];
    const float*         Wo      = (const float*)d_in[6];
    const float*         ln2_g   = (const float*)d_in[7];
    const float*         ln2_b   = (const float*)d_in[8];
    const float*         Wfc_in  = (const float*)d_in[9];
    const float*         Wfc_out = (const float*)d_in[10];
    float*               out     = (float*)d_out;

    __half *X, *Q, *K, *V, *CTX, *X2, *G;
    __half *WqkvT, *WoT, *WfciT, *WfcoT;
    float *H1;
    float2 *RTAB;
    cudaGetSymbolAddress((void**)&X,     g_X);
    cudaGetSymbolAddress((void**)&Q,     g_Q);
    cudaGetSymbolAddress((void**)&K,     g_K);
    cudaGetSymbolAddress((void**)&V,     g_V);
    cudaGetSymbolAddress((void**)&CTX,   g_CTX);
    cudaGetSymbolAddress((void**)&H1,    g_H1);
    cudaGetSymbolAddress((void**)&X2,    g_X2);
    cudaGetSymbolAddress((void**)&G,     g_G);
    cudaGetSymbolAddress((void**)&RTAB,  g_rtab);
    cudaGetSymbolAddress((void**)&WqkvT, g_WqkvT);
    cudaGetSymbolAddress((void**)&WoT,   g_WoT);
    cudaGetSymbolAddress((void**)&WfciT, g_WfciT);
    cudaGetSymbolAddress((void**)&WfcoT, g_WfcoT);

    cudaFuncSetAttribute(attn_kernel,
                         cudaFuncAttributeMaxDynamicSharedMemorySize,
                         AT_SMEM_BYTES);
    cudaFuncSetAttribute((tgemm<0,1>),
                         cudaFuncAttributeMaxDynamicSharedMemorySize,
                         GM_SMEM_BYTES);
    cudaFuncSetAttribute((tgemm<1,0>),
                         cudaFuncAttributeMaxDynamicSharedMemorySize,
                         GM_SMEM_BYTES);
    cudaFuncSetAttribute((tgemm<0,2>),
                         cudaFuncAttributeMaxDynamicSharedMemorySize,
                         GM_SMEM_BYTES);
    cudaFuncSetAttribute((tgemm<0,3>),
                         cudaFuncAttributeMaxDynamicSharedMemorySize,
                         GM_SMEM_BYTES);

    // 0) weight transposes + rope table
    transpose_h<<<dim3(NQKV/64, DD/64),  dim3(64,4)>>>(Wqkv,    WqkvT, DD,  NQKV);
    transpose_h<<<dim3(DD/64,   DD/64),  dim3(64,4)>>>(Wo,      WoT,   DD,  DD);
    transpose_h<<<dim3(DD/64,   FFN/64), dim3(64,4)>>>(Wfc_out, WfcoT, FFN, DD);
    transpose_h_pair2<<<dim3(FFN/64, DD/64), dim3(64,4)>>>(Wfc_in, WfciT);
    rtab_kernel<<<ROWS, 64>>>(pos, RTAB);

    // 1) LN1 (fp16 out)
    ln_kernel<<<ROWS, 256>>>(hidden, ln1_g, ln1_b, X);
    // 2) QKV projection + fused rope + scatter to Q/K/V
    tgemm<0,3><<<dim3(NQKV/128, ROWS/128), 128, GM_SMEM_BYTES>>>(
        X, WqkvT, nullptr, nullptr, DD, NQKV, RTAB, Q, K, V);
    // 3) attention -> ctx (fp16)
    attn_kernel<<<dim3(SS/128, HH, BB), 256, AT_SMEM_BYTES>>>(Q, K, V, mask, CTX);
    // 4) Wo projection + residual (f32 out)
    tgemm<1,0><<<dim3(DD/128, ROWS/128), 128, GM_SMEM_BYTES>>>(
        CTX, WoT, hidden, H1, DD, DD, nullptr, nullptr, nullptr, nullptr);
    // 5) LN2 (fp16 out)
    ln_kernel<<<ROWS, 256>>>(H1, ln2_g, ln2_b, X2);
    // 6) fc_in + fused SwiGLU (fp16 G out)
    tgemm<0,2><<<dim3(NFC/128, ROWS/128), 128, GM_SMEM_BYTES>>>(
        X2, WfciT, nullptr, G, DD, NFC, nullptr, nullptr, nullptr, nullptr);
    // 7) fc_out + residual (final output, f32)
    tgemm<1,0><<<dim3(DD/128, ROWS/128), 128, GM_SMEM_BYTES>>>(
        G, WfcoT, H1, out, FFN, DD, nullptr, nullptr, nullptr, nullptr);
}

// round 16
// speedup vs baseline: 1.2984x; 1.0025x over previous
#include <cuda_runtime.h>
#include <cuda_fp16.h>
#include <math.h>
#include <stdint.h>

// ---------------------------------------------------------------------------
// Problem constants
// ---------------------------------------------------------------------------
#define BB   2
#define SS   2048
#define DD   2048
#define HH   16
#define DHH  128
#define FFN  5632
#define ROWS (BB*SS)           // 4096
#define NQKV (3*HH*DHH)        // 6144
#define NFC  (2*FFN)           // 11264

// ---------------------------------------------------------------------------
// Scratch
// ---------------------------------------------------------------------------
__device__ __half g_X  [ROWS*DD];    // LN1 out
__device__ __half g_Q  [ROWS*DD];    // [B,H,S,DH]
__device__ __half g_K  [ROWS*DD];
__device__ __half g_V  [ROWS*DD];    // [B,H,S,DH]
__device__ __half g_CTX[ROWS*DD];    // [B,S,H*DH]
__device__ float  g_H1 [ROWS*DD];    // residual 1 (fp32)
__device__ __half g_X2 [ROWS*DD];    // LN2 out
__device__ __half g_G  [ROWS*FFN];   // swiglu out (written by fused fc_in)
__device__ float2 g_rtab[ROWS*64];   // rope (cos, sin) table per (row, freq)
// transposed weights [N,K] K-major, fp16
__device__ __half g_WqkvT [NQKV*DD];
__device__ __half g_WoT   [DD*DD];
__device__ __half g_WfciT [NFC*DD];  // interleaved: row 2j = a_j, 2j+1 = b_j
__device__ __half g_WfcoT [DD*FFN];

// ---------------------------------------------------------------------------
// Helpers
// ---------------------------------------------------------------------------
__device__ __forceinline__ uint32_t smem_u32(const void* p) {
    uint32_t a;
    asm("{ .reg .u64 t; cvta.to.shared.u64 t, %1; cvt.u32.u64 %0, t; }"
        : "=r"(a) : "l"(p));
    return a;
}

#define CP_ASYNC16(dst, src) \
    asm volatile("cp.async.cg.shared.global [%0], [%1], 16;" \
                 :: "r"(dst), "l"(src))
#define CP_COMMIT() asm volatile("cp.async.commit_group;" ::: "memory")
#define CP_WAIT1()  asm volatile("cp.async.wait_group 1;" ::: "memory")
#define CP_WAIT0()  asm volatile("cp.async.wait_group 0;" ::: "memory")

#define MMA_F16(d, a, b)                                                   \
    asm volatile(                                                          \
        "mma.sync.aligned.m16n8k16.row.col.f32.f16.f16.f32 "               \
        "{%0,%1,%2,%3}, {%4,%5,%6,%7}, {%8,%9}, {%0,%1,%2,%3};"            \
        : "+f"((d)[0]), "+f"((d)[1]), "+f"((d)[2]), "+f"((d)[3])           \
        : "r"((a)[0]), "r"((a)[1]), "r"((a)[2]), "r"((a)[3]),              \
          "r"((b)[0]), "r"((b)[1]))

#define LDSM_X4(r0, r1, r2, r3, addr)                                      \
    asm volatile("ldmatrix.sync.aligned.m8n8.x4.shared.b16 "               \
                 "{%0,%1,%2,%3}, [%4];"                                    \
                 : "=r"(r0), "=r"(r1), "=r"(r2), "=r"(r3) : "r"(addr))

#define LDSM_X2(r0, r1, addr)                                              \
    asm volatile("ldmatrix.sync.aligned.m8n8.x2.shared.b16 "               \
                 "{%0,%1}, [%2];"                                          \
                 : "=r"(r0), "=r"(r1) : "r"(addr))

#define LDSM_X2T(r0, r1, addr)                                             \
    asm volatile("ldmatrix.sync.aligned.m8n8.x2.trans.shared.b16 "         \
                 "{%0,%1}, [%2];"                                          \
                 : "=r"(r0), "=r"(r1) : "r"(addr))

// ---------------------------------------------------------------------------
// Weight transpose + fp16 round: W[K,N] f32 -> Wt[N,K] f16 (64x64 tiles)
// ---------------------------------------------------------------------------
__global__ void __launch_bounds__(256) transpose_h(
    const float* __restrict__ W, __half* __restrict__ Wt, int K, int N)
{
    __shared__ float t[64][65];
    const int tx = threadIdx.x;
    const int ty = threadIdx.y;
    const int n0 = blockIdx.x * 64, k0 = blockIdx.y * 64;
#pragma unroll
    for (int j = 0; j < 16; j++)
        t[ty + j*4][tx] = W[(size_t)(k0 + ty + j*4) * N + n0 + tx];
    __syncthreads();
#pragma unroll
    for (int j = 0; j < 16; j++)
        Wt[(size_t)(n0 + ty + j*4) * K + k0 + tx] =
            __float2half_rn(t[tx][ty + j*4]);
}

// Merged paired transpose for fc_in (64x64 tiles)
__global__ void __launch_bounds__(256) transpose_h_pair2(
    const float* __restrict__ W, __half* __restrict__ Wt)
{
    __shared__ float ta[64][65];
    __shared__ float tb[64][65];
    const int tx = threadIdx.x, ty = threadIdx.y;
    const int n0 = blockIdx.x * 64, k0 = blockIdx.y * 64;
#pragma unroll
    for (int j = 0; j < 16; j++) {
        const size_t rbase = (size_t)(k0 + ty + j*4) * NFC;
        ta[ty + j*4][tx] = W[rbase + n0 + tx];
        tb[ty + j*4][tx] = W[rbase + FFN + n0 + tx];
    }
    __syncthreads();
#pragma unroll
    for (int j = 0; j < 16; j++) {
        const int n = n0 + ty + j*4;
        Wt[(size_t)(2*n)     * DD + k0 + tx] = __float2half_rn(ta[tx][ty + j*4]);
        Wt[(size_t)(2*n + 1) * DD + k0 + tx] = __float2half_rn(tb[tx][ty + j*4]);
    }
}

// ---------------------------------------------------------------------------
// Rope sin/cos table
// ---------------------------------------------------------------------------
__global__ void __launch_bounds__(64) rtab_kernel(
    const int* __restrict__ pos_ids, float2* __restrict__ tab)
{
    const int r = blockIdx.x;
    const int j = threadIdx.x;
    const float pos = (float)pos_ids[r];
    const float inv = 1.0f / powf(10000.0f, (float)(2*j) * (1.0f/128.0f));
    float sn, cs;
    sincosf(pos * inv, &sn, &cs);
    tab[r*64 + j] = make_float2(cs, sn);
}

// ---------------------------------------------------------------------------
// FP16 mma.sync GEMM, ldmatrix fragments, 3-stage cp.async, k-chunk 64.
// CTA tile 128x128x64, 4 warps (2M x 2N), warp tile 64x64, 2 CTAs/SM.
// OUT: 0 = f32 (+residual if EPI), 1 = f16,
//      2 = f16 fused swiglu (paired cols),
//      3 = fused rope+scatter to Q/K/V
// ---------------------------------------------------------------------------
#define TILE_BYTES 18432              // 128 rows * 144 B
#define STAGE_BYTES (2*TILE_BYTES)    // 36864
#define GM_SMEM_BYTES (3*STAGE_BYTES) // 110592

template<int EPI, int OUT>
__global__ void __launch_bounds__(128, 2) tgemm(
    const __half* __restrict__ A, const __half* __restrict__ Bt,
    const float* __restrict__ R, void* __restrict__ Cv,
    int K, int N,
    const float2* __restrict__ rtab,
    __half* __restrict__ Qo, __half* __restrict__ Ko,
    __half* __restrict__ Vo)
{
    extern __shared__ char smc[];
    const uint32_t smb = smem_u32(smc);

    const int tid  = threadIdx.x;
    const int wid  = tid >> 5;
    const int lane = tid & 31;
    const int g    = lane >> 2;
    const int cc   = lane & 3;
    const int wm   = (wid & 1) * 64;
    const int wn   = (wid >> 1) * 64;

    const int m0 = blockIdx.y * 128;
    const int n0 = blockIdx.x * 128;

    const __half* Ab = A  + (size_t)m0 * K;
    const __half* Bb = Bt + (size_t)n0 * K;

    const int NC = K / 64;

    const uint32_t aoff = (uint32_t)(wm + (lane & 15)) * 144 + (lane >> 4) * 16;
    const uint32_t boff = (uint32_t)(wn + (lane & 7) + ((lane >> 4) * 8)) * 144
                        + ((lane >> 3) & 1) * 16;

#define LOAD_STAGE(chunk, st) do {                                         \
        const uint32_t asw = smb + (st)*STAGE_BYTES;                       \
        const uint32_t bsw = asw + TILE_BYTES;                             \
        const int kt = (chunk) * 64;                                       \
        _Pragma("unroll")                                                  \
        for (int j = 0; j < 8; j++) {                                      \
            const int f = tid + j * 128;                                   \
            const int row = f >> 3, c8 = f & 7;                            \
            CP_ASYNC16(asw + (uint32_t)(row*144 + c8*16),                  \
                       Ab + (size_t)row * K + kt + c8*8);                  \
            CP_ASYNC16(bsw + (uint32_t)(row*144 + c8*16),                  \
                       Bb + (size_t)row * K + kt + c8*8);                  \
        }                                                                  \
        CP_COMMIT();                                                       \
    } while (0)

    float acc[4][8][4];
#pragma unroll
    for (int mf = 0; mf < 4; mf++)
#pragma unroll
        for (int nf = 0; nf < 8; nf++)
#pragma unroll
            for (int q = 0; q < 4; q++) acc[mf][nf][q] = 0.f;

    LOAD_STAGE(0, 0);
    LOAD_STAGE(1, 1);

    int st = 0;
    for (int i = 0; i < NC; i++) {
        if (i == NC - 1) CP_WAIT0(); else CP_WAIT1();
        __syncthreads();
        if (i + 2 < NC) {
            const int st2 = (st + 2 >= 3) ? st - 1 : st + 2;
            LOAD_STAGE(i + 2, st2);
        }

        const uint32_t abase = smb + st * STAGE_BYTES;
        const uint32_t bbase = abase + TILE_BYTES;

#pragma unroll
        for (int ks = 0; ks < 4; ks++) {
            uint32_t a[4][4], b[8][2];
#pragma unroll
            for (int mf = 0; mf < 4; mf++)
                LDSM_X4(a[mf][0], a[mf][1], a[mf][2], a[mf][3],
                        abase + aoff + mf*2304 + ks*32);
#pragma unroll
            for (int p = 0; p < 4; p++)
                LDSM_X4(b[2*p][0], b[2*p][1], b[2*p+1][0], b[2*p+1][1],
                        bbase + boff + p*2304 + ks*32);
#pragma unroll
            for (int mf = 0; mf < 4; mf++)
#pragma unroll
                for (int nf = 0; nf < 8; nf++)
                    MMA_F16(acc[mf][nf], a[mf], b[nf]);
        }
        st = (st + 1 >= 3) ? 0 : st + 1;
    }
#undef LOAD_STAGE

    if (OUT == 3) {
        const int head = n0 / 384;
        const int part = (n0 - head*384) / 128;   // 0=q, 1=k, 2=v
        __half* sh = (__half*)smc;

        __syncthreads();
#pragma unroll
        for (int mf = 0; mf < 4; mf++) {
#pragma unroll
            for (int nf = 0; nf < 8; nf++) {
                const int row = wm + mf * 16 + g;
                const int col = wn + nf * 8 + cc * 2;
                const __half2 h0 = __floats2half2_rn(acc[mf][nf][0], acc[mf][nf][1]);
                const __half2 h1 = __floats2half2_rn(acc[mf][nf][2], acc[mf][nf][3]);
                *(uint32_t*)&sh[row*132 + col]       = *(const uint32_t*)&h0;
                *(uint32_t*)&sh[(row + 8)*132 + col] = *(const uint32_t*)&h1;
            }
        }
        __syncthreads();

        __half* dst = (part == 0) ? Qo : (part == 1) ? Ko : Vo;
        const int rr = tid >> 6;
        const int dd = tid & 63;
#pragma unroll 4
        for (int i = 0; i < 64; i++) {
            const int r  = rr * 64 + i;
            const int bs = m0 + r;
            const int bI = bs >> 11, sI = bs & 2047;
            const size_t o = (((size_t)(bI*HH + head)) * SS + sI) * DHH;
            const float h0 = __half2float(sh[r*132 + dd]);
            const float h1 = __half2float(sh[r*132 + dd + 64]);
            if (part < 2) {
                const float2 t = rtab[(size_t)bs*64 + dd];
                dst[o + dd]      = __float2half_rn(h0*t.x - h1*t.y);
                dst[o + dd + 64] = __float2half_rn(h1*t.x + h0*t.y);
            } else {
                dst[o + dd]      = __float2half_rn(h0);
                dst[o + dd + 64] = __float2half_rn(h1);
            }
        }
        return;
    }

#pragma unroll
    for (int mf = 0; mf < 4; mf++) {
#pragma unroll
        for (int nf = 0; nf < 8; nf++) {
            const int row = m0 + wm + mf * 16 + g;
            const int col = n0 + wn + nf * 8 + cc * 2;
            float2 v0 = { acc[mf][nf][0], acc[mf][nf][1] };
            float2 v1 = { acc[mf][nf][2], acc[mf][nf][3] };
            if (OUT == 2) {
                __half* Gp = (__half*)Cv;
                const int gcol = col >> 1;
                const float s0 = v0.x / (1.0f + __expf(-v0.x)) * v0.y;
                const float s1 = v1.x / (1.0f + __expf(-v1.x)) * v1.y;
                Gp[(size_t)row * FFN + gcol]       = __float2half_rn(s0);
                Gp[(size_t)(row + 8) * FFN + gcol] = __float2half_rn(s1);
            } else {
                const size_t o0 = (size_t)row * N + col;
                const size_t o1 = (size_t)(row + 8) * N + col;
                if (EPI == 1) {
                    float2 r0 = *(const float2*)&R[o0];
                    float2 r1 = *(const float2*)&R[o1];
                    v0.x += r0.x; v0.y += r0.y;
                    v1.x += r1.x; v1.y += r1.y;
                }
                if (OUT == 1) {
                    __half* C = (__half*)Cv;
                    const __half2 h0 = __floats2half2_rn(v0.x, v0.y);
                    const __half2 h1 = __floats2half2_rn(v1.x, v1.y);
                    *(uint32_t*)&C[o0] = *(const uint32_t*)&h0;
                    *(uint32_t*)&C[o1] = *(const uint32_t*)&h1;
                } else {
                    float* C = (float*)Cv;
                    *(float2*)&C[o0] = v0;
                    *(float2*)&C[o1] = v1;
                }
            }
        }
    }
}

// ---------------------------------------------------------------------------
// LayerNorm: fp32 in, fp16 out
// ---------------------------------------------------------------------------
__global__ void __launch_bounds__(256) ln_kernel(
    const float* __restrict__ X, const float* __restrict__ g,
    const float* __restrict__ b, __half* __restrict__ Y)
{
    const int tid = threadIdx.x;
    const float* x = X + (size_t)blockIdx.x * DD;
    __half* y = Y + (size_t)blockIdx.x * DD;

    float v[8];
    *(float4*)&v[0] = *(const float4*)&x[tid*8];
    *(float4*)&v[4] = *(const float4*)&x[tid*8 + 4];

    float s = 0.f, sq = 0.f;
#pragma unroll
    for (int i = 0; i < 8; i++) { s += v[i]; sq += v[i]*v[i]; }
#pragma unroll
    for (int o = 16; o; o >>= 1) {
        s  += __shfl_xor_sync(0xffffffffu, s,  o);
        sq += __shfl_xor_sync(0xffffffffu, sq, o);
    }
    __shared__ float red[2][8];
    __shared__ float stats[2];
    const int w = tid >> 5, l = tid & 31;
    if (l == 0) { red[0][w] = s; red[1][w] = sq; }
    __syncthreads();
    if (tid == 0) {
        float S = 0.f, SQ = 0.f;
#pragma unroll
        for (int i = 0; i < 8; i++) { S += red[0][i]; SQ += red[1][i]; }
        const float mean = S * (1.0f/DD);
        const float var  = SQ * (1.0f/DD) - mean*mean;
        stats[0] = mean;
        stats[1] = rsqrtf(var + 1e-5f);
    }
    __syncthreads();
    const float mean = stats[0], rstd = stats[1];

    float gv[8], bv[8];
    *(float4*)&gv[0] = *(const float4*)&g[tid*8];
    *(float4*)&gv[4] = *(const float4*)&g[tid*8+4];
    *(float4*)&bv[0] = *(const float4*)&b[tid*8];
    *(float4*)&bv[4] = *(const float4*)&b[tid*8+4];

    __half2 h[4];
#pragma unroll
    for (int i = 0; i < 4; i++) {
        const float a0 = (v[2*i]   - mean) * rstd * gv[2*i]   + bv[2*i];
        const float a1 = (v[2*i+1] - mean) * rstd * gv[2*i+1] + bv[2*i+1];
        h[i] = __floats2half2_rn(a0, a1);
    }
    *(uint4*)&y[tid*8] = *(uint4*)h;
}

// ---------------------------------------------------------------------------
// Flash attention: fp16 mma + ldmatrix, cp.async double-buffered K/V tiles
// of 128 kv rows (16 tile iterations), V via ldmatrix.trans, Q frags and
// P in registers, 1 sync per tile.
// smem: Q 34816 | K 2x34816 | V 2x34816 = 174080 B
// ---------------------------------------------------------------------------
#define AT_SMEM_BYTES 174080

__global__ void __launch_bounds__(256) attn_kernel(
    const __half* __restrict__ Q, const __half* __restrict__ K,
    const __half* __restrict__ V, const unsigned char* __restrict__ mask,
    __half* __restrict__ CTX)
{
    extern __shared__ uint32_t smu[];
    const uint32_t smb = smem_u32(smu);
    const uint32_t kB0 = smb + 34816;
    const uint32_t vB0 = smb + 34816 + 69632;
#define KBUF(bf) (kB0 + (bf)*34816)
#define VBUF(bf) (vB0 + (bf)*34816)

    const int tid  = threadIdx.x;
    const int lane = tid & 31;
    const int wid  = tid >> 5;
    const int g    = lane >> 2;
    const int cc   = lane & 3;
    const int wm   = wid * 16;

    const int qt = blockIdx.x, h = blockIdx.y, b = blockIdx.z;
    const size_t headoff = ((size_t)(b*HH + h)) * SS * DHH;
    const __half* Qg    = Q + headoff + (size_t)qt * 128 * DHH;
    const __half* Kbase = K + headoff;
    const __half* Vbase = V + headoff;

#pragma unroll
    for (int j = 0; j < 8; j++) {
        const int f = tid + j * 256;
        const int r = f >> 4, c = f & 15;
        CP_ASYNC16(smb + (uint32_t)(r*272 + c*16), Qg + r*DHH + c*8);
    }
    CP_COMMIT();

    // one KV tile = 128 kv rows
#define LOAD_KV(t, bf) do {                                                \
        const __half* Kg_ = Kbase + (size_t)(t) * 128 * DHH;               \
        const __half* Vg_ = Vbase + (size_t)(t) * 128 * DHH;               \
        _Pragma("unroll")                                                  \
        for (int j = 0; j < 8; j++) {                                      \
            const int f = tid + j * 256;                                   \
            const int r = f >> 4, c = f & 15;                              \
            CP_ASYNC16(KBUF(bf) + (uint32_t)(r*272 + c*16),                \
                       Kg_ + r*DHH + c*8);                                 \
            CP_ASYNC16(VBUF(bf) + (uint32_t)(r*272 + c*16),                \
                       Vg_ + r*DHH + c*8);                                 \
        }                                                                  \
        CP_COMMIT();                                                       \
    } while (0)

    LOAD_KV(0, 0);
    LOAD_KV(1, 1);

    CP_WAIT1();
    __syncthreads();

    uint32_t qf[8][4];
    {
        const uint32_t qaddr = smb + (uint32_t)(wm + (lane & 15)) * 272
                             + (lane >> 4) * 16;
#pragma unroll
        for (int ks = 0; ks < 8; ks++)
            LDSM_X4(qf[ks][0], qf[ks][1], qf[ks][2], qf[ks][3], qaddr + ks*32);
    }

    const uint32_t kaddrL = (uint32_t)(lane & 7) * 272 + ((lane >> 3) & 1) * 16;
    const uint32_t vaddrL = (uint32_t)(lane & 15) * 272;

    float m0r = -1e30f, m1r = -1e30f, l0r = 0.f, l1r = 0.f;
    float O[16][4];
#pragma unroll
    for (int nf = 0; nf < 16; nf++)
#pragma unroll
        for (int q = 0; q < 4; q++) O[nf][q] = 0.f;

    const float scale = 0.08838834764831845f;
    const unsigned char* mrow = mask + (size_t)b * SS * SS;
    const int qg0 = qt * 128 + wm + g;
    const int qg8 = qg0 + 8;

    for (int t = 0; t < 16; t++) {
        const int bf = t & 1;
        const int kt = t * 128;

        unsigned short mRa[16], mRb[16];
        {
            const unsigned char* mpA = mrow + (size_t)qg0 * SS + kt + 2*cc;
            const unsigned char* mpB = mrow + (size_t)qg8 * SS + kt + 2*cc;
#pragma unroll
            for (int nf = 0; nf < 16; nf++) {
                mRa[nf] = *(const unsigned short*)(mpA + nf*8);
                mRb[nf] = *(const unsigned short*)(mpB + nf*8);
            }
        }

        // ---- S = Q @ K^T : per warp 16x128, 8 k-steps ----
        float s[16][4];
#pragma unroll
        for (int nf = 0; nf < 16; nf++)
#pragma unroll
            for (int q = 0; q < 4; q++) s[nf][q] = 0.f;

        const uint32_t kb = KBUF(bf) + kaddrL;
#pragma unroll
        for (int ks = 0; ks < 8; ks++) {
            uint32_t bb[16][2];
#pragma unroll
            for (int nf = 0; nf < 16; nf++)
                LDSM_X2(bb[nf][0], bb[nf][1], kb + nf*2176 + ks*32);
#pragma unroll
            for (int nf = 0; nf < 16; nf++)
                MMA_F16(s[nf], qf[ks], bb[nf]);
        }

        float rmax0 = -1e30f, rmax1 = -1e30f;
#pragma unroll
        for (int nf = 0; nf < 16; nf++) {
            float s0 = s[nf][0]*scale, s1 = s[nf][1]*scale;
            float s2 = s[nf][2]*scale, s3 = s[nf][3]*scale;
            if (mRa[nf] & 0x00ffu) s0 = -10000.f;
            if (mRa[nf] & 0xff00u) s1 = -10000.f;
            if (mRb[nf] & 0x00ffu) s2 = -10000.f;
            if (mRb[nf] & 0xff00u) s3 = -10000.f;
            s[nf][0] = s0; s[nf][1] = s1; s[nf][2] = s2; s[nf][3] = s3;
            rmax0 = fmaxf(rmax0, fmaxf(s0, s1));
            rmax1 = fmaxf(rmax1, fmaxf(s2, s3));
        }
        rmax0 = fmaxf(rmax0, __shfl_xor_sync(0xffffffffu, rmax0, 1));
        rmax0 = fmaxf(rmax0, __shfl_xor_sync(0xffffffffu, rmax0, 2));
        rmax1 = fmaxf(rmax1, __shfl_xor_sync(0xffffffffu, rmax1, 1));
        rmax1 = fmaxf(rmax1, __shfl_xor_sync(0xffffffffu, rmax1, 2));

        const float mn0 = fmaxf(m0r, rmax0);
        const float mn1 = fmaxf(m1r, rmax1);
        const float cf0 = __expf(m0r - mn0);
        const float cf1 = __expf(m1r - mn1);
        m0r = mn0; m1r = mn1;

        uint32_t pfrag[16][2];
        float ls0 = 0.f, ls1 = 0.f;
#pragma unroll
        for (int nf = 0; nf < 16; nf++) {
            const float p0 = __expf(s[nf][0] - mn0);
            const float p1 = __expf(s[nf][1] - mn0);
            const float p2 = __expf(s[nf][2] - mn1);
            const float p3 = __expf(s[nf][3] - mn1);
            ls0 += p0 + p1; ls1 += p2 + p3;
            const __half2 h01 = __floats2half2_rn(p0, p1);
            const __half2 h23 = __floats2half2_rn(p2, p3);
            pfrag[nf][0] = *(const uint32_t*)&h01;
            pfrag[nf][1] = *(const uint32_t*)&h23;
        }
        ls0 += __shfl_xor_sync(0xffffffffu, ls0, 1);
        ls0 += __shfl_xor_sync(0xffffffffu, ls0, 2);
        ls1 += __shfl_xor_sync(0xffffffffu, ls1, 1);
        ls1 += __shfl_xor_sync(0xffffffffu, ls1, 2);
        l0r = l0r * cf0 + ls0;
        l1r = l1r * cf1 + ls1;

#pragma unroll
        for (int nf = 0; nf < 16; nf++) {
            O[nf][0] *= cf0; O[nf][1] *= cf0;
            O[nf][2] *= cf1; O[nf][3] *= cf1;
        }

        // ---- O += P @ V : 8 k-steps of 16 kv, A from registers ----
        const uint32_t vb = VBUF(bf) + vaddrL;
#pragma unroll
        for (int ks = 0; ks < 8; ks++) {
            uint32_t a[4] = { pfrag[2*ks][0],   pfrag[2*ks][1],
                              pfrag[2*ks+1][0], pfrag[2*ks+1][1] };
            uint32_t bb[16][2];
#pragma unroll
            for (int nf = 0; nf < 16; nf++)
                LDSM_X2T(bb[nf][0], bb[nf][1], vb + ks*4352 + nf*16);
#pragma unroll
            for (int nf = 0; nf < 16; nf++)
                MMA_F16(O[nf], a, bb[nf]);
        }
        __syncthreads();

        if (t + 2 < 16) LOAD_KV(t + 2, bf);
        CP_WAIT1();
    }
#undef LOAD_KV

    const float inv0 = 1.0f / l0r;
    const float inv1 = 1.0f / l1r;
    __half* C0 = CTX + ((size_t)(b*SS + qg0)) * DD + h*DHH;
    __half* C1 = CTX + ((size_t)(b*SS + qg8)) * DD + h*DHH;
#pragma unroll
    for (int nf = 0; nf < 16; nf++) {
        const int c2 = nf*8 + 2*cc;
        const __half2 h0 = __floats2half2_rn(O[nf][0]*inv0, O[nf][1]*inv0);
        const __half2 h1 = __floats2half2_rn(O[nf][2]*inv1, O[nf][3]*inv1);
        *(uint32_t*)(C0 + c2) = *(const uint32_t*)&h0;
        *(uint32_t*)(C1 + c2) = *(const uint32_t*)&h1;
    }
}

// ---------------------------------------------------------------------------
// Launch
// ---------------------------------------------------------------------------
extern "C" void kernel_launch(void* const* d_in, const int* in_sizes, int n_in,
                              void* d_out, int out_size)
{
    const float*         hidden  = (const float*)d_in[0];
    const unsigned char* mask    = (const unsigned char*)d_in[1];
    const int*           pos     = (const int*)d_in[2];
    const float*         ln1_g   = (const float*)d_in[3];
    const float*         ln1_b   = (const float*)d_in[4];
    const float*         Wqkv    = (const float*)d_in[5];
    const float*         Wo      = (const float*)d_in[6];
    const float*         ln2_g   = (const float*)d_in[7];
    const float*         ln2_b   = (const float*)d_in[8];
    const float*         Wfc_in  = (const float*)d_in[9];
    const float*         Wfc_out = (const float*)d_in[10];
    float*               out     = (float*)d_out;

    __half *X, *Q, *K, *V, *CTX, *X2, *G;
    __half *WqkvT, *WoT, *WfciT, *WfcoT;
    float *H1;
    float2 *RTAB;
    cudaGetSymbolAddress((void**)&X,     g_X);
    cudaGetSymbolAddress((void**)&Q,     g_Q);
    cudaGetSymbolAddress((void**)&K,     g_K);
    cudaGetSymbolAddress((void**)&V,     g_V);
    cudaGetSymbolAddress((void**)&CTX,   g_CTX);
    cudaGetSymbolAddress((void**)&H1,    g_H1);
    cudaGetSymbolAddress((void**)&X2,    g_X2);
    cudaGetSymbolAddress((void**)&G,     g_G);
    cudaGetSymbolAddress((void**)&RTAB,  g_rtab);
    cudaGetSymbolAddress((void**)&WqkvT, g_WqkvT);
    cudaGetSymbolAddress((void**)&WoT,   g_WoT);
    cudaGetSymbolAddress((void**)&WfciT, g_WfciT);
    cudaGetSymbolAddress((void**)&WfcoT, g_WfcoT);

    cudaFuncSetAttribute(attn_kernel,
                         cudaFuncAttributeMaxDynamicSharedMemorySize,
                         AT_SMEM_BYTES);
    cudaFuncSetAttribute((tgemm<0,1>),
                         cudaFuncAttributeMaxDynamicSharedMemorySize,
                         GM_SMEM_BYTES);
    cudaFuncSetAttribute((tgemm<1,0>),
                         cudaFuncAttributeMaxDynamicSharedMemorySize,
                         GM_SMEM_BYTES);
    cudaFuncSetAttribute((tgemm<0,2>),
                         cudaFuncAttributeMaxDynamicSharedMemorySize,
                         GM_SMEM_BYTES);
    cudaFuncSetAttribute((tgemm<0,3>),
                         cudaFuncAttributeMaxDynamicSharedMemorySize,
                         GM_SMEM_BYTES);

    // 0) weight transposes + rope table
    transpose_h<<<dim3(NQKV/64, DD/64),  dim3(64,4)>>>(Wqkv,    WqkvT, DD,  NQKV);
    transpose_h<<<dim3(DD/64,   DD/64),  dim3(64,4)>>>(Wo,      WoT,   DD,  DD);
    transpose_h<<<dim3(DD/64,   FFN/64), dim3(64,4)>>>(Wfc_out, WfcoT, FFN, DD);
    transpose_h_pair2<<<dim3(FFN/64, DD/64), dim3(64,4)>>>(Wfc_in, WfciT);
    rtab_kernel<<<ROWS, 64>>>(pos, RTAB);

    // 1) LN1 (fp16 out)
    ln_kernel<<<ROWS, 256>>>(hidden, ln1_g, ln1_b, X);
    // 2) QKV projection + fused rope + scatter to Q/K/V
    tgemm<0,3><<<dim3(NQKV/128, ROWS/128), 128, GM_SMEM_BYTES>>>(
        X, WqkvT, nullptr, nullptr, DD, NQKV, RTAB, Q, K, V);
    // 3) attention -> ctx (fp16)
    attn_kernel<<<dim3(SS/128, HH, BB), 256, AT_SMEM_BYTES>>>(Q, K, V, mask, CTX);
    // 4) Wo projection + residual (f32 out)
    tgemm<1,0><<<dim3(DD/128, ROWS/128), 128, GM_SMEM_BYTES>>>(
        CTX, WoT, hidden, H1, DD, DD, nullptr, nullptr, nullptr, nullptr);
    // 5) LN2 (fp16 out)
    ln_kernel<<<ROWS, 256>>>(H1, ln2_g, ln2_b, X2);
    // 6) fc_in + fused SwiGLU (fp16 G out)
    tgemm<0,2><<<dim3(NFC/128, ROWS/128), 128, GM_SMEM_BYTES>>>(
        X2, WfciT, nullptr, G, DD, NFC, nullptr, nullptr, nullptr, nullptr);
    // 7) fc_out + residual (final output, f32)
    tgemm<1,0><<<dim3(DD/128, ROWS/128), 128, GM_SMEM_BYTES>>>(
        G, WfcoT, H1, out, FFN, DD, nullptr, nullptr, nullptr, nullptr);
}